// round 12
// baseline (speedup 1.0000x reference)
#include <cuda_runtime.h>
#include <cuda_fp16.h>
#include <math.h>
#include <stdint.h>

#define B_    2
#define L_    1024
#define D_    1024
#define H_    16
#define DH_   64
#define E_    32
#define ES_   128
#define T_    (B_*L_)
#define P2_   (2*L_-1)
#define NC_   (E_*ES_)

// ---------------- helpers ----------------
__device__ __forceinline__ uint32_t smem_u32(const void* p) {
    uint32_t a;
    asm("{ .reg .u64 t; cvta.to.shared.u64 t, %1; cvt.u32.u64 %0, t; }" : "=r"(a) : "l"(p));
    return a;
}
__device__ __forceinline__ void ldsm4(uint32_t& r0, uint32_t& r1, uint32_t& r2, uint32_t& r3, uint32_t addr) {
    asm volatile("ldmatrix.sync.aligned.m8n8.x4.shared.b16 {%0,%1,%2,%3}, [%4];"
        : "=r"(r0), "=r"(r1), "=r"(r2), "=r"(r3) : "r"(addr));
}
__device__ __forceinline__ void mma16816(float* c, const uint32_t* a, uint32_t b0, uint32_t b1) {
    asm volatile("mma.sync.aligned.m16n8k16.row.col.f32.f16.f16.f32 "
        "{%0,%1,%2,%3}, {%4,%5,%6,%7}, {%8,%9}, {%0,%1,%2,%3};"
        : "+f"(c[0]), "+f"(c[1]), "+f"(c[2]), "+f"(c[3])
        : "r"(a[0]), "r"(a[1]), "r"(a[2]), "r"(a[3]), "r"(b0), "r"(b1));
}
__device__ __forceinline__ void cpa16(uint32_t saddr, const void* gaddr) {
    asm volatile("cp.async.ca.shared.global [%0], [%1], 16;" :: "r"(saddr), "l"(gaddr));
}
#define CPA_COMMIT() asm volatile("cp.async.commit_group;" ::: "memory")
#define CPA_WAIT1()  asm volatile("cp.async.wait_group 1;" ::: "memory")
#define CPA_WAIT0()  asm volatile("cp.async.wait_group 0;" ::: "memory")

// store a pair (x,y) split into hi/lo half arrays at even index idx
__device__ __forceinline__ void sp2(float x, float y, __half* ph, __half* pl, size_t idx) {
    __half hx = __float2half_rn(x), hy = __float2half_rn(y);
    *reinterpret_cast<__half2*>(ph + idx) = __halves2half2(hx, hy);
    *reinterpret_cast<__half2*>(pl + idx) = __halves2half2(
        __float2half_rn(x - __half2float(hx)), __float2half_rn(y - __half2float(hy)));
}

// 128x128 warp-tile MMA body (warp = 32x64): PASS=2 (Ah+Al)*Bh, PASS=1 Ah*Bh
template<int PASS>
__device__ __forceinline__ void mma_tile(uint32_t sAh, uint32_t sAl, uint32_t sBh,
                                         int lane, int wm0, int wn0, float acc[2][8][4]) {
#pragma unroll
    for (int ks = 0; ks < 2; ks++) {
        uint32_t bh[16];
        int g = lane >> 3;
#pragma unroll
        for (int p = 0; p < 4; p++) {
            uint32_t bo = (uint32_t)(((wn0 + p*16 + (g>>1)*8 + (lane&7))*40 + ks*16 + (g&1)*8) * 2);
            ldsm4(bh[p*4], bh[p*4+1], bh[p*4+2], bh[p*4+3], sBh + bo);
        }
#pragma unroll
        for (int am = 0; am < 2; am++) {
            uint32_t ah[4], al[4];
            uint32_t ao = (uint32_t)(((wm0 + am*16 + (lane&15))*40 + ks*16 + (lane>>4)*8) * 2);
            ldsm4(ah[0], ah[1], ah[2], ah[3], sAh + ao);
            if (PASS == 2) ldsm4(al[0], al[1], al[2], al[3], sAl + ao);
#pragma unroll
            for (int bn = 0; bn < 8; bn++) {
                mma16816(acc[am][bn], ah, bh[bn*2], bh[bn*2+1]);
                if (PASS == 2) mma16816(acc[am][bn], al, bh[bn*2], bh[bn*2+1]);
            }
        }
    }
}
// 32x32 warp-tile variant (for att@V, N=64), 1-pass
__device__ __forceinline__ void mma_tile32(uint32_t sAh, uint32_t sBh,
                                           int lane, int wm0, int wn0, float acc[2][4][4]) {
#pragma unroll
    for (int ks = 0; ks < 2; ks++) {
        uint32_t bh[8];
        int g = lane >> 3;
#pragma unroll
        for (int p = 0; p < 2; p++) {
            uint32_t bo = (uint32_t)(((wn0 + p*16 + (g>>1)*8 + (lane&7))*40 + ks*16 + (g&1)*8) * 2);
            ldsm4(bh[p*4], bh[p*4+1], bh[p*4+2], bh[p*4+3], sBh + bo);
        }
#pragma unroll
        for (int am = 0; am < 2; am++) {
            uint32_t ah[4];
            uint32_t ao = (uint32_t)(((wm0 + am*16 + (lane&15))*40 + ks*16 + (lane>>4)*8) * 2);
            ldsm4(ah[0], ah[1], ah[2], ah[3], sAh + ao);
#pragma unroll
            for (int bn = 0; bn < 4; bn++)
                mma16816(acc[am][bn], ah, bh[bn*2], bh[bn*2+1]);
        }
    }
}

// cp.async loaders: fill 128x32 (or 64x32) half tile into 40-stride smem stage
#define CPLD128(SRC, KST, DB) do { \
    int _row = tid >> 2, _q = tid & 3; \
    cpa16((DB) + (uint32_t)((_row*40 + _q*8) * 2), &(SRC)[(size_t)_row*(KST) + kk0 + _q*8]); \
    cpa16((DB) + (uint32_t)(((_row+64)*40 + _q*8) * 2), &(SRC)[(size_t)(_row+64)*(KST) + kk0 + _q*8]); \
} while (0)
#define CPLD64(SRC, KST, DB) do { \
    int _row = tid >> 2, _q = tid & 3; \
    cpa16((DB) + (uint32_t)((_row*40 + _q*8) * 2), &(SRC)[(size_t)_row*(KST) + kk0 + _q*8]); \
} while (0)

// stage sizes in bytes
#define STG128 (128*40*2)   // 10240
#define STG64  (64*40*2)    // 5120

// ---------------- scratch (all zero-initialized __device__) ----------------
__device__ __align__(16) __half g_peh [(size_t)2048 * D_];
__device__ __align__(16) __half g_pel [(size_t)2048 * D_];
__device__ __align__(16) __half g_wqh [(size_t)D_ * D_];
__device__ __align__(16) __half g_wkh [(size_t)D_ * D_];
__device__ __align__(16) __half g_wvh [(size_t)D_ * D_];
__device__ __align__(16) __half g_woh [(size_t)D_ * D_];
__device__ __align__(16) __half g_wph [(size_t)D_ * D_];
__device__ __align__(16) __half g_keyh[(size_t)NC_ * D_];
__device__ __align__(16) __half g_valh[(size_t)D_ * NC_];
__device__ __align__(16) __half g_x2h [(size_t)T_ * D_],  g_x2l [(size_t)T_ * D_];
__device__ __align__(16) __half g_qh  [(size_t)T_ * D_],  g_ql  [(size_t)T_ * D_];
__device__ __align__(16) __half g_kh  [(size_t)T_ * D_];
__device__ __align__(16) __half g_vth [(size_t)T_ * D_];
__device__ __align__(16) __half g_ph  [(size_t)2048 * D_];
__device__ __align__(16) __half g_ctxh[(size_t)T_ * D_];
__device__ __align__(16) __half g_tbh [(size_t)T_ * D_],  g_tbl [(size_t)T_ * D_];
__device__ __align__(16) __half g_hbh [(size_t)T_ * NC_];
__device__ __align__(16) __half g_atth[(size_t)B_*H_*L_*L_];
__device__ __align__(16) float  g_vb  [(size_t)T_ * D_];
__device__ __align__(16) float  g_sc  [(size_t)B_*H_*L_*L_];
__device__ __align__(16) float  g_xr  [(size_t)T_ * D_];
__device__ __align__(16) float  g_gate[(size_t)T_ * E_];

// ---------------- small kernels ----------------
__global__ __launch_bounds__(256) void k_pos() {
    int r = blockIdx.x;                                   // 0..2046
    float pos = (float)(L_ - 1 - r);
    const float c = 9.210340371976184f / 1024.0f;         // ln(10000)/D
    for (int m = threadIdx.x; m < D_; m += 256) {
        int j = (m < 512) ? m : m - 512;
        float ang = pos * expf(-c * (float)(2 * j));
        float v = (m < 512) ? sinf(ang) : cosf(ang);
        __half h = __float2half_rn(v);
        g_peh[(size_t)r * D_ + m] = h;
        g_pel[(size_t)r * D_ + m] = __float2half_rn(v - __half2float(h));
    }
}

// transpose hi-only: fp32 in[R][C] -> half out[C][R], z-batched via explicit pointers
__global__ __launch_bounds__(256) void k_trh(const float* __restrict__ in,
                                             __half* __restrict__ oh, int R, int C) {
    __shared__ float t[32][33];
    size_t zoff = (size_t)blockIdx.z * R * C;
    int c0 = blockIdx.x * 32, r0 = blockIdx.y * 32;
    int x = threadIdx.x & 31, y = threadIdx.x >> 5;
    for (int i = y; i < 32; i += 8)
        t[i][x] = in[zoff + (size_t)(r0 + i) * C + c0 + x];
    __syncthreads();
    for (int i = y; i < 32; i += 8)
        oh[zoff + (size_t)(c0 + i) * R + r0 + x] = __float2half_rn(t[x][i]);
}

// batched 5x DxD weight transpose: z selects (src,dst)
__global__ __launch_bounds__(256) void k_trh5(const float* __restrict__ w0, const float* __restrict__ w1,
                                              const float* __restrict__ w2, const float* __restrict__ w3,
                                              const float* __restrict__ w4) {
    __shared__ float t[32][33];
    int z = blockIdx.z;
    const float* in = (z == 0) ? w0 : (z == 1) ? w1 : (z == 2) ? w2 : (z == 3) ? w3 : w4;
    __half* oh = (z == 0) ? g_wqh : (z == 1) ? g_wkh : (z == 2) ? g_wvh : (z == 3) ? g_woh : g_wph;
    int c0 = blockIdx.x * 32, r0 = blockIdx.y * 32;
    int x = threadIdx.x & 31, y = threadIdx.x >> 5;
    for (int i = y; i < 32; i += 8)
        t[i][x] = in[(size_t)(r0 + i) * D_ + c0 + x];
    __syncthreads();
    for (int i = y; i < 32; i += 8)
        oh[(size_t)(c0 + i) * D_ + r0 + x] = __float2half_rn(t[x][i]);
}

// v transpose hi-only: vb fp32 [b*L+i][hd] -> vth [b*1024+hd][i]
__global__ __launch_bounds__(256) void k_vts() {
    __shared__ float t[32][33];
    int b = blockIdx.z;
    int i0 = blockIdx.x * 32, hd0 = blockIdx.y * 32;
    int x = threadIdx.x & 31, y = threadIdx.x >> 5;
    for (int r = y; r < 32; r += 8)
        t[r][x] = g_vb[(size_t)(b*L_ + i0 + r) * D_ + hd0 + x];
    __syncthreads();
    for (int r = y; r < 32; r += 8)
        g_vth[(size_t)(b*1024 + hd0 + r) * 1024 + i0 + x] = __float2half_rn(t[x][r]);
}

// layer norm fp32 -> half hi/lo
__global__ __launch_bounds__(256) void k_ln(const float* __restrict__ x,
                                            const float* __restrict__ g,
                                            const float* __restrict__ b,
                                            __half* __restrict__ oh, __half* __restrict__ ol) {
    __shared__ float rs[256], rq[256];
    size_t row = blockIdx.x;
    int tid = threadIdx.x;
    float4 v = reinterpret_cast<const float4*>(x + row * D_)[tid];
    rs[tid] = v.x + v.y + v.z + v.w;
    rq[tid] = v.x*v.x + v.y*v.y + v.z*v.z + v.w*v.w;
    __syncthreads();
    for (int s = 128; s; s >>= 1) {
        if (tid < s) { rs[tid] += rs[tid+s]; rq[tid] += rq[tid+s]; }
        __syncthreads();
    }
    float mean = rs[0] * (1.0f / D_);
    float inv  = rsqrtf(rq[0] * (1.0f / D_) - mean * mean + 1e-5f);
    float4 gv = reinterpret_cast<const float4*>(g)[tid];
    float4 bv = reinterpret_cast<const float4*>(b)[tid];
    size_t o = row * D_ + tid * 4;
    sp2((v.x-mean)*inv*gv.x+bv.x, (v.y-mean)*inv*gv.y+bv.y, oh, ol, o);
    sp2((v.z-mean)*inv*gv.z+bv.z, (v.w-mean)*inv*gv.w+bv.w, oh, ol, o + 2);
}

// ---------------- HMMA GEMM (A hi[/lo], B hi), cp.async double-buffered ----------------
// EPI 1: hi-only half out   2: fp32 + aux   3: relu*gate -> hi-only half out
template<int EPI, int PASS>
__global__ __launch_bounds__(256) void khg(const __half* __restrict__ Ah, const __half* __restrict__ Al,
                                           const __half* __restrict__ Bh,
                                           float* __restrict__ Cf,
                                           __half* __restrict__ Ch,
                                           const float* __restrict__ aux,
                                           const float* __restrict__ gate, int K) {
    extern __shared__ __half dsm[];
    const int tid = threadIdx.x, wid = tid >> 5, lane = tid & 31;
    const int m0 = blockIdx.y * 128, n0 = blockIdx.x * 128;
    const int ldc = gridDim.x * 128;
    const int wm0 = (wid & 3) * 32, wn0 = (wid >> 2) * 64;
    const __half* Abh = Ah + (size_t)m0 * K;
    const __half* Abl = (PASS == 2) ? (Al + (size_t)m0 * K) : nullptr;
    const __half* Bbh = Bh + (size_t)n0 * K;
    const uint32_t base = smem_u32(dsm);
    const uint32_t uAh = base;
    const uint32_t uAl = base + 2*STG128;
    const uint32_t uBh = base + PASS * 2 * STG128;
    float acc[2][8][4] = {};
    const int nk = K / 32;
    {   // prologue
        int kk0 = 0;
        CPLD128(Abh, K, uAh);
        if (PASS == 2) CPLD128(Abl, K, uAl);
        CPLD128(Bbh, K, uBh);
        CPA_COMMIT();
    }
    for (int kc = 0; kc < nk; kc++) {
        if (kc + 1 < nk) {
            int kk0 = (kc + 1) * 32;
            uint32_t so = (uint32_t)(((kc + 1) & 1) * STG128);
            CPLD128(Abh, K, uAh + so);
            if (PASS == 2) CPLD128(Abl, K, uAl + so);
            CPLD128(Bbh, K, uBh + so);
            CPA_COMMIT();
            CPA_WAIT1();
        } else {
            CPA_WAIT0();
        }
        __syncthreads();
        uint32_t so = (uint32_t)((kc & 1) * STG128);
        mma_tile<PASS>(uAh + so, uAl + so, uBh + so, lane, wm0, wn0, acc);
        __syncthreads();
    }
#pragma unroll
    for (int am = 0; am < 2; am++) {
        int r0 = m0 + wm0 + am * 16 + (lane >> 2);
#pragma unroll
        for (int bn = 0; bn < 8; bn++) {
            int cN = n0 + wn0 + bn * 8 + (lane & 3) * 2;
            float* a4 = acc[am][bn];
            if (EPI == 1) {
                *reinterpret_cast<__half2*>(Ch + (size_t)r0 * ldc + cN)     = __floats2half2_rn(a4[0], a4[1]);
                *reinterpret_cast<__half2*>(Ch + (size_t)(r0+8) * ldc + cN) = __floats2half2_rn(a4[2], a4[3]);
            } else if (EPI == 2) {
                float2 x0 = *reinterpret_cast<const float2*>(aux + (size_t)r0 * ldc + cN);
                float2 x1 = *reinterpret_cast<const float2*>(aux + (size_t)(r0+8) * ldc + cN);
                *reinterpret_cast<float2*>(Cf + (size_t)r0 * ldc + cN)     = make_float2(a4[0]+x0.x, a4[1]+x0.y);
                *reinterpret_cast<float2*>(Cf + (size_t)(r0+8) * ldc + cN) = make_float2(a4[2]+x1.x, a4[3]+x1.y);
            } else {
                int e = cN >> 7;
                float g0 = gate[r0 * E_ + e], g1 = gate[(r0+8) * E_ + e];
                *reinterpret_cast<__half2*>(Ch + (size_t)r0 * ldc + cN) =
                    __floats2half2_rn(fmaxf(a4[0],0.f)*g0, fmaxf(a4[1],0.f)*g0);
                *reinterpret_cast<__half2*>(Ch + (size_t)(r0+8) * ldc + cN) =
                    __floats2half2_rn(fmaxf(a4[2],0.f)*g1, fmaxf(a4[3],0.f)*g1);
            }
        }
    }
}

// QKV fused: z=0 -> q hi/lo (pre-scaled by 1/8), z=1 -> k hi, z=2 -> v fp32
__global__ __launch_bounds__(256) void khg_qkv(const __half* __restrict__ Ah, const __half* __restrict__ Al,
                                               const __half* __restrict__ B0h,
                                               const __half* __restrict__ B1h,
                                               const __half* __restrict__ B2h) {
    extern __shared__ __half dsm[];
    const int tid = threadIdx.x, wid = tid >> 5, lane = tid & 31;
    const int m0 = blockIdx.y * 128, n0 = blockIdx.x * 128, z = blockIdx.z;
    const int K = D_;
    const int wm0 = (wid & 3) * 32, wn0 = (wid >> 2) * 64;
    const __half* Bh = (z == 0) ? B0h : (z == 1) ? B1h : B2h;
    const __half* Abh = Ah + (size_t)m0 * K;
    const __half* Abl = Al + (size_t)m0 * K;
    const __half* Bbh = Bh + (size_t)n0 * K;
    const uint32_t base = smem_u32(dsm);
    const uint32_t uAh = base, uAl = base + 2*STG128, uBh = base + 4*STG128;
    float acc[2][8][4] = {};
    const int nk = K / 32;
    {
        int kk0 = 0;
        CPLD128(Abh, K, uAh); CPLD128(Abl, K, uAl); CPLD128(Bbh, K, uBh);
        CPA_COMMIT();
    }
    for (int kc = 0; kc < nk; kc++) {
        if (kc + 1 < nk) {
            int kk0 = (kc + 1) * 32;
            uint32_t so = (uint32_t)(((kc + 1) & 1) * STG128);
            CPLD128(Abh, K, uAh + so); CPLD128(Abl, K, uAl + so); CPLD128(Bbh, K, uBh + so);
            CPA_COMMIT();
            CPA_WAIT1();
        } else {
            CPA_WAIT0();
        }
        __syncthreads();
        uint32_t so = (uint32_t)((kc & 1) * STG128);
        mma_tile<2>(uAh + so, uAl + so, uBh + so, lane, wm0, wn0, acc);
        __syncthreads();
    }
#pragma unroll
    for (int am = 0; am < 2; am++) {
        int r0 = m0 + wm0 + am * 16 + (lane >> 2);
#pragma unroll
        for (int bn = 0; bn < 8; bn++) {
            int cN = n0 + wn0 + bn * 8 + (lane & 3) * 2;
            float* a4 = acc[am][bn];
            if (z == 2) {
                *reinterpret_cast<float2*>(g_vb + (size_t)r0 * D_ + cN)     = make_float2(a4[0], a4[1]);
                *reinterpret_cast<float2*>(g_vb + (size_t)(r0+8) * D_ + cN) = make_float2(a4[2], a4[3]);
            } else if (z == 0) {
                sp2(a4[0]*0.125f, a4[1]*0.125f, g_qh, g_ql, (size_t)r0 * D_ + cN);
                sp2(a4[2]*0.125f, a4[3]*0.125f, g_qh, g_ql, (size_t)(r0+8) * D_ + cN);
            } else {
                *reinterpret_cast<__half2*>(g_kh + (size_t)r0 * D_ + cN)     = __floats2half2_rn(a4[0], a4[1]);
                *reinterpret_cast<__half2*>(g_kh + (size_t)(r0+8) * D_ + cN) = __floats2half2_rn(a4[2], a4[3]);
            }
        }
    }
}

// ---------------- attention: ac = q.k^T (q pre-scaled; writes sc) ----------------
__global__ __launch_bounds__(256) void k_ac() {
    extern __shared__ __half dsm[];
    const int tid = threadIdx.x, wid = tid >> 5, lane = tid & 31;
    const int bh = blockIdx.z, b = bh >> 4, h = bh & 15;
    const int i0 = blockIdx.y * 128, j0 = blockIdx.x * 128;
    const int wm0 = (wid & 3) * 32, wn0 = (wid >> 2) * 64;
    const __half* Abh = g_qh + (size_t)(b*L_ + i0) * D_ + h*DH_;
    const __half* Abl = g_ql + (size_t)(b*L_ + i0) * D_ + h*DH_;
    const __half* Bbh = g_kh + (size_t)(b*L_ + j0) * D_ + h*DH_;
    const uint32_t base = smem_u32(dsm);
    const uint32_t uAh = base, uAl = base + 2*STG128, uBh = base + 4*STG128;
    float acc[2][8][4] = {};
    {
        int kk0 = 0;
        CPLD128(Abh, D_, uAh); CPLD128(Abl, D_, uAl); CPLD128(Bbh, D_, uBh);
        CPA_COMMIT();
    }
    for (int kc = 0; kc < 2; kc++) {
        if (kc == 0) {
            int kk0 = 32;
            uint32_t so = STG128;
            CPLD128(Abh, D_, uAh + so); CPLD128(Abl, D_, uAl + so); CPLD128(Bbh, D_, uBh + so);
            CPA_COMMIT();
            CPA_WAIT1();
        } else {
            CPA_WAIT0();
        }
        __syncthreads();
        uint32_t so = (uint32_t)((kc & 1) * STG128);
        mma_tile<2>(uAh + so, uAl + so, uBh + so, lane, wm0, wn0, acc);
        __syncthreads();
    }
#pragma unroll
    for (int am = 0; am < 2; am++) {
        int r0 = i0 + wm0 + am * 16 + (lane >> 2);
#pragma unroll
        for (int bn = 0; bn < 8; bn++) {
            int cN = j0 + wn0 + bn * 8 + (lane & 3) * 2;
            float* a4 = acc[am][bn];
            *reinterpret_cast<float2*>(g_sc + ((size_t)bh*L_ + r0) * L_ + cN) =
                make_float2(a4[0], a4[1]);
            *reinterpret_cast<float2*>(g_sc + ((size_t)bh*L_ + r0 + 8) * L_ + cN) =
                make_float2(a4[2], a4[3]);
        }
    }
}

// ---------------- attention: bd scatter-add (sc[i][j] += q_i . p_{j-i+L-1}) ----------------
__global__ __launch_bounds__(256) void k_bd() {
    extern __shared__ __half dsm[];
    const int tid = threadIdx.x, wid = tid >> 5, lane = tid & 31;
    const int bh = blockIdx.z, b = bh >> 4, h = bh & 15;
    const int i0 = blockIdx.y * 128, rt = blockIdx.x;
    const int rbase = 896 - i0 + rt * 128;                // global P row of column n=0 (0..1920)
    const int wm0 = (wid & 3) * 32, wn0 = (wid >> 2) * 64;
    const __half* Abh = g_qh + (size_t)(b*L_ + i0) * D_ + h*DH_;
    const __half* Abl = g_ql + (size_t)(b*L_ + i0) * D_ + h*DH_;
    const __half* Bbh = g_ph + (size_t)rbase * D_ + h*DH_;
    const uint32_t base = smem_u32(dsm);
    const uint32_t uAh = base, uAl = base + 2*STG128, uBh = base + 4*STG128;
    float acc[2][8][4] = {};
    {
        int kk0 = 0;
        CPLD128(Abh, D_, uAh); CPLD128(Abl, D_, uAl); CPLD128(Bbh, D_, uBh);
        CPA_COMMIT();
    }
    for (int kc = 0; kc < 2; kc++) {
        if (kc == 0) {
            int kk0 = 32;
            uint32_t so = STG128;
            CPLD128(Abh, D_, uAh + so); CPLD128(Abl, D_, uAl + so); CPLD128(Bbh, D_, uBh + so);
            CPA_COMMIT();
            CPA_WAIT1();
        } else {
            CPA_WAIT0();
        }
        __syncthreads();
        uint32_t so = (uint32_t)((kc & 1) * STG128);
        mma_tile<2>(uAh + so, uAl + so, uBh + so, lane, wm0, wn0, acc);
        __syncthreads();
    }
#pragma unroll
    for (int am = 0; am < 2; am++) {
#pragma unroll
        for (int rr = 0; rr < 2; rr++) {
            int i = i0 + wm0 + am * 16 + (lane >> 2) + rr * 8;
#pragma unroll
            for (int bn = 0; bn < 8; bn++) {
                int nn = wn0 + bn * 8 + (lane & 3) * 2;
#pragma unroll
                for (int c = 0; c < 2; c++) {
                    int j = rbase + nn + c + i - 1023;
                    if (j >= 0 && j < L_) {
                        size_t o = ((size_t)bh*L_ + i) * L_ + j;
                        g_sc[o] += acc[am][bn][rr*2 + c];
                    }
                }
            }
        }
    }
}

// ---------------- softmax (fp32 in, half hi out) ----------------
__global__ __launch_bounds__(256) void k_softmax() {
    __shared__ float red[256];
    size_t row = blockIdx.x;
    const float* r = g_sc + row * L_;
    int tid = threadIdx.x;
    float4 v = reinterpret_cast<const float4*>(r)[tid];
    red[tid] = fmaxf(fmaxf(v.x, v.y), fmaxf(v.z, v.w));
    __syncthreads();
    for (int s = 128; s; s >>= 1) {
        if (tid < s) red[tid] = fmaxf(red[tid], red[tid+s]);
        __syncthreads();
    }
    float mx = red[0];
    __syncthreads();
    v.x = expf(v.x - mx); v.y = expf(v.y - mx);
    v.z = expf(v.z - mx); v.w = expf(v.w - mx);
    red[tid] = v.x + v.y + v.z + v.w;
    __syncthreads();
    for (int s = 128; s; s >>= 1) {
        if (tid < s) red[tid] += red[tid+s];
        __syncthreads();
    }
    float inv = 1.f / red[0];
    size_t o = row * L_ + tid * 4;
    *reinterpret_cast<__half2*>(g_atth + o)     = __floats2half2_rn(v.x * inv, v.y * inv);
    *reinterpret_cast<__half2*>(g_atth + o + 2) = __floats2half2_rn(v.z * inv, v.w * inv);
}

// ---------------- ctx = att @ v (1-pass, half hi out, layout [b*L+i][hd]) ----------------
__global__ __launch_bounds__(256) void k_av() {
    extern __shared__ __half dsm[];
    const int tid = threadIdx.x, wid = tid >> 5, lane = tid & 31;
    const int bh = blockIdx.y, b = bh >> 4, h = bh & 15;
    const int i0 = blockIdx.x * 128;
    const int wm0 = (wid & 3) * 32, wn0 = (wid >> 2) * 32;
    const __half* Abh = g_atth + ((size_t)bh*L_ + i0) * L_;
    const __half* Bbh = g_vth + (size_t)(b*1024 + h*DH_) * 1024;
    const uint32_t base = smem_u32(dsm);
    const uint32_t uAh = base;
    const uint32_t uBh = base + 2*STG128;
    float acc[2][4][4] = {};
    {
        int kk0 = 0;
        CPLD128(Abh, L_, uAh); CPLD64(Bbh, 1024, uBh);
        CPA_COMMIT();
    }
    const int nk = L_ / 32;
    for (int kc = 0; kc < nk; kc++) {
        if (kc + 1 < nk) {
            int kk0 = (kc + 1) * 32;
            uint32_t soA = (uint32_t)(((kc + 1) & 1) * STG128);
            uint32_t soB = (uint32_t)(((kc + 1) & 1) * STG64);
            CPLD128(Abh, L_, uAh + soA);
            CPLD64(Bbh, 1024, uBh + soB);
            CPA_COMMIT();
            CPA_WAIT1();
        } else {
            CPA_WAIT0();
        }
        __syncthreads();
        uint32_t soA = (uint32_t)((kc & 1) * STG128);
        uint32_t soB = (uint32_t)((kc & 1) * STG64);
        mma_tile32(uAh + soA, uBh + soB, lane, wm0, wn0, acc);
        __syncthreads();
    }
#pragma unroll
    for (int am = 0; am < 2; am++) {
        int r0 = i0 + wm0 + am * 16 + (lane >> 2);
#pragma unroll
        for (int bn = 0; bn < 4; bn++) {
            int d = wn0 + bn * 8 + (lane & 3) * 2;
            float* a4 = acc[am][bn];
            *reinterpret_cast<__half2*>(g_ctxh + (size_t)(b*L_ + r0) * D_ + h*DH_ + d) =
                __floats2half2_rn(a4[0], a4[1]);
            *reinterpret_cast<__half2*>(g_ctxh + (size_t)(b*L_ + r0 + 8) * D_ + h*DH_ + d) =
                __floats2half2_rn(a4[2], a4[3]);
        }
    }
}

// ---------------- gating (warp-parallel) ----------------
__global__ __launch_bounds__(256) void k_gates(const float* __restrict__ sw) {
    __shared__ float ts[D_];
    __shared__ float gsm[E_];
    const int tok = blockIdx.x;
    const int tid = threadIdx.x;
    const int wid = tid >> 5, lane = tid & 31;
    const __half2* th = reinterpret_cast<const __half2*>(g_tbh + (size_t)tok * D_);
    const __half2* tl = reinterpret_cast<const __half2*>(g_tbl + (size_t)tok * D_);
#pragma unroll
    for (int q = 0; q < 2; q++) {
        __half2 a = th[tid*2+q], c = tl[tid*2+q];
        ts[tid*4 + q*2 + 0] = __low2float(a)  + __low2float(c);
        ts[tid*4 + q*2 + 1] = __high2float(a) + __high2float(c);
    }
    __syncthreads();
    // 8 warps x 4 experts: lane-strided dot + shfl reduce
#pragma unroll
    for (int sub = 0; sub < 4; sub++) {
        int e = wid * 4 + sub;
        float acc = 0.f;
#pragma unroll 8
        for (int d = lane; d < D_; d += 32)
            acc += ts[d] * sw[d * E_ + e];
        for (int off = 16; off; off >>= 1)
            acc += __shfl_xor_sync(0xffffffffu, acc, off);
        if (lane == 0) gsm[e] = acc;
    }
    __syncthreads();
    if (tid < 32) {
        float gv = 1.f / (1.f + expf(-gsm[tid]));
        bool sel = false;
        for (int r = 0; r < 4; r++) {
            float cand = sel ? -1e30f : gv;
            float bv = cand; int bi = tid;
            for (int off = 16; off; off >>= 1) {
                float ov = __shfl_xor_sync(0xffffffffu, bv, off);
                int oi = __shfl_xor_sync(0xffffffffu, bi, off);
                if (ov > bv || (ov == bv && oi < bi)) { bv = ov; bi = oi; }
            }
            if (tid == bi) sel = true;
        }
        g_gate[tok * E_ + tid] = sel ? gv : 0.f;
    }
}

// ---------------- launch ----------------
extern "C" void kernel_launch(void* const* d_in, const int* in_sizes, int n_in,
                              void* d_out, int out_size) {
    const float* src  = (const float*)d_in[0];
    const float* Wq   = (const float*)d_in[1];
    const float* Wk   = (const float*)d_in[2];
    const float* Wv   = (const float*)d_in[3];
    const float* Wo   = (const float*)d_in[4];
    const float* Wp   = (const float*)d_in[5];
    const float* ln1g = (const float*)d_in[6];
    const float* ln1b = (const float*)d_in[7];
    const float* ln2g = (const float*)d_in[8];
    const float* ln2b = (const float*)d_in[9];
    const float* selw = (const float*)d_in[10];
    const float* keys = (const float*)d_in[11];
    const float* vals = (const float*)d_in[12];
    float* out = (float*)d_out;

    __half *wph,*keyh,*valh;
    __half *x2h,*x2l,*ph,*peh,*pel,*ctxh,*tbh,*tbl,*hbh,*woh;
    float *xr,*gate;
    cudaGetSymbolAddress((void**)&wph, g_wph);
    cudaGetSymbolAddress((void**)&woh, g_woh);
    cudaGetSymbolAddress((void**)&keyh, g_keyh);
    cudaGetSymbolAddress((void**)&valh, g_valh);
    cudaGetSymbolAddress((void**)&x2h, g_x2h);  cudaGetSymbolAddress((void**)&x2l, g_x2l);
    cudaGetSymbolAddress((void**)&peh, g_peh);  cudaGetSymbolAddress((void**)&pel, g_pel);
    cudaGetSymbolAddress((void**)&ph,  g_ph);
    cudaGetSymbolAddress((void**)&ctxh, g_ctxh);
    cudaGetSymbolAddress((void**)&tbh, g_tbh);  cudaGetSymbolAddress((void**)&tbl, g_tbl);
    cudaGetSymbolAddress((void**)&hbh, g_hbh);
    cudaGetSymbolAddress((void**)&xr,  g_xr);
    cudaGetSymbolAddress((void**)&gate, g_gate);
    __half *wqh, *wkh, *wvh;
    cudaGetSymbolAddress((void**)&wqh, g_wqh);
    cudaGetSymbolAddress((void**)&wkh, g_wkh);
    cudaGetSymbolAddress((void**)&wvh, g_wvh);

    // opt-in dynamic smem (>48KB)
    const int SM2  = 6 * STG128;                        // 61440 B (2-pass)
    const int SM1  = 4 * STG128;                        // 40960 B (1-pass)
    const int SMAV = 2 * STG128 + 2 * STG64;            // 30720 B
    cudaFuncSetAttribute((const void*)khg<1,2>, cudaFuncAttributeMaxDynamicSharedMemorySize, SM2);
    cudaFuncSetAttribute((const void*)khg<2,2>, cudaFuncAttributeMaxDynamicSharedMemorySize, SM2);
    cudaFuncSetAttribute((const void*)khg<2,1>, cudaFuncAttributeMaxDynamicSharedMemorySize, SM1);
    cudaFuncSetAttribute((const void*)khg<3,1>, cudaFuncAttributeMaxDynamicSharedMemorySize, SM1);
    cudaFuncSetAttribute((const void*)khg_qkv,  cudaFuncAttributeMaxDynamicSharedMemorySize, SM2);
    cudaFuncSetAttribute((const void*)k_ac,     cudaFuncAttributeMaxDynamicSharedMemorySize, SM2);
    cudaFuncSetAttribute((const void*)k_bd,     cudaFuncAttributeMaxDynamicSharedMemorySize, SM2);
    cudaFuncSetAttribute((const void*)k_av,     cudaFuncAttributeMaxDynamicSharedMemorySize, SMAV);

    // prep: pos-enc (split, fp32 math) + weight transposes (hi only, batched)
    k_pos<<<P2_, 256>>>();
    k_trh5<<<dim3(32, 32, 5), 256>>>(Wq, Wk, Wv, Wo, Wp);
    k_trh<<<dim3(4, 32, E_), 256>>>(keys, keyh, D_, ES_);
    k_trh<<<dim3(32, 128, 1), 256>>>(vals, valh, NC_, D_);

    k_ln<<<T_, 256>>>(src, ln1g, ln1b, x2h, x2l);

    // projections (tensor, 2-pass, pipelined)
    khg_qkv<<<dim3(8, 16, 3), 256, SM2>>>(x2h, x2l, wqh, wkh, wvh);
    khg<1,2><<<dim3(8, 16), 256, SM2>>>(peh, pel, wph, nullptr, ph, nullptr, nullptr, D_);
    k_vts<<<dim3(32, 32, 2), 256>>>();

    // attention (tensor)
    k_ac<<<dim3(8, 8, 32), 256, SM2>>>();
    k_bd<<<dim3(9, 8, 32), 256, SM2>>>();
    k_softmax<<<B_*H_*L_, 256>>>();
    k_av<<<dim3(8, 32), 256, SMAV>>>();
    khg<2,1><<<dim3(8, 16), 256, SM1>>>(ctxh, nullptr, woh, xr, nullptr, src, nullptr, D_);

    // MoE (tensor, 1-pass)
    k_ln<<<T_, 256>>>(xr, ln2g, ln2b, tbh, tbl);
    k_gates<<<T_, 256>>>(selw);
    khg<3,1><<<dim3(32, 16), 256, SM1>>>(tbh, nullptr, keyh, nullptr, hbh, nullptr, gate, D_);
    khg<2,1><<<dim3(8, 16), 256, SM1>>>(hbh, nullptr, valh, out, nullptr, xr, nullptr, NC_);
}

// round 13
// speedup vs baseline: 1.3633x; 1.3633x over previous
#include <cuda_runtime.h>
#include <cuda_fp16.h>
#include <math.h>
#include <stdint.h>

#define B_    2
#define L_    1024
#define D_    1024
#define H_    16
#define DH_   64
#define E_    32
#define ES_   128
#define T_    (B_*L_)
#define P2_   (2*L_-1)
#define NC_   (E_*ES_)
#define BAND_ 1152

// ---------------- helpers ----------------
__device__ __forceinline__ uint32_t smem_u32(const void* p) {
    uint32_t a;
    asm("{ .reg .u64 t; cvta.to.shared.u64 t, %1; cvt.u32.u64 %0, t; }" : "=r"(a) : "l"(p));
    return a;
}
__device__ __forceinline__ void ldsm4(uint32_t& r0, uint32_t& r1, uint32_t& r2, uint32_t& r3, uint32_t addr) {
    asm volatile("ldmatrix.sync.aligned.m8n8.x4.shared.b16 {%0,%1,%2,%3}, [%4];"
        : "=r"(r0), "=r"(r1), "=r"(r2), "=r"(r3) : "r"(addr));
}
__device__ __forceinline__ void mma16816(float* c, const uint32_t* a, uint32_t b0, uint32_t b1) {
    asm volatile("mma.sync.aligned.m16n8k16.row.col.f32.f16.f16.f32 "
        "{%0,%1,%2,%3}, {%4,%5,%6,%7}, {%8,%9}, {%0,%1,%2,%3};"
        : "+f"(c[0]), "+f"(c[1]), "+f"(c[2]), "+f"(c[3])
        : "r"(a[0]), "r"(a[1]), "r"(a[2]), "r"(a[3]), "r"(b0), "r"(b1));
}
__device__ __forceinline__ void cpa16(uint32_t saddr, const void* gaddr) {
    asm volatile("cp.async.ca.shared.global [%0], [%1], 16;" :: "r"(saddr), "l"(gaddr));
}
#define CPA_COMMIT() asm volatile("cp.async.commit_group;" ::: "memory")
#define CPA_WAIT1()  asm volatile("cp.async.wait_group 1;" ::: "memory")
#define CPA_WAIT0()  asm volatile("cp.async.wait_group 0;" ::: "memory")

__device__ __forceinline__ void sp2(float x, float y, __half* ph, __half* pl, size_t idx) {
    __half hx = __float2half_rn(x), hy = __float2half_rn(y);
    *reinterpret_cast<__half2*>(ph + idx) = __halves2half2(hx, hy);
    *reinterpret_cast<__half2*>(pl + idx) = __halves2half2(
        __float2half_rn(x - __half2float(hx)), __float2half_rn(y - __half2float(hy)));
}

template<int PASS>
__device__ __forceinline__ void mma_tile(uint32_t sAh, uint32_t sAl, uint32_t sBh,
                                         int lane, int wm0, int wn0, float acc[2][8][4]) {
#pragma unroll
    for (int ks = 0; ks < 2; ks++) {
        uint32_t bh[16];
        int g = lane >> 3;
#pragma unroll
        for (int p = 0; p < 4; p++) {
            uint32_t bo = (uint32_t)(((wn0 + p*16 + (g>>1)*8 + (lane&7))*40 + ks*16 + (g&1)*8) * 2);
            ldsm4(bh[p*4], bh[p*4+1], bh[p*4+2], bh[p*4+3], sBh + bo);
        }
#pragma unroll
        for (int am = 0; am < 2; am++) {
            uint32_t ah[4], al[4];
            uint32_t ao = (uint32_t)(((wm0 + am*16 + (lane&15))*40 + ks*16 + (lane>>4)*8) * 2);
            ldsm4(ah[0], ah[1], ah[2], ah[3], sAh + ao);
            if (PASS == 2) ldsm4(al[0], al[1], al[2], al[3], sAl + ao);
#pragma unroll
            for (int bn = 0; bn < 8; bn++) {
                mma16816(acc[am][bn], ah, bh[bn*2], bh[bn*2+1]);
                if (PASS == 2) mma16816(acc[am][bn], al, bh[bn*2], bh[bn*2+1]);
            }
        }
    }
}
__device__ __forceinline__ void mma_tile32(uint32_t sAh, uint32_t sBh,
                                           int lane, int wm0, int wn0, float acc[2][4][4]) {
#pragma unroll
    for (int ks = 0; ks < 2; ks++) {
        uint32_t bh[8];
        int g = lane >> 3;
#pragma unroll
        for (int p = 0; p < 2; p++) {
            uint32_t bo = (uint32_t)(((wn0 + p*16 + (g>>1)*8 + (lane&7))*40 + ks*16 + (g&1)*8) * 2);
            ldsm4(bh[p*4], bh[p*4+1], bh[p*4+2], bh[p*4+3], sBh + bo);
        }
#pragma unroll
        for (int am = 0; am < 2; am++) {
            uint32_t ah[4];
            uint32_t ao = (uint32_t)(((wm0 + am*16 + (lane&15))*40 + ks*16 + (lane>>4)*8) * 2);
            ldsm4(ah[0], ah[1], ah[2], ah[3], sAh + ao);
#pragma unroll
            for (int bn = 0; bn < 4; bn++)
                mma16816(acc[am][bn], ah, bh[bn*2], bh[bn*2+1]);
        }
    }
}

#define CPLD128(SRC, KST, DB) do { \
    int _row = tid >> 2, _q = tid & 3; \
    cpa16((DB) + (uint32_t)((_row*40 + _q*8) * 2), &(SRC)[(size_t)_row*(KST) + kk0 + _q*8]); \
    cpa16((DB) + (uint32_t)(((_row+64)*40 + _q*8) * 2), &(SRC)[(size_t)(_row+64)*(KST) + kk0 + _q*8]); \
} while (0)
#define CPLD64(SRC, KST, DB) do { \
    int _row = tid >> 2, _q = tid & 3; \
    cpa16((DB) + (uint32_t)((_row*40 + _q*8) * 2), &(SRC)[(size_t)_row*(KST) + kk0 + _q*8]); \
} while (0)

#define STG128 (128*40*2)
#define STG64  (64*40*2)

// ---------------- scratch ----------------
__device__ __align__(16) __half g_peh [(size_t)2048 * D_];
__device__ __align__(16) __half g_pel [(size_t)2048 * D_];
__device__ __align__(16) __half g_wqh [(size_t)D_ * D_];
__device__ __align__(16) __half g_wkh [(size_t)D_ * D_];
__device__ __align__(16) __half g_wvh [(size_t)D_ * D_];
__device__ __align__(16) __half g_woh [(size_t)D_ * D_];
__device__ __align__(16) __half g_wph [(size_t)D_ * D_];
__device__ __align__(16) __half g_keyh[(size_t)NC_ * D_];
__device__ __align__(16) __half g_valh[(size_t)D_ * NC_];
__device__ __align__(16) __half g_x2h [(size_t)T_ * D_],  g_x2l [(size_t)T_ * D_];
__device__ __align__(16) __half g_qh  [(size_t)T_ * D_],  g_ql  [(size_t)T_ * D_];
__device__ __align__(16) __half g_kh  [(size_t)T_ * D_];
__device__ __align__(16) __half g_vth [(size_t)T_ * D_];
__device__ __align__(16) __half g_ph  [(size_t)2048 * D_];
__device__ __align__(16) __half g_ctxh[(size_t)T_ * D_];
__device__ __align__(16) __half g_tbh [(size_t)T_ * D_],  g_tbl [(size_t)T_ * D_];
__device__ __align__(16) __half g_hbh [(size_t)T_ * NC_];
__device__ __align__(16) __half g_atth[(size_t)B_*H_*L_*L_];
__device__ __align__(16) __half g_qp  [(size_t)B_*H_*8*128*BAND_];    // banded rel-pos scores, 75.5 MB
__device__ __align__(16) float  g_vb  [(size_t)T_ * D_];
__device__ __align__(16) float  g_sc  [(size_t)B_*H_*L_*L_];
__device__ __align__(16) float  g_xr  [(size_t)T_ * D_];
__device__ __align__(16) float  g_gate[(size_t)T_ * E_];

// ---------------- small kernels ----------------
__global__ __launch_bounds__(256) void k_pos() {
    int r = blockIdx.x;
    float pos = (float)(L_ - 1 - r);
    const float c = 9.210340371976184f / 1024.0f;
    for (int m = threadIdx.x; m < D_; m += 256) {
        int j = (m < 512) ? m : m - 512;
        float ang = pos * expf(-c * (float)(2 * j));
        float v = (m < 512) ? sinf(ang) : cosf(ang);
        __half h = __float2half_rn(v);
        g_peh[(size_t)r * D_ + m] = h;
        g_pel[(size_t)r * D_ + m] = __float2half_rn(v - __half2float(h));
    }
}

__global__ __launch_bounds__(256) void k_trh(const float* __restrict__ in,
                                             __half* __restrict__ oh, int R, int C) {
    __shared__ float t[32][33];
    size_t zoff = (size_t)blockIdx.z * R * C;
    int c0 = blockIdx.x * 32, r0 = blockIdx.y * 32;
    int x = threadIdx.x & 31, y = threadIdx.x >> 5;
    for (int i = y; i < 32; i += 8)
        t[i][x] = in[zoff + (size_t)(r0 + i) * C + c0 + x];
    __syncthreads();
    for (int i = y; i < 32; i += 8)
        oh[zoff + (size_t)(c0 + i) * R + r0 + x] = __float2half_rn(t[x][i]);
}

__global__ __launch_bounds__(256) void k_vts() {
    __shared__ float t[32][33];
    int b = blockIdx.z;
    int i0 = blockIdx.x * 32, hd0 = blockIdx.y * 32;
    int x = threadIdx.x & 31, y = threadIdx.x >> 5;
    for (int r = y; r < 32; r += 8)
        t[r][x] = g_vb[(size_t)(b*L_ + i0 + r) * D_ + hd0 + x];
    __syncthreads();
    for (int r = y; r < 32; r += 8)
        g_vth[(size_t)(b*1024 + hd0 + r) * 1024 + i0 + x] = __float2half_rn(t[x][r]);
}

__global__ __launch_bounds__(256) void k_ln(const float* __restrict__ x,
                                            const float* __restrict__ g,
                                            const float* __restrict__ b,
                                            __half* __restrict__ oh, __half* __restrict__ ol) {
    __shared__ float rs[256], rq[256];
    size_t row = blockIdx.x;
    int tid = threadIdx.x;
    float4 v = reinterpret_cast<const float4*>(x + row * D_)[tid];
    rs[tid] = v.x + v.y + v.z + v.w;
    rq[tid] = v.x*v.x + v.y*v.y + v.z*v.z + v.w*v.w;
    __syncthreads();
    for (int s = 128; s; s >>= 1) {
        if (tid < s) { rs[tid] += rs[tid+s]; rq[tid] += rq[tid+s]; }
        __syncthreads();
    }
    float mean = rs[0] * (1.0f / D_);
    float inv  = rsqrtf(rq[0] * (1.0f / D_) - mean * mean + 1e-5f);
    float4 gv = reinterpret_cast<const float4*>(g)[tid];
    float4 bv = reinterpret_cast<const float4*>(b)[tid];
    size_t o = row * D_ + tid * 4;
    sp2((v.x-mean)*inv*gv.x+bv.x, (v.y-mean)*inv*gv.y+bv.y, oh, ol, o);
    sp2((v.z-mean)*inv*gv.z+bv.z, (v.w-mean)*inv*gv.w+bv.w, oh, ol, o + 2);
}

// ---------------- HMMA GEMM ----------------
template<int EPI, int PASS>
__global__ __launch_bounds__(256) void khg(const __half* __restrict__ Ah, const __half* __restrict__ Al,
                                           const __half* __restrict__ Bh,
                                           float* __restrict__ Cf,
                                           __half* __restrict__ Ch,
                                           const float* __restrict__ aux,
                                           const float* __restrict__ gate, int K) {
    extern __shared__ __half dsm[];
    const int tid = threadIdx.x, wid = tid >> 5, lane = tid & 31;
    const int m0 = blockIdx.y * 128, n0 = blockIdx.x * 128;
    const int ldc = gridDim.x * 128;
    const int wm0 = (wid & 3) * 32, wn0 = (wid >> 2) * 64;
    const __half* Abh = Ah + (size_t)m0 * K;
    const __half* Abl = (PASS == 2) ? (Al + (size_t)m0 * K) : nullptr;
    const __half* Bbh = Bh + (size_t)n0 * K;
    const uint32_t base = smem_u32(dsm);
    const uint32_t uAh = base;
    const uint32_t uAl = base + 2*STG128;
    const uint32_t uBh = base + PASS * 2 * STG128;
    float acc[2][8][4] = {};
    const int nk = K / 32;
    {
        int kk0 = 0;
        CPLD128(Abh, K, uAh);
        if (PASS == 2) CPLD128(Abl, K, uAl);
        CPLD128(Bbh, K, uBh);
        CPA_COMMIT();
    }
    for (int kc = 0; kc < nk; kc++) {
        if (kc + 1 < nk) {
            int kk0 = (kc + 1) * 32;
            uint32_t so = (uint32_t)(((kc + 1) & 1) * STG128);
            CPLD128(Abh, K, uAh + so);
            if (PASS == 2) CPLD128(Abl, K, uAl + so);
            CPLD128(Bbh, K, uBh + so);
            CPA_COMMIT();
            CPA_WAIT1();
        } else {
            CPA_WAIT0();
        }
        __syncthreads();
        uint32_t so = (uint32_t)((kc & 1) * STG128);
        mma_tile<PASS>(uAh + so, uAl + so, uBh + so, lane, wm0, wn0, acc);
        __syncthreads();
    }
#pragma unroll
    for (int am = 0; am < 2; am++) {
        int r0 = m0 + wm0 + am * 16 + (lane >> 2);
#pragma unroll
        for (int bn = 0; bn < 8; bn++) {
            int cN = n0 + wn0 + bn * 8 + (lane & 3) * 2;
            float* a4 = acc[am][bn];
            if (EPI == 1) {
                *reinterpret_cast<__half2*>(Ch + (size_t)r0 * ldc + cN)     = __floats2half2_rn(a4[0], a4[1]);
                *reinterpret_cast<__half2*>(Ch + (size_t)(r0+8) * ldc + cN) = __floats2half2_rn(a4[2], a4[3]);
            } else if (EPI == 2) {
                float2 x0 = *reinterpret_cast<const float2*>(aux + (size_t)r0 * ldc + cN);
                float2 x1 = *reinterpret_cast<const float2*>(aux + (size_t)(r0+8) * ldc + cN);
                *reinterpret_cast<float2*>(Cf + (size_t)r0 * ldc + cN)     = make_float2(a4[0]+x0.x, a4[1]+x0.y);
                *reinterpret_cast<float2*>(Cf + (size_t)(r0+8) * ldc + cN) = make_float2(a4[2]+x1.x, a4[3]+x1.y);
            } else {
                int e = cN >> 7;
                float g0 = gate[r0 * E_ + e], g1 = gate[(r0+8) * E_ + e];
                *reinterpret_cast<__half2*>(Ch + (size_t)r0 * ldc + cN) =
                    __floats2half2_rn(fmaxf(a4[0],0.f)*g0, fmaxf(a4[1],0.f)*g0);
                *reinterpret_cast<__half2*>(Ch + (size_t)(r0+8) * ldc + cN) =
                    __floats2half2_rn(fmaxf(a4[2],0.f)*g1, fmaxf(a4[3],0.f)*g1);
            }
        }
    }
}

// QKV fused
__global__ __launch_bounds__(256) void khg_qkv(const __half* __restrict__ Ah, const __half* __restrict__ Al,
                                               const __half* __restrict__ B0h,
                                               const __half* __restrict__ B1h,
                                               const __half* __restrict__ B2h) {
    extern __shared__ __half dsm[];
    const int tid = threadIdx.x, wid = tid >> 5, lane = tid & 31;
    const int m0 = blockIdx.y * 128, n0 = blockIdx.x * 128, z = blockIdx.z;
    const int K = D_;
    const int wm0 = (wid & 3) * 32, wn0 = (wid >> 2) * 64;
    const __half* Bh = (z == 0) ? B0h : (z == 1) ? B1h : B2h;
    const __half* Abh = Ah + (size_t)m0 * K;
    const __half* Abl = Al + (size_t)m0 * K;
    const __half* Bbh = Bh + (size_t)n0 * K;
    const uint32_t base = smem_u32(dsm);
    const uint32_t uAh = base, uAl = base + 2*STG128, uBh = base + 4*STG128;
    float acc[2][8][4] = {};
    const int nk = K / 32;
    {
        int kk0 = 0;
        CPLD128(Abh, K, uAh); CPLD128(Abl, K, uAl); CPLD128(Bbh, K, uBh);
        CPA_COMMIT();
    }
    for (int kc = 0; kc < nk; kc++) {
        if (kc + 1 < nk) {
            int kk0 = (kc + 1) * 32;
            uint32_t so = (uint32_t)(((kc + 1) & 1) * STG128);
            CPLD128(Abh, K, uAh + so); CPLD128(Abl, K, uAl + so); CPLD128(Bbh, K, uBh + so);
            CPA_COMMIT();
            CPA_WAIT1();
        } else {
            CPA_WAIT0();
        }
        __syncthreads();
        uint32_t so = (uint32_t)((kc & 1) * STG128);
        mma_tile<2>(uAh + so, uAl + so, uBh + so, lane, wm0, wn0, acc);
        __syncthreads();
    }
#pragma unroll
    for (int am = 0; am < 2; am++) {
        int r0 = m0 + wm0 + am * 16 + (lane >> 2);
#pragma unroll
        for (int bn = 0; bn < 8; bn++) {
            int cN = n0 + wn0 + bn * 8 + (lane & 3) * 2;
            float* a4 = acc[am][bn];
            if (z == 2) {
                *reinterpret_cast<float2*>(g_vb + (size_t)r0 * D_ + cN)     = make_float2(a4[0], a4[1]);
                *reinterpret_cast<float2*>(g_vb + (size_t)(r0+8) * D_ + cN) = make_float2(a4[2], a4[3]);
            } else if (z == 0) {
                sp2(a4[0]*0.125f, a4[1]*0.125f, g_qh, g_ql, (size_t)r0 * D_ + cN);
                sp2(a4[2]*0.125f, a4[3]*0.125f, g_qh, g_ql, (size_t)(r0+8) * D_ + cN);
            } else {
                *reinterpret_cast<__half2*>(g_kh + (size_t)r0 * D_ + cN)     = __floats2half2_rn(a4[0], a4[1]);
                *reinterpret_cast<__half2*>(g_kh + (size_t)(r0+8) * D_ + cN) = __floats2half2_rn(a4[2], a4[3]);
            }
        }
    }
}

// ---------------- attention: ac = q.k^T (writes sc) ----------------
__global__ __launch_bounds__(256) void k_ac() {
    extern __shared__ __half dsm[];
    const int tid = threadIdx.x, wid = tid >> 5, lane = tid & 31;
    const int bh = blockIdx.z, b = bh >> 4, h = bh & 15;
    const int i0 = blockIdx.y * 128, j0 = blockIdx.x * 128;
    const int wm0 = (wid & 3) * 32, wn0 = (wid >> 2) * 64;
    const __half* Abh = g_qh + (size_t)(b*L_ + i0) * D_ + h*DH_;
    const __half* Abl = g_ql + (size_t)(b*L_ + i0) * D_ + h*DH_;
    const __half* Bbh = g_kh + (size_t)(b*L_ + j0) * D_ + h*DH_;
    const uint32_t base = smem_u32(dsm);
    const uint32_t uAh = base, uAl = base + 2*STG128, uBh = base + 4*STG128;
    float acc[2][8][4] = {};
    {
        int kk0 = 0;
        CPLD128(Abh, D_, uAh); CPLD128(Abl, D_, uAl); CPLD128(Bbh, D_, uBh);
        CPA_COMMIT();
    }
    for (int kc = 0; kc < 2; kc++) {
        if (kc == 0) {
            int kk0 = 32;
            uint32_t so = STG128;
            CPLD128(Abh, D_, uAh + so); CPLD128(Abl, D_, uAl + so); CPLD128(Bbh, D_, uBh + so);
            CPA_COMMIT();
            CPA_WAIT1();
        } else {
            CPA_WAIT0();
        }
        __syncthreads();
        uint32_t so = (uint32_t)((kc & 1) * STG128);
        mma_tile<2>(uAh + so, uAl + so, uBh + so, lane, wm0, wn0, acc);
        __syncthreads();
    }
#pragma unroll
    for (int am = 0; am < 2; am++) {
        int r0 = i0 + wm0 + am * 16 + (lane >> 2);
#pragma unroll
        for (int bn = 0; bn < 8; bn++) {
            int cN = j0 + wn0 + bn * 8 + (lane & 3) * 2;
            float* a4 = acc[am][bn];
            *reinterpret_cast<float2*>(g_sc + ((size_t)bh*L_ + r0) * L_ + cN) =
                make_float2(a4[0], a4[1]);
            *reinterpret_cast<float2*>(g_sc + ((size_t)bh*L_ + r0 + 8) * L_ + cN) =
                make_float2(a4[2], a4[3]);
        }
    }
}

// ---------------- attention: bd -> dense banded qp (half) ----------------
__global__ __launch_bounds__(256) void k_bd() {
    extern __shared__ __half dsm[];
    const int tid = threadIdx.x, wid = tid >> 5, lane = tid & 31;
    const int bh = blockIdx.z, b = bh >> 4, h = bh & 15;
    const int it = blockIdx.y, i0 = it * 128, rt = blockIdx.x;
    const int rbase = 896 - i0 + rt * 128;
    const int wm0 = (wid & 3) * 32, wn0 = (wid >> 2) * 64;
    const __half* Abh = g_qh + (size_t)(b*L_ + i0) * D_ + h*DH_;
    const __half* Abl = g_ql + (size_t)(b*L_ + i0) * D_ + h*DH_;
    const __half* Bbh = g_ph + (size_t)rbase * D_ + h*DH_;
    const uint32_t base = smem_u32(dsm);
    const uint32_t uAh = base, uAl = base + 2*STG128, uBh = base + 4*STG128;
    float acc[2][8][4] = {};
    {
        int kk0 = 0;
        CPLD128(Abh, D_, uAh); CPLD128(Abl, D_, uAl); CPLD128(Bbh, D_, uBh);
        CPA_COMMIT();
    }
    for (int kc = 0; kc < 2; kc++) {
        if (kc == 0) {
            int kk0 = 32;
            uint32_t so = STG128;
            CPLD128(Abh, D_, uAh + so); CPLD128(Abl, D_, uAl + so); CPLD128(Bbh, D_, uBh + so);
            CPA_COMMIT();
            CPA_WAIT1();
        } else {
            CPA_WAIT0();
        }
        __syncthreads();
        uint32_t so = (uint32_t)((kc & 1) * STG128);
        mma_tile<2>(uAh + so, uAl + so, uBh + so, lane, wm0, wn0, acc);
        __syncthreads();
    }
    // dense banded write: qp[((bh*8+it)*128 + il)][rt*128 + col]
    __half* qpb = g_qp + (((size_t)bh * 8 + it) * 128) * BAND_ + rt * 128;
#pragma unroll
    for (int am = 0; am < 2; am++) {
#pragma unroll
        for (int rr = 0; rr < 2; rr++) {
            int il = wm0 + am * 16 + (lane >> 2) + rr * 8;
#pragma unroll
            for (int bn = 0; bn < 8; bn++) {
                int nn = wn0 + bn * 8 + (lane & 3) * 2;
                *reinterpret_cast<__half2*>(qpb + (size_t)il * BAND_ + nn) =
                    __floats2half2_rn(acc[am][bn][rr*2], acc[am][bn][rr*2+1]);
            }
        }
    }
}

// ---------------- softmax: gather ac + banded qp, half att out ----------------
__global__ __launch_bounds__(256) void k_softmax() {
    __shared__ float red[256];
    int bh = blockIdx.x >> 10;
    int i  = blockIdx.x & 1023;
    int il = i & 127;
    const float*  r   = g_sc + (size_t)blockIdx.x * L_;
    const __half* qpr = g_qp + (((size_t)bh * 8 + (i >> 7)) * 128 + il) * BAND_ + (127 - il);
    int tid = threadIdx.x;
    float4 v = reinterpret_cast<const float4*>(r)[tid];
    int jb = tid * 4;
    v.x += __half2float(qpr[jb]);
    v.y += __half2float(qpr[jb + 1]);
    v.z += __half2float(qpr[jb + 2]);
    v.w += __half2float(qpr[jb + 3]);
    red[tid] = fmaxf(fmaxf(v.x, v.y), fmaxf(v.z, v.w));
    __syncthreads();
    for (int s = 128; s; s >>= 1) {
        if (tid < s) red[tid] = fmaxf(red[tid], red[tid+s]);
        __syncthreads();
    }
    float mx = red[0];
    __syncthreads();
    v.x = expf(v.x - mx); v.y = expf(v.y - mx);
    v.z = expf(v.z - mx); v.w = expf(v.w - mx);
    red[tid] = v.x + v.y + v.z + v.w;
    __syncthreads();
    for (int s = 128; s; s >>= 1) {
        if (tid < s) red[tid] += red[tid+s];
        __syncthreads();
    }
    float inv = 1.f / red[0];
    size_t o = (size_t)blockIdx.x * L_ + jb;
    *reinterpret_cast<__half2*>(g_atth + o)     = __floats2half2_rn(v.x * inv, v.y * inv);
    *reinterpret_cast<__half2*>(g_atth + o + 2) = __floats2half2_rn(v.z * inv, v.w * inv);
}

// ---------------- ctx = att @ v (1-pass, half hi out) ----------------
__global__ __launch_bounds__(256) void k_av() {
    extern __shared__ __half dsm[];
    const int tid = threadIdx.x, wid = tid >> 5, lane = tid & 31;
    const int bh = blockIdx.y, b = bh >> 4, h = bh & 15;
    const int i0 = blockIdx.x * 128;
    const int wm0 = (wid & 3) * 32, wn0 = (wid >> 2) * 32;
    const __half* Abh = g_atth + ((size_t)bh*L_ + i0) * L_;
    const __half* Bbh = g_vth + (size_t)(b*1024 + h*DH_) * 1024;
    const uint32_t base = smem_u32(dsm);
    const uint32_t uAh = base;
    const uint32_t uBh = base + 2*STG128;
    float acc[2][4][4] = {};
    {
        int kk0 = 0;
        CPLD128(Abh, L_, uAh); CPLD64(Bbh, 1024, uBh);
        CPA_COMMIT();
    }
    const int nk = L_ / 32;
    for (int kc = 0; kc < nk; kc++) {
        if (kc + 1 < nk) {
            int kk0 = (kc + 1) * 32;
            uint32_t soA = (uint32_t)(((kc + 1) & 1) * STG128);
            uint32_t soB = (uint32_t)(((kc + 1) & 1) * STG64);
            CPLD128(Abh, L_, uAh + soA);
            CPLD64(Bbh, 1024, uBh + soB);
            CPA_COMMIT();
            CPA_WAIT1();
        } else {
            CPA_WAIT0();
        }
        __syncthreads();
        uint32_t soA = (uint32_t)((kc & 1) * STG128);
        uint32_t soB = (uint32_t)((kc & 1) * STG64);
        mma_tile32(uAh + soA, uBh + soB, lane, wm0, wn0, acc);
        __syncthreads();
    }
#pragma unroll
    for (int am = 0; am < 2; am++) {
        int r0 = i0 + wm0 + am * 16 + (lane >> 2);
#pragma unroll
        for (int bn = 0; bn < 4; bn++) {
            int d = wn0 + bn * 8 + (lane & 3) * 2;
            float* a4 = acc[am][bn];
            *reinterpret_cast<__half2*>(g_ctxh + (size_t)(b*L_ + r0) * D_ + h*DH_ + d) =
                __floats2half2_rn(a4[0], a4[1]);
            *reinterpret_cast<__half2*>(g_ctxh + (size_t)(b*L_ + r0 + 8) * D_ + h*DH_ + d) =
                __floats2half2_rn(a4[2], a4[3]);
        }
    }
}

// ---------------- gating (warp-parallel) ----------------
__global__ __launch_bounds__(256) void k_gates(const float* __restrict__ sw) {
    __shared__ float ts[D_];
    __shared__ float gsm[E_];
    const int tok = blockIdx.x;
    const int tid = threadIdx.x;
    const int wid = tid >> 5, lane = tid & 31;
    const __half2* th = reinterpret_cast<const __half2*>(g_tbh + (size_t)tok * D_);
    const __half2* tl = reinterpret_cast<const __half2*>(g_tbl + (size_t)tok * D_);
#pragma unroll
    for (int q = 0; q < 2; q++) {
        __half2 a = th[tid*2+q], c = tl[tid*2+q];
        ts[tid*4 + q*2 + 0] = __low2float(a)  + __low2float(c);
        ts[tid*4 + q*2 + 1] = __high2float(a) + __high2float(c);
    }
    __syncthreads();
#pragma unroll
    for (int sub = 0; sub < 4; sub++) {
        int e = wid * 4 + sub;
        float acc = 0.f;
#pragma unroll 8
        for (int d = lane; d < D_; d += 32)
            acc += ts[d] * sw[d * E_ + e];
        for (int off = 16; off; off >>= 1)
            acc += __shfl_xor_sync(0xffffffffu, acc, off);
        if (lane == 0) gsm[e] = acc;
    }
    __syncthreads();
    if (tid < 32) {
        float gv = 1.f / (1.f + expf(-gsm[tid]));
        bool sel = false;
        for (int r = 0; r < 4; r++) {
            float cand = sel ? -1e30f : gv;
            float bv = cand; int bi = tid;
            for (int off = 16; off; off >>= 1) {
                float ov = __shfl_xor_sync(0xffffffffu, bv, off);
                int oi = __shfl_xor_sync(0xffffffffu, bi, off);
                if (ov > bv || (ov == bv && oi < bi)) { bv = ov; bi = oi; }
            }
            if (tid == bi) sel = true;
        }
        g_gate[tok * E_ + tid] = sel ? gv : 0.f;
    }
}

// ---------------- launch ----------------
extern "C" void kernel_launch(void* const* d_in, const int* in_sizes, int n_in,
                              void* d_out, int out_size) {
    const float* src  = (const float*)d_in[0];
    const float* Wq   = (const float*)d_in[1];
    const float* Wk   = (const float*)d_in[2];
    const float* Wv   = (const float*)d_in[3];
    const float* Wo   = (const float*)d_in[4];
    const float* Wp   = (const float*)d_in[5];
    const float* ln1g = (const float*)d_in[6];
    const float* ln1b = (const float*)d_in[7];
    const float* ln2g = (const float*)d_in[8];
    const float* ln2b = (const float*)d_in[9];
    const float* selw = (const float*)d_in[10];
    const float* keys = (const float*)d_in[11];
    const float* vals = (const float*)d_in[12];
    float* out = (float*)d_out;

    __half *wqh,*wkh,*wvh,*woh,*wph,*keyh,*valh;
    __half *x2h,*x2l,*ph,*peh,*pel,*ctxh,*tbh,*tbl,*hbh;
    float *xr,*gate;
    cudaGetSymbolAddress((void**)&wqh, g_wqh);
    cudaGetSymbolAddress((void**)&wkh, g_wkh);
    cudaGetSymbolAddress((void**)&wvh, g_wvh);
    cudaGetSymbolAddress((void**)&woh, g_woh);
    cudaGetSymbolAddress((void**)&wph, g_wph);
    cudaGetSymbolAddress((void**)&keyh, g_keyh);
    cudaGetSymbolAddress((void**)&valh, g_valh);
    cudaGetSymbolAddress((void**)&x2h, g_x2h);  cudaGetSymbolAddress((void**)&x2l, g_x2l);
    cudaGetSymbolAddress((void**)&peh, g_peh);  cudaGetSymbolAddress((void**)&pel, g_pel);
    cudaGetSymbolAddress((void**)&ph,  g_ph);
    cudaGetSymbolAddress((void**)&ctxh, g_ctxh);
    cudaGetSymbolAddress((void**)&tbh, g_tbh);  cudaGetSymbolAddress((void**)&tbl, g_tbl);
    cudaGetSymbolAddress((void**)&hbh, g_hbh);
    cudaGetSymbolAddress((void**)&xr,  g_xr);
    cudaGetSymbolAddress((void**)&gate, g_gate);

    const int SM2  = 6 * STG128;
    const int SM1  = 4 * STG128;
    const int SMAV = 2 * STG128 + 2 * STG64;
    cudaFuncSetAttribute((const void*)khg<1,2>, cudaFuncAttributeMaxDynamicSharedMemorySize, SM2);
    cudaFuncSetAttribute((const void*)khg<2,1>, cudaFuncAttributeMaxDynamicSharedMemorySize, SM1);
    cudaFuncSetAttribute((const void*)khg<3,1>, cudaFuncAttributeMaxDynamicSharedMemorySize, SM1);
    cudaFuncSetAttribute((const void*)khg_qkv,  cudaFuncAttributeMaxDynamicSharedMemorySize, SM2);
    cudaFuncSetAttribute((const void*)k_ac,     cudaFuncAttributeMaxDynamicSharedMemorySize, SM2);
    cudaFuncSetAttribute((const void*)k_bd,     cudaFuncAttributeMaxDynamicSharedMemorySize, SM2);
    cudaFuncSetAttribute((const void*)k_av,     cudaFuncAttributeMaxDynamicSharedMemorySize, SMAV);

    // prep (separate transposes, as in R11-best)
    k_pos<<<P2_, 256>>>();
    dim3 g1k(32, 32, 1);
    k_trh<<<g1k, 256>>>(Wq, wqh, D_, D_);
    k_trh<<<g1k, 256>>>(Wk, wkh, D_, D_);
    k_trh<<<g1k, 256>>>(Wv, wvh, D_, D_);
    k_trh<<<g1k, 256>>>(Wo, woh, D_, D_);
    k_trh<<<g1k, 256>>>(Wp, wph, D_, D_);
    k_trh<<<dim3(4, 32, E_), 256>>>(keys, keyh, D_, ES_);
    k_trh<<<dim3(32, 128, 1), 256>>>(vals, valh, NC_, D_);

    k_ln<<<T_, 256>>>(src, ln1g, ln1b, x2h, x2l);

    // projections
    khg_qkv<<<dim3(8, 16, 3), 256, SM2>>>(x2h, x2l, wqh, wkh, wvh);
    khg<1,2><<<dim3(8, 16), 256, SM2>>>(peh, pel, wph, nullptr, ph, nullptr, nullptr, D_);
    k_vts<<<dim3(32, 32, 2), 256>>>();

    // attention
    k_ac<<<dim3(8, 8, 32), 256, SM2>>>();
    k_bd<<<dim3(9, 8, 32), 256, SM2>>>();
    k_softmax<<<B_*H_*L_, 256>>>();
    k_av<<<dim3(8, 32), 256, SMAV>>>();
    khg<2,1><<<dim3(8, 16), 256, SM1>>>(ctxh, nullptr, woh, xr, nullptr, src, nullptr, D_);

    // MoE (1-pass)
    k_ln<<<T_, 256>>>(xr, ln2g, ln2b, tbh, tbl);
    k_gates<<<T_, 256>>>(selw);
    khg<3,1><<<dim3(32, 16), 256, SM1>>>(tbh, nullptr, keyh, nullptr, hbh, nullptr, gate, D_);
    khg<2,1><<<dim3(8, 16), 256, SM1>>>(hbh, nullptr, valh, out, nullptr, xr, nullptr, NC_);
}

// round 14
// speedup vs baseline: 1.4002x; 1.0271x over previous
#include <cuda_runtime.h>
#include <cuda_fp16.h>
#include <math.h>
#include <stdint.h>

#define B_    2
#define L_    1024
#define D_    1024
#define H_    16
#define DH_   64
#define E_    32
#define ES_   128
#define T_    (B_*L_)
#define P2_   (2*L_-1)
#define NC_   (E_*ES_)
#define BAND_ 1152

// ---------------- helpers ----------------
__device__ __forceinline__ uint32_t smem_u32(const void* p) {
    uint32_t a;
    asm("{ .reg .u64 t; cvta.to.shared.u64 t, %1; cvt.u32.u64 %0, t; }" : "=r"(a) : "l"(p));
    return a;
}
__device__ __forceinline__ void ldsm4(uint32_t& r0, uint32_t& r1, uint32_t& r2, uint32_t& r3, uint32_t addr) {
    asm volatile("ldmatrix.sync.aligned.m8n8.x4.shared.b16 {%0,%1,%2,%3}, [%4];"
        : "=r"(r0), "=r"(r1), "=r"(r2), "=r"(r3) : "r"(addr));
}
__device__ __forceinline__ void mma16816(float* c, const uint32_t* a, uint32_t b0, uint32_t b1) {
    asm volatile("mma.sync.aligned.m16n8k16.row.col.f32.f16.f16.f32 "
        "{%0,%1,%2,%3}, {%4,%5,%6,%7}, {%8,%9}, {%0,%1,%2,%3};"
        : "+f"(c[0]), "+f"(c[1]), "+f"(c[2]), "+f"(c[3])
        : "r"(a[0]), "r"(a[1]), "r"(a[2]), "r"(a[3]), "r"(b0), "r"(b1));
}
__device__ __forceinline__ void cpa16(uint32_t saddr, const void* gaddr) {
    asm volatile("cp.async.ca.shared.global [%0], [%1], 16;" :: "r"(saddr), "l"(gaddr));
}
#define CPA_COMMIT() asm volatile("cp.async.commit_group;" ::: "memory")
#define CPA_WAIT1()  asm volatile("cp.async.wait_group 1;" ::: "memory")
#define CPA_WAIT0()  asm volatile("cp.async.wait_group 0;" ::: "memory")

__device__ __forceinline__ void sp2(float x, float y, __half* ph, __half* pl, size_t idx) {
    __half hx = __float2half_rn(x), hy = __float2half_rn(y);
    *reinterpret_cast<__half2*>(ph + idx) = __halves2half2(hx, hy);
    *reinterpret_cast<__half2*>(pl + idx) = __halves2half2(
        __float2half_rn(x - __half2float(hx)), __float2half_rn(y - __half2float(hy)));
}

template<int PASS>
__device__ __forceinline__ void mma_tile(uint32_t sAh, uint32_t sAl, uint32_t sBh,
                                         int lane, int wm0, int wn0, float acc[2][8][4]) {
#pragma unroll
    for (int ks = 0; ks < 2; ks++) {
        uint32_t bh[16];
        int g = lane >> 3;
#pragma unroll
        for (int p = 0; p < 4; p++) {
            uint32_t bo = (uint32_t)(((wn0 + p*16 + (g>>1)*8 + (lane&7))*40 + ks*16 + (g&1)*8) * 2);
            ldsm4(bh[p*4], bh[p*4+1], bh[p*4+2], bh[p*4+3], sBh + bo);
        }
#pragma unroll
        for (int am = 0; am < 2; am++) {
            uint32_t ah[4], al[4];
            uint32_t ao = (uint32_t)(((wm0 + am*16 + (lane&15))*40 + ks*16 + (lane>>4)*8) * 2);
            ldsm4(ah[0], ah[1], ah[2], ah[3], sAh + ao);
            if (PASS == 2) ldsm4(al[0], al[1], al[2], al[3], sAl + ao);
#pragma unroll
            for (int bn = 0; bn < 8; bn++) {
                mma16816(acc[am][bn], ah, bh[bn*2], bh[bn*2+1]);
                if (PASS == 2) mma16816(acc[am][bn], al, bh[bn*2], bh[bn*2+1]);
            }
        }
    }
}
__device__ __forceinline__ void mma_tile32(uint32_t sAh, uint32_t sBh,
                                           int lane, int wm0, int wn0, float acc[2][4][4]) {
#pragma unroll
    for (int ks = 0; ks < 2; ks++) {
        uint32_t bh[8];
        int g = lane >> 3;
#pragma unroll
        for (int p = 0; p < 2; p++) {
            uint32_t bo = (uint32_t)(((wn0 + p*16 + (g>>1)*8 + (lane&7))*40 + ks*16 + (g&1)*8) * 2);
            ldsm4(bh[p*4], bh[p*4+1], bh[p*4+2], bh[p*4+3], sBh + bo);
        }
#pragma unroll
        for (int am = 0; am < 2; am++) {
            uint32_t ah[4];
            uint32_t ao = (uint32_t)(((wm0 + am*16 + (lane&15))*40 + ks*16 + (lane>>4)*8) * 2);
            ldsm4(ah[0], ah[1], ah[2], ah[3], sAh + ao);
#pragma unroll
            for (int bn = 0; bn < 4; bn++)
                mma16816(acc[am][bn], ah, bh[bn*2], bh[bn*2+1]);
        }
    }
}

#define CPLD128(SRC, KST, DB) do { \
    int _row = tid >> 2, _q = tid & 3; \
    cpa16((DB) + (uint32_t)((_row*40 + _q*8) * 2), &(SRC)[(size_t)_row*(KST) + kk0 + _q*8]); \
    cpa16((DB) + (uint32_t)(((_row+64)*40 + _q*8) * 2), &(SRC)[(size_t)(_row+64)*(KST) + kk0 + _q*8]); \
} while (0)
#define CPLD64(SRC, KST, DB) do { \
    int _row = tid >> 2, _q = tid & 3; \
    cpa16((DB) + (uint32_t)((_row*40 + _q*8) * 2), &(SRC)[(size_t)_row*(KST) + kk0 + _q*8]); \
} while (0)

#define STG128 (128*40*2)
#define STG64  (64*40*2)

// ---------------- scratch ----------------
__device__ __align__(16) __half g_peh [(size_t)2048 * D_];
__device__ __align__(16) __half g_pel [(size_t)2048 * D_];
__device__ __align__(16) __half g_wqh [(size_t)D_ * D_];
__device__ __align__(16) __half g_wkh [(size_t)D_ * D_];
__device__ __align__(16) __half g_wvh [(size_t)D_ * D_];
__device__ __align__(16) __half g_woh [(size_t)D_ * D_];
__device__ __align__(16) __half g_wph [(size_t)D_ * D_];
__device__ __align__(16) __half g_keyh[(size_t)NC_ * D_];
__device__ __align__(16) __half g_valh[(size_t)D_ * NC_];
__device__ __align__(16) __half g_x2h [(size_t)T_ * D_],  g_x2l [(size_t)T_ * D_];
__device__ __align__(16) __half g_qh  [(size_t)T_ * D_];
__device__ __align__(16) __half g_kh  [(size_t)T_ * D_];
__device__ __align__(16) __half g_vth [(size_t)T_ * D_];
__device__ __align__(16) __half g_ph  [(size_t)2048 * D_];
__device__ __align__(16) __half g_ctxh[(size_t)T_ * D_];
__device__ __align__(16) __half g_tbh [(size_t)T_ * D_],  g_tbl [(size_t)T_ * D_];
__device__ __align__(16) __half g_hbh [(size_t)T_ * NC_];
__device__ __align__(16) __half g_atth[(size_t)B_*H_*L_*L_];
__device__ __align__(16) __half g_qp  [(size_t)B_*H_*8*128*BAND_];
__device__ __align__(16) __half g_sch [(size_t)B_*H_*L_*L_];
__device__ __align__(16) float  g_vb  [(size_t)T_ * D_];
__device__ __align__(16) float  g_xr  [(size_t)T_ * D_];
__device__ __align__(16) float  g_gate[(size_t)T_ * E_];

// ---------------- small kernels ----------------
__global__ __launch_bounds__(256) void k_pos() {
    int r = blockIdx.x;
    float pos = (float)(L_ - 1 - r);
    const float c = 9.210340371976184f / 1024.0f;
    for (int m = threadIdx.x; m < D_; m += 256) {
        int j = (m < 512) ? m : m - 512;
        float ang = pos * expf(-c * (float)(2 * j));
        float v = (m < 512) ? sinf(ang) : cosf(ang);
        __half h = __float2half_rn(v);
        g_peh[(size_t)r * D_ + m] = h;
        g_pel[(size_t)r * D_ + m] = __float2half_rn(v - __half2float(h));
    }
}

__global__ __launch_bounds__(256) void k_trh(const float* __restrict__ in,
                                             __half* __restrict__ oh, int R, int C) {
    __shared__ float t[32][33];
    size_t zoff = (size_t)blockIdx.z * R * C;
    int c0 = blockIdx.x * 32, r0 = blockIdx.y * 32;
    int x = threadIdx.x & 31, y = threadIdx.x >> 5;
    for (int i = y; i < 32; i += 8)
        t[i][x] = in[zoff + (size_t)(r0 + i) * C + c0 + x];
    __syncthreads();
    for (int i = y; i < 32; i += 8)
        oh[zoff + (size_t)(c0 + i) * R + r0 + x] = __float2half_rn(t[x][i]);
}

__global__ __launch_bounds__(256) void k_vts() {
    __shared__ float t[32][33];
    int b = blockIdx.z;
    int i0 = blockIdx.x * 32, hd0 = blockIdx.y * 32;
    int x = threadIdx.x & 31, y = threadIdx.x >> 5;
    for (int r = y; r < 32; r += 8)
        t[r][x] = g_vb[(size_t)(b*L_ + i0 + r) * D_ + hd0 + x];
    __syncthreads();
    for (int r = y; r < 32; r += 8)
        g_vth[(size_t)(b*1024 + hd0 + r) * 1024 + i0 + x] = __float2half_rn(t[x][r]);
}

__global__ __launch_bounds__(256) void k_ln(const float* __restrict__ x,
                                            const float* __restrict__ g,
                                            const float* __restrict__ b,
                                            __half* __restrict__ oh, __half* __restrict__ ol) {
    __shared__ float rs[256], rq[256];
    size_t row = blockIdx.x;
    int tid = threadIdx.x;
    float4 v = reinterpret_cast<const float4*>(x + row * D_)[tid];
    rs[tid] = v.x + v.y + v.z + v.w;
    rq[tid] = v.x*v.x + v.y*v.y + v.z*v.z + v.w*v.w;
    __syncthreads();
    for (int s = 128; s; s >>= 1) {
        if (tid < s) { rs[tid] += rs[tid+s]; rq[tid] += rq[tid+s]; }
        __syncthreads();
    }
    float mean = rs[0] * (1.0f / D_);
    float inv  = rsqrtf(rq[0] * (1.0f / D_) - mean * mean + 1e-5f);
    float4 gv = reinterpret_cast<const float4*>(g)[tid];
    float4 bv = reinterpret_cast<const float4*>(b)[tid];
    size_t o = row * D_ + tid * 4;
    sp2((v.x-mean)*inv*gv.x+bv.x, (v.y-mean)*inv*gv.y+bv.y, oh, ol, o);
    sp2((v.z-mean)*inv*gv.z+bv.z, (v.w-mean)*inv*gv.w+bv.w, oh, ol, o + 2);
}

// ---------------- HMMA GEMM ----------------
template<int EPI, int PASS>
__global__ __launch_bounds__(256) void khg(const __half* __restrict__ Ah, const __half* __restrict__ Al,
                                           const __half* __restrict__ Bh,
                                           float* __restrict__ Cf,
                                           __half* __restrict__ Ch,
                                           const float* __restrict__ aux,
                                           const float* __restrict__ gate, int K) {
    extern __shared__ __half dsm[];
    const int tid = threadIdx.x, wid = tid >> 5, lane = tid & 31;
    const int m0 = blockIdx.y * 128, n0 = blockIdx.x * 128;
    const int ldc = gridDim.x * 128;
    const int wm0 = (wid & 3) * 32, wn0 = (wid >> 2) * 64;
    const __half* Abh = Ah + (size_t)m0 * K;
    const __half* Abl = (PASS == 2) ? (Al + (size_t)m0 * K) : nullptr;
    const __half* Bbh = Bh + (size_t)n0 * K;
    const uint32_t base = smem_u32(dsm);
    const uint32_t uAh = base;
    const uint32_t uAl = base + 2*STG128;
    const uint32_t uBh = base + PASS * 2 * STG128;
    float acc[2][8][4] = {};
    const int nk = K / 32;
    {
        int kk0 = 0;
        CPLD128(Abh, K, uAh);
        if (PASS == 2) CPLD128(Abl, K, uAl);
        CPLD128(Bbh, K, uBh);
        CPA_COMMIT();
    }
    for (int kc = 0; kc < nk; kc++) {
        if (kc + 1 < nk) {
            int kk0 = (kc + 1) * 32;
            uint32_t so = (uint32_t)(((kc + 1) & 1) * STG128);
            CPLD128(Abh, K, uAh + so);
            if (PASS == 2) CPLD128(Abl, K, uAl + so);
            CPLD128(Bbh, K, uBh + so);
            CPA_COMMIT();
            CPA_WAIT1();
        } else {
            CPA_WAIT0();
        }
        __syncthreads();
        uint32_t so = (uint32_t)((kc & 1) * STG128);
        mma_tile<PASS>(uAh + so, uAl + so, uBh + so, lane, wm0, wn0, acc);
        __syncthreads();
    }
#pragma unroll
    for (int am = 0; am < 2; am++) {
        int r0 = m0 + wm0 + am * 16 + (lane >> 2);
#pragma unroll
        for (int bn = 0; bn < 8; bn++) {
            int cN = n0 + wn0 + bn * 8 + (lane & 3) * 2;
            float* a4 = acc[am][bn];
            if (EPI == 1) {
                *reinterpret_cast<__half2*>(Ch + (size_t)r0 * ldc + cN)     = __floats2half2_rn(a4[0], a4[1]);
                *reinterpret_cast<__half2*>(Ch + (size_t)(r0+8) * ldc + cN) = __floats2half2_rn(a4[2], a4[3]);
            } else if (EPI == 2) {
                float2 x0 = *reinterpret_cast<const float2*>(aux + (size_t)r0 * ldc + cN);
                float2 x1 = *reinterpret_cast<const float2*>(aux + (size_t)(r0+8) * ldc + cN);
                *reinterpret_cast<float2*>(Cf + (size_t)r0 * ldc + cN)     = make_float2(a4[0]+x0.x, a4[1]+x0.y);
                *reinterpret_cast<float2*>(Cf + (size_t)(r0+8) * ldc + cN) = make_float2(a4[2]+x1.x, a4[3]+x1.y);
            } else {
                int e = cN >> 7;
                float g0 = gate[r0 * E_ + e], g1 = gate[(r0+8) * E_ + e];
                *reinterpret_cast<__half2*>(Ch + (size_t)r0 * ldc + cN) =
                    __floats2half2_rn(fmaxf(a4[0],0.f)*g0, fmaxf(a4[1],0.f)*g0);
                *reinterpret_cast<__half2*>(Ch + (size_t)(r0+8) * ldc + cN) =
                    __floats2half2_rn(fmaxf(a4[2],0.f)*g1, fmaxf(a4[3],0.f)*g1);
            }
        }
    }
}

// QKV fused: z=0 -> q hi (pre-scaled by 1/8), z=1 -> k hi, z=2 -> v fp32
__global__ __launch_bounds__(256) void khg_qkv(const __half* __restrict__ Ah, const __half* __restrict__ Al,
                                               const __half* __restrict__ B0h,
                                               const __half* __restrict__ B1h,
                                               const __half* __restrict__ B2h) {
    extern __shared__ __half dsm[];
    const int tid = threadIdx.x, wid = tid >> 5, lane = tid & 31;
    const int m0 = blockIdx.y * 128, n0 = blockIdx.x * 128, z = blockIdx.z;
    const int K = D_;
    const int wm0 = (wid & 3) * 32, wn0 = (wid >> 2) * 64;
    const __half* Bh = (z == 0) ? B0h : (z == 1) ? B1h : B2h;
    const __half* Abh = Ah + (size_t)m0 * K;
    const __half* Abl = Al + (size_t)m0 * K;
    const __half* Bbh = Bh + (size_t)n0 * K;
    const uint32_t base = smem_u32(dsm);
    const uint32_t uAh = base, uAl = base + 2*STG128, uBh = base + 4*STG128;
    float acc[2][8][4] = {};
    const int nk = K / 32;
    {
        int kk0 = 0;
        CPLD128(Abh, K, uAh); CPLD128(Abl, K, uAl); CPLD128(Bbh, K, uBh);
        CPA_COMMIT();
    }
    for (int kc = 0; kc < nk; kc++) {
        if (kc + 1 < nk) {
            int kk0 = (kc + 1) * 32;
            uint32_t so = (uint32_t)(((kc + 1) & 1) * STG128);
            CPLD128(Abh, K, uAh + so); CPLD128(Abl, K, uAl + so); CPLD128(Bbh, K, uBh + so);
            CPA_COMMIT();
            CPA_WAIT1();
        } else {
            CPA_WAIT0();
        }
        __syncthreads();
        uint32_t so = (uint32_t)((kc & 1) * STG128);
        mma_tile<2>(uAh + so, uAl + so, uBh + so, lane, wm0, wn0, acc);
        __syncthreads();
    }
#pragma unroll
    for (int am = 0; am < 2; am++) {
        int r0 = m0 + wm0 + am * 16 + (lane >> 2);
#pragma unroll
        for (int bn = 0; bn < 8; bn++) {
            int cN = n0 + wn0 + bn * 8 + (lane & 3) * 2;
            float* a4 = acc[am][bn];
            if (z == 2) {
                *reinterpret_cast<float2*>(g_vb + (size_t)r0 * D_ + cN)     = make_float2(a4[0], a4[1]);
                *reinterpret_cast<float2*>(g_vb + (size_t)(r0+8) * D_ + cN) = make_float2(a4[2], a4[3]);
            } else if (z == 0) {
                *reinterpret_cast<__half2*>(g_qh + (size_t)r0 * D_ + cN) =
                    __floats2half2_rn(a4[0]*0.125f, a4[1]*0.125f);
                *reinterpret_cast<__half2*>(g_qh + (size_t)(r0+8) * D_ + cN) =
                    __floats2half2_rn(a4[2]*0.125f, a4[3]*0.125f);
            } else {
                *reinterpret_cast<__half2*>(g_kh + (size_t)r0 * D_ + cN)     = __floats2half2_rn(a4[0], a4[1]);
                *reinterpret_cast<__half2*>(g_kh + (size_t)(r0+8) * D_ + cN) = __floats2half2_rn(a4[2], a4[3]);
            }
        }
    }
}

// ---------------- attention: ac = q.k^T (1-pass, writes half sc) ----------------
__global__ __launch_bounds__(256) void k_ac() {
    extern __shared__ __half dsm[];
    const int tid = threadIdx.x, wid = tid >> 5, lane = tid & 31;
    const int bh = blockIdx.z, b = bh >> 4, h = bh & 15;
    const int i0 = blockIdx.y * 128, j0 = blockIdx.x * 128;
    const int wm0 = (wid & 3) * 32, wn0 = (wid >> 2) * 64;
    const __half* Abh = g_qh + (size_t)(b*L_ + i0) * D_ + h*DH_;
    const __half* Bbh = g_kh + (size_t)(b*L_ + j0) * D_ + h*DH_;
    const uint32_t base = smem_u32(dsm);
    const uint32_t uAh = base, uBh = base + 2*STG128;
    float acc[2][8][4] = {};
    {
        int kk0 = 0;
        CPLD128(Abh, D_, uAh); CPLD128(Bbh, D_, uBh);
        CPA_COMMIT();
    }
    for (int kc = 0; kc < 2; kc++) {
        if (kc == 0) {
            int kk0 = 32;
            uint32_t so = STG128;
            CPLD128(Abh, D_, uAh + so); CPLD128(Bbh, D_, uBh + so);
            CPA_COMMIT();
            CPA_WAIT1();
        } else {
            CPA_WAIT0();
        }
        __syncthreads();
        uint32_t so = (uint32_t)((kc & 1) * STG128);
        mma_tile<1>(uAh + so, 0u, uBh + so, lane, wm0, wn0, acc);
        __syncthreads();
    }
#pragma unroll
    for (int am = 0; am < 2; am++) {
        int r0 = i0 + wm0 + am * 16 + (lane >> 2);
#pragma unroll
        for (int bn = 0; bn < 8; bn++) {
            int cN = j0 + wn0 + bn * 8 + (lane & 3) * 2;
            float* a4 = acc[am][bn];
            *reinterpret_cast<__half2*>(g_sch + ((size_t)bh*L_ + r0) * L_ + cN) =
                __floats2half2_rn(a4[0], a4[1]);
            *reinterpret_cast<__half2*>(g_sch + ((size_t)bh*L_ + r0 + 8) * L_ + cN) =
                __floats2half2_rn(a4[2], a4[3]);
        }
    }
}

// ---------------- attention: bd -> dense banded qp (1-pass, half) ----------------
__global__ __launch_bounds__(256) void k_bd() {
    extern __shared__ __half dsm[];
    const int tid = threadIdx.x, wid = tid >> 5, lane = tid & 31;
    const int bh = blockIdx.z, b = bh >> 4, h = bh & 15;
    const int it = blockIdx.y, i0 = it * 128, rt = blockIdx.x;
    const int rbase = 896 - i0 + rt * 128;
    const int wm0 = (wid & 3) * 32, wn0 = (wid >> 2) * 64;
    const __half* Abh = g_qh + (size_t)(b*L_ + i0) * D_ + h*DH_;
    const __half* Bbh = g_ph + (size_t)rbase * D_ + h*DH_;
    const uint32_t base = smem_u32(dsm);
    const uint32_t uAh = base, uBh = base + 2*STG128;
    float acc[2][8][4] = {};
    {
        int kk0 = 0;
        CPLD128(Abh, D_, uAh); CPLD128(Bbh, D_, uBh);
        CPA_COMMIT();
    }
    for (int kc = 0; kc < 2; kc++) {
        if (kc == 0) {
            int kk0 = 32;
            uint32_t so = STG128;
            CPLD128(Abh, D_, uAh + so); CPLD128(Bbh, D_, uBh + so);
            CPA_COMMIT();
            CPA_WAIT1();
        } else {
            CPA_WAIT0();
        }
        __syncthreads();
        uint32_t so = (uint32_t)((kc & 1) * STG128);
        mma_tile<1>(uAh + so, 0u, uBh + so, lane, wm0, wn0, acc);
        __syncthreads();
    }
    __half* qpb = g_qp + (((size_t)bh * 8 + it) * 128) * BAND_ + rt * 128;
#pragma unroll
    for (int am = 0; am < 2; am++) {
#pragma unroll
        for (int rr = 0; rr < 2; rr++) {
            int il = wm0 + am * 16 + (lane >> 2) + rr * 8;
#pragma unroll
            for (int bn = 0; bn < 8; bn++) {
                int nn = wn0 + bn * 8 + (lane & 3) * 2;
                *reinterpret_cast<__half2*>(qpb + (size_t)il * BAND_ + nn) =
                    __floats2half2_rn(acc[am][bn][rr*2], acc[am][bn][rr*2+1]);
            }
        }
    }
}

// ---------------- softmax: gather half sc + banded qp, half att out ----------------
__global__ __launch_bounds__(256) void k_softmax() {
    __shared__ float red[256];
    int bh = blockIdx.x >> 10;
    int i  = blockIdx.x & 1023;
    int il = i & 127;
    const __half* r   = g_sch + (size_t)blockIdx.x * L_;
    const __half* qpr = g_qp + (((size_t)bh * 8 + (i >> 7)) * 128 + il) * BAND_ + (127 - il);
    int tid = threadIdx.x;
    int jb = tid * 4;
    const __half2* rp = reinterpret_cast<const __half2*>(r + jb);
    __half2 s0 = rp[0], s1 = rp[1];
    float4 v;
    v.x = __low2float(s0)  + __half2float(qpr[jb]);
    v.y = __high2float(s0) + __half2float(qpr[jb + 1]);
    v.z = __low2float(s1)  + __half2float(qpr[jb + 2]);
    v.w = __high2float(s1) + __half2float(qpr[jb + 3]);
    red[tid] = fmaxf(fmaxf(v.x, v.y), fmaxf(v.z, v.w));
    __syncthreads();
    for (int s = 128; s; s >>= 1) {
        if (tid < s) red[tid] = fmaxf(red[tid], red[tid+s]);
        __syncthreads();
    }
    float mx = red[0];
    __syncthreads();
    v.x = expf(v.x - mx); v.y = expf(v.y - mx);
    v.z = expf(v.z - mx); v.w = expf(v.w - mx);
    red[tid] = v.x + v.y + v.z + v.w;
    __syncthreads();
    for (int s = 128; s; s >>= 1) {
        if (tid < s) red[tid] += red[tid+s];
        __syncthreads();
    }
    float inv = 1.f / red[0];
    size_t o = (size_t)blockIdx.x * L_ + jb;
    *reinterpret_cast<__half2*>(g_atth + o)     = __floats2half2_rn(v.x * inv, v.y * inv);
    *reinterpret_cast<__half2*>(g_atth + o + 2) = __floats2half2_rn(v.z * inv, v.w * inv);
}

// ---------------- ctx = att @ v (1-pass, half hi out) ----------------
__global__ __launch_bounds__(256) void k_av() {
    extern __shared__ __half dsm[];
    const int tid = threadIdx.x, wid = tid >> 5, lane = tid & 31;
    const int bh = blockIdx.y, b = bh >> 4, h = bh & 15;
    const int i0 = blockIdx.x * 128;
    const int wm0 = (wid & 3) * 32, wn0 = (wid >> 2) * 32;
    const __half* Abh = g_atth + ((size_t)bh*L_ + i0) * L_;
    const __half* Bbh = g_vth + (size_t)(b*1024 + h*DH_) * 1024;
    const uint32_t base = smem_u32(dsm);
    const uint32_t uAh = base;
    const uint32_t uBh = base + 2*STG128;
    float acc[2][4][4] = {};
    {
        int kk0 = 0;
        CPLD128(Abh, L_, uAh); CPLD64(Bbh, 1024, uBh);
        CPA_COMMIT();
    }
    const int nk = L_ / 32;
    for (int kc = 0; kc < nk; kc++) {
        if (kc + 1 < nk) {
            int kk0 = (kc + 1) * 32;
            uint32_t soA = (uint32_t)(((kc + 1) & 1) * STG128);
            uint32_t soB = (uint32_t)(((kc + 1) & 1) * STG64);
            CPLD128(Abh, L_, uAh + soA);
            CPLD64(Bbh, 1024, uBh + soB);
            CPA_COMMIT();
            CPA_WAIT1();
        } else {
            CPA_WAIT0();
        }
        __syncthreads();
        uint32_t soA = (uint32_t)((kc & 1) * STG128);
        uint32_t soB = (uint32_t)((kc & 1) * STG64);
        mma_tile32(uAh + soA, uBh + soB, lane, wm0, wn0, acc);
        __syncthreads();
    }
#pragma unroll
    for (int am = 0; am < 2; am++) {
        int r0 = i0 + wm0 + am * 16 + (lane >> 2);
#pragma unroll
        for (int bn = 0; bn < 4; bn++) {
            int d = wn0 + bn * 8 + (lane & 3) * 2;
            float* a4 = acc[am][bn];
            *reinterpret_cast<__half2*>(g_ctxh + (size_t)(b*L_ + r0) * D_ + h*DH_ + d) =
                __floats2half2_rn(a4[0], a4[1]);
            *reinterpret_cast<__half2*>(g_ctxh + (size_t)(b*L_ + r0 + 8) * D_ + h*DH_ + d) =
                __floats2half2_rn(a4[2], a4[3]);
        }
    }
}

// ---------------- gating (warp-parallel) ----------------
__global__ __launch_bounds__(256) void k_gates(const float* __restrict__ sw) {
    __shared__ float ts[D_];
    __shared__ float gsm[E_];
    const int tok = blockIdx.x;
    const int tid = threadIdx.x;
    const int wid = tid >> 5, lane = tid & 31;
    const __half2* th = reinterpret_cast<const __half2*>(g_tbh + (size_t)tok * D_);
    const __half2* tl = reinterpret_cast<const __half2*>(g_tbl + (size_t)tok * D_);
#pragma unroll
    for (int q = 0; q < 2; q++) {
        __half2 a = th[tid*2+q], c = tl[tid*2+q];
        ts[tid*4 + q*2 + 0] = __low2float(a)  + __low2float(c);
        ts[tid*4 + q*2 + 1] = __high2float(a) + __high2float(c);
    }
    __syncthreads();
#pragma unroll
    for (int sub = 0; sub < 4; sub++) {
        int e = wid * 4 + sub;
        float acc = 0.f;
#pragma unroll 8
        for (int d = lane; d < D_; d += 32)
            acc += ts[d] * sw[d * E_ + e];
        for (int off = 16; off; off >>= 1)
            acc += __shfl_xor_sync(0xffffffffu, acc, off);
        if (lane == 0) gsm[e] = acc;
    }
    __syncthreads();
    if (tid < 32) {
        float gv = 1.f / (1.f + expf(-gsm[tid]));
        bool sel = false;
        for (int r = 0; r < 4; r++) {
            float cand = sel ? -1e30f : gv;
            float bv = cand; int bi = tid;
            for (int off = 16; off; off >>= 1) {
                float ov = __shfl_xor_sync(0xffffffffu, bv, off);
                int oi = __shfl_xor_sync(0xffffffffu, bi, off);
                if (ov > bv || (ov == bv && oi < bi)) { bv = ov; bi = oi; }
            }
            if (tid == bi) sel = true;
        }
        g_gate[tok * E_ + tid] = sel ? gv : 0.f;
    }
}

// ---------------- launch ----------------
extern "C" void kernel_launch(void* const* d_in, const int* in_sizes, int n_in,
                              void* d_out, int out_size) {
    const float* src  = (const float*)d_in[0];
    const float* Wq   = (const float*)d_in[1];
    const float* Wk   = (const float*)d_in[2];
    const float* Wv   = (const float*)d_in[3];
    const float* Wo   = (const float*)d_in[4];
    const float* Wp   = (const float*)d_in[5];
    const float* ln1g = (const float*)d_in[6];
    const float* ln1b = (const float*)d_in[7];
    const float* ln2g = (const float*)d_in[8];
    const float* ln2b = (const float*)d_in[9];
    const float* selw = (const float*)d_in[10];
    const float* keys = (const float*)d_in[11];
    const float* vals = (const float*)d_in[12];
    float* out = (float*)d_out;

    __half *wqh,*wkh,*wvh,*woh,*wph,*keyh,*valh;
    __half *x2h,*x2l,*ph,*peh,*pel,*ctxh,*tbh,*tbl,*hbh;
    float *xr,*gate;
    cudaGetSymbolAddress((void**)&wqh, g_wqh);
    cudaGetSymbolAddress((void**)&wkh, g_wkh);
    cudaGetSymbolAddress((void**)&wvh, g_wvh);
    cudaGetSymbolAddress((void**)&woh, g_woh);
    cudaGetSymbolAddress((void**)&wph, g_wph);
    cudaGetSymbolAddress((void**)&keyh, g_keyh);
    cudaGetSymbolAddress((void**)&valh, g_valh);
    cudaGetSymbolAddress((void**)&x2h, g_x2h);  cudaGetSymbolAddress((void**)&x2l, g_x2l);
    cudaGetSymbolAddress((void**)&peh, g_peh);  cudaGetSymbolAddress((void**)&pel, g_pel);
    cudaGetSymbolAddress((void**)&ph,  g_ph);
    cudaGetSymbolAddress((void**)&ctxh, g_ctxh);
    cudaGetSymbolAddress((void**)&tbh, g_tbh);  cudaGetSymbolAddress((void**)&tbl, g_tbl);
    cudaGetSymbolAddress((void**)&hbh, g_hbh);
    cudaGetSymbolAddress((void**)&xr,  g_xr);
    cudaGetSymbolAddress((void**)&gate, g_gate);

    const int SM2  = 6 * STG128;
    const int SM1  = 4 * STG128;
    const int SMAV = 2 * STG128 + 2 * STG64;
    cudaFuncSetAttribute((const void*)khg<1,2>, cudaFuncAttributeMaxDynamicSharedMemorySize, SM2);
    cudaFuncSetAttribute((const void*)khg<2,1>, cudaFuncAttributeMaxDynamicSharedMemorySize, SM1);
    cudaFuncSetAttribute((const void*)khg<3,1>, cudaFuncAttributeMaxDynamicSharedMemorySize, SM1);
    cudaFuncSetAttribute((const void*)khg_qkv,  cudaFuncAttributeMaxDynamicSharedMemorySize, SM2);
    cudaFuncSetAttribute((const void*)k_ac,     cudaFuncAttributeMaxDynamicSharedMemorySize, SM1);
    cudaFuncSetAttribute((const void*)k_bd,     cudaFuncAttributeMaxDynamicSharedMemorySize, SM1);
    cudaFuncSetAttribute((const void*)k_av,     cudaFuncAttributeMaxDynamicSharedMemorySize, SMAV);

    // prep
    k_pos<<<P2_, 256>>>();
    dim3 g1k(32, 32, 1);
    k_trh<<<g1k, 256>>>(Wq, wqh, D_, D_);
    k_trh<<<g1k, 256>>>(Wk, wkh, D_, D_);
    k_trh<<<g1k, 256>>>(Wv, wvh, D_, D_);
    k_trh<<<g1k, 256>>>(Wo, woh, D_, D_);
    k_trh<<<g1k, 256>>>(Wp, wph, D_, D_);
    k_trh<<<dim3(4, 32, E_), 256>>>(keys, keyh, D_, ES_);
    k_trh<<<dim3(32, 128, 1), 256>>>(vals, valh, NC_, D_);

    k_ln<<<T_, 256>>>(src, ln1g, ln1b, x2h, x2l);

    // projections
    khg_qkv<<<dim3(8, 16, 3), 256, SM2>>>(x2h, x2l, wqh, wkh, wvh);
    khg<1,2><<<dim3(8, 16), 256, SM2>>>(peh, pel, wph, nullptr, ph, nullptr, nullptr, D_);
    k_vts<<<dim3(32, 32, 2), 256>>>();

    // attention (1-pass logits, half sc)
    k_ac<<<dim3(8, 8, 32), 256, SM1>>>();
    k_bd<<<dim3(9, 8, 32), 256, SM1>>>();
    k_softmax<<<B_*H_*L_, 256>>>();
    k_av<<<dim3(8, 32), 256, SMAV>>>();
    khg<2,1><<<dim3(8, 16), 256, SM1>>>(ctxh, nullptr, woh, xr, nullptr, src, nullptr, D_);

    // MoE (1-pass)
    k_ln<<<T_, 256>>>(xr, ln2g, ln2b, tbh, tbl);
    k_gates<<<T_, 256>>>(selw);
    khg<3,1><<<dim3(32, 16), 256, SM1>>>(tbh, nullptr, keyh, nullptr, hbh, nullptr, gate, D_);
    khg<2,1><<<dim3(8, 16), 256, SM1>>>(hbh, nullptr, valh, out, nullptr, xr, nullptr, NC_);
}

// round 15
// speedup vs baseline: 1.4553x; 1.0393x over previous
#include <cuda_runtime.h>
#include <cuda_fp16.h>
#include <math.h>
#include <stdint.h>

#define B_    2
#define L_    1024
#define D_    1024
#define H_    16
#define DH_   64
#define E_    32
#define ES_   128
#define T_    (B_*L_)
#define P2_   (2*L_-1)
#define NC_   (E_*ES_)
#define BAND_ 1152

// ---------------- helpers ----------------
__device__ __forceinline__ uint32_t smem_u32(const void* p) {
    uint32_t a;
    asm("{ .reg .u64 t; cvta.to.shared.u64 t, %1; cvt.u32.u64 %0, t; }" : "=r"(a) : "l"(p));
    return a;
}
__device__ __forceinline__ void ldsm4(uint32_t& r0, uint32_t& r1, uint32_t& r2, uint32_t& r3, uint32_t addr) {
    asm volatile("ldmatrix.sync.aligned.m8n8.x4.shared.b16 {%0,%1,%2,%3}, [%4];"
        : "=r"(r0), "=r"(r1), "=r"(r2), "=r"(r3) : "r"(addr));
}
__device__ __forceinline__ void mma16816(float* c, const uint32_t* a, uint32_t b0, uint32_t b1) {
    asm volatile("mma.sync.aligned.m16n8k16.row.col.f32.f16.f16.f32 "
        "{%0,%1,%2,%3}, {%4,%5,%6,%7}, {%8,%9}, {%0,%1,%2,%3};"
        : "+f"(c[0]), "+f"(c[1]), "+f"(c[2]), "+f"(c[3])
        : "r"(a[0]), "r"(a[1]), "r"(a[2]), "r"(a[3]), "r"(b0), "r"(b1));
}
__device__ __forceinline__ void cpa16(uint32_t saddr, const void* gaddr) {
    asm volatile("cp.async.ca.shared.global [%0], [%1], 16;" :: "r"(saddr), "l"(gaddr));
}
#define CPA_COMMIT() asm volatile("cp.async.commit_group;" ::: "memory")
#define CPA_WAIT1()  asm volatile("cp.async.wait_group 1;" ::: "memory")
#define CPA_WAIT0()  asm volatile("cp.async.wait_group 0;" ::: "memory")

__device__ __forceinline__ void sp2(float x, float y, __half* ph, __half* pl, size_t idx) {
    __half hx = __float2half_rn(x), hy = __float2half_rn(y);
    *reinterpret_cast<__half2*>(ph + idx) = __halves2half2(hx, hy);
    *reinterpret_cast<__half2*>(pl + idx) = __halves2half2(
        __float2half_rn(x - __half2float(hx)), __float2half_rn(y - __half2float(hy)));
}

template<int PASS>
__device__ __forceinline__ void mma_tile(uint32_t sAh, uint32_t sAl, uint32_t sBh,
                                         int lane, int wm0, int wn0, float acc[2][8][4]) {
#pragma unroll
    for (int ks = 0; ks < 2; ks++) {
        uint32_t bh[16];
        int g = lane >> 3;
#pragma unroll
        for (int p = 0; p < 4; p++) {
            uint32_t bo = (uint32_t)(((wn0 + p*16 + (g>>1)*8 + (lane&7))*40 + ks*16 + (g&1)*8) * 2);
            ldsm4(bh[p*4], bh[p*4+1], bh[p*4+2], bh[p*4+3], sBh + bo);
        }
#pragma unroll
        for (int am = 0; am < 2; am++) {
            uint32_t ah[4], al[4];
            uint32_t ao = (uint32_t)(((wm0 + am*16 + (lane&15))*40 + ks*16 + (lane>>4)*8) * 2);
            ldsm4(ah[0], ah[1], ah[2], ah[3], sAh + ao);
            if (PASS == 2) ldsm4(al[0], al[1], al[2], al[3], sAl + ao);
#pragma unroll
            for (int bn = 0; bn < 8; bn++) {
                mma16816(acc[am][bn], ah, bh[bn*2], bh[bn*2+1]);
                if (PASS == 2) mma16816(acc[am][bn], al, bh[bn*2], bh[bn*2+1]);
            }
        }
    }
}
__device__ __forceinline__ void mma_tile32(uint32_t sAh, uint32_t sBh,
                                           int lane, int wm0, int wn0, float acc[2][4][4]) {
#pragma unroll
    for (int ks = 0; ks < 2; ks++) {
        uint32_t bh[8];
        int g = lane >> 3;
#pragma unroll
        for (int p = 0; p < 2; p++) {
            uint32_t bo = (uint32_t)(((wn0 + p*16 + (g>>1)*8 + (lane&7))*40 + ks*16 + (g&1)*8) * 2);
            ldsm4(bh[p*4], bh[p*4+1], bh[p*4+2], bh[p*4+3], sBh + bo);
        }
#pragma unroll
        for (int am = 0; am < 2; am++) {
            uint32_t ah[4];
            uint32_t ao = (uint32_t)(((wm0 + am*16 + (lane&15))*40 + ks*16 + (lane>>4)*8) * 2);
            ldsm4(ah[0], ah[1], ah[2], ah[3], sAh + ao);
#pragma unroll
            for (int bn = 0; bn < 4; bn++)
                mma16816(acc[am][bn], ah, bh[bn*2], bh[bn*2+1]);
        }
    }
}

#define CPLD128(SRC, KST, DB) do { \
    int _row = tid >> 2, _q = tid & 3; \
    cpa16((DB) + (uint32_t)((_row*40 + _q*8) * 2), &(SRC)[(size_t)_row*(KST) + kk0 + _q*8]); \
    cpa16((DB) + (uint32_t)(((_row+64)*40 + _q*8) * 2), &(SRC)[(size_t)(_row+64)*(KST) + kk0 + _q*8]); \
} while (0)
#define CPLD64(SRC, KST, DB) do { \
    int _row = tid >> 2, _q = tid & 3; \
    cpa16((DB) + (uint32_t)((_row*40 + _q*8) * 2), &(SRC)[(size_t)_row*(KST) + kk0 + _q*8]); \
} while (0)

#define STG128 (128*40*2)
#define STG64  (64*40*2)

// ---------------- scratch ----------------
__device__ __align__(16) __half g_peh [(size_t)2048 * D_];
__device__ __align__(16) __half g_pel [(size_t)2048 * D_];
__device__ __align__(16) __half g_wqh [(size_t)D_ * D_];
__device__ __align__(16) __half g_wkh [(size_t)D_ * D_];
__device__ __align__(16) __half g_wvh [(size_t)D_ * D_];
__device__ __align__(16) __half g_woh [(size_t)D_ * D_];
__device__ __align__(16) __half g_wph [(size_t)D_ * D_];
__device__ __align__(16) __half g_keyh[(size_t)NC_ * D_];
__device__ __align__(16) __half g_valh[(size_t)D_ * NC_];
__device__ __align__(16) __half g_x2h [(size_t)T_ * D_],  g_x2l [(size_t)T_ * D_];
__device__ __align__(16) __half g_qh  [(size_t)T_ * D_];
__device__ __align__(16) __half g_kh  [(size_t)T_ * D_];
__device__ __align__(16) __half g_vth [(size_t)T_ * D_];
__device__ __align__(16) __half g_ph  [(size_t)2048 * D_];
__device__ __align__(16) __half g_ctxh[(size_t)T_ * D_];
__device__ __align__(16) __half g_tbh [(size_t)T_ * D_],  g_tbl [(size_t)T_ * D_];
__device__ __align__(16) __half g_hbh [(size_t)T_ * NC_];
__device__ __align__(16) __half g_qp  [(size_t)B_*H_*8*128*BAND_];
__device__ __align__(16) float  g_vb  [(size_t)T_ * D_];
__device__ __align__(16) float  g_xr  [(size_t)T_ * D_];
__device__ __align__(16) float  g_gate[(size_t)T_ * E_];

// ---------------- small kernels ----------------
__global__ __launch_bounds__(256) void k_pos() {
    int r = blockIdx.x;
    float pos = (float)(L_ - 1 - r);
    const float c = 9.210340371976184f / 1024.0f;
    for (int m = threadIdx.x; m < D_; m += 256) {
        int j = (m < 512) ? m : m - 512;
        float ang = pos * expf(-c * (float)(2 * j));
        float v = (m < 512) ? sinf(ang) : cosf(ang);
        __half h = __float2half_rn(v);
        g_peh[(size_t)r * D_ + m] = h;
        g_pel[(size_t)r * D_ + m] = __float2half_rn(v - __half2float(h));
    }
}

__global__ __launch_bounds__(256) void k_trh(const float* __restrict__ in,
                                             __half* __restrict__ oh, int R, int C) {
    __shared__ float t[32][33];
    size_t zoff = (size_t)blockIdx.z * R * C;
    int c0 = blockIdx.x * 32, r0 = blockIdx.y * 32;
    int x = threadIdx.x & 31, y = threadIdx.x >> 5;
    for (int i = y; i < 32; i += 8)
        t[i][x] = in[zoff + (size_t)(r0 + i) * C + c0 + x];
    __syncthreads();
    for (int i = y; i < 32; i += 8)
        oh[zoff + (size_t)(c0 + i) * R + r0 + x] = __float2half_rn(t[x][i]);
}

__global__ __launch_bounds__(256) void k_vts() {
    __shared__ float t[32][33];
    int b = blockIdx.z;
    int i0 = blockIdx.x * 32, hd0 = blockIdx.y * 32;
    int x = threadIdx.x & 31, y = threadIdx.x >> 5;
    for (int r = y; r < 32; r += 8)
        t[r][x] = g_vb[(size_t)(b*L_ + i0 + r) * D_ + hd0 + x];
    __syncthreads();
    for (int r = y; r < 32; r += 8)
        g_vth[(size_t)(b*1024 + hd0 + r) * 1024 + i0 + x] = __float2half_rn(t[x][r]);
}

__global__ __launch_bounds__(256) void k_ln(const float* __restrict__ x,
                                            const float* __restrict__ g,
                                            const float* __restrict__ b,
                                            __half* __restrict__ oh, __half* __restrict__ ol) {
    __shared__ float rs[256], rq[256];
    size_t row = blockIdx.x;
    int tid = threadIdx.x;
    float4 v = reinterpret_cast<const float4*>(x + row * D_)[tid];
    rs[tid] = v.x + v.y + v.z + v.w;
    rq[tid] = v.x*v.x + v.y*v.y + v.z*v.z + v.w*v.w;
    __syncthreads();
    for (int s = 128; s; s >>= 1) {
        if (tid < s) { rs[tid] += rs[tid+s]; rq[tid] += rq[tid+s]; }
        __syncthreads();
    }
    float mean = rs[0] * (1.0f / D_);
    float inv  = rsqrtf(rq[0] * (1.0f / D_) - mean * mean + 1e-5f);
    float4 gv = reinterpret_cast<const float4*>(g)[tid];
    float4 bv = reinterpret_cast<const float4*>(b)[tid];
    size_t o = row * D_ + tid * 4;
    sp2((v.x-mean)*inv*gv.x+bv.x, (v.y-mean)*inv*gv.y+bv.y, oh, ol, o);
    sp2((v.z-mean)*inv*gv.z+bv.z, (v.w-mean)*inv*gv.w+bv.w, oh, ol, o + 2);
}

// ---------------- HMMA GEMM ----------------
template<int EPI, int PASS>
__global__ __launch_bounds__(256) void khg(const __half* __restrict__ Ah, const __half* __restrict__ Al,
                                           const __half* __restrict__ Bh,
                                           float* __restrict__ Cf,
                                           __half* __restrict__ Ch,
                                           const float* __restrict__ aux,
                                           const float* __restrict__ gate, int K) {
    extern __shared__ __half dsm[];
    const int tid = threadIdx.x, wid = tid >> 5, lane = tid & 31;
    const int m0 = blockIdx.y * 128, n0 = blockIdx.x * 128;
    const int ldc = gridDim.x * 128;
    const int wm0 = (wid & 3) * 32, wn0 = (wid >> 2) * 64;
    const __half* Abh = Ah + (size_t)m0 * K;
    const __half* Abl = (PASS == 2) ? (Al + (size_t)m0 * K) : nullptr;
    const __half* Bbh = Bh + (size_t)n0 * K;
    const uint32_t base = smem_u32(dsm);
    const uint32_t uAh = base;
    const uint32_t uAl = base + 2*STG128;
    const uint32_t uBh = base + PASS * 2 * STG128;
    float acc[2][8][4] = {};
    const int nk = K / 32;
    {
        int kk0 = 0;
        CPLD128(Abh, K, uAh);
        if (PASS == 2) CPLD128(Abl, K, uAl);
        CPLD128(Bbh, K, uBh);
        CPA_COMMIT();
    }
    for (int kc = 0; kc < nk; kc++) {
        if (kc + 1 < nk) {
            int kk0 = (kc + 1) * 32;
            uint32_t so = (uint32_t)(((kc + 1) & 1) * STG128);
            CPLD128(Abh, K, uAh + so);
            if (PASS == 2) CPLD128(Abl, K, uAl + so);
            CPLD128(Bbh, K, uBh + so);
            CPA_COMMIT();
            CPA_WAIT1();
        } else {
            CPA_WAIT0();
        }
        __syncthreads();
        uint32_t so = (uint32_t)((kc & 1) * STG128);
        mma_tile<PASS>(uAh + so, uAl + so, uBh + so, lane, wm0, wn0, acc);
        __syncthreads();
    }
#pragma unroll
    for (int am = 0; am < 2; am++) {
        int r0 = m0 + wm0 + am * 16 + (lane >> 2);
#pragma unroll
        for (int bn = 0; bn < 8; bn++) {
            int cN = n0 + wn0 + bn * 8 + (lane & 3) * 2;
            float* a4 = acc[am][bn];
            if (EPI == 1) {
                *reinterpret_cast<__half2*>(Ch + (size_t)r0 * ldc + cN)     = __floats2half2_rn(a4[0], a4[1]);
                *reinterpret_cast<__half2*>(Ch + (size_t)(r0+8) * ldc + cN) = __floats2half2_rn(a4[2], a4[3]);
            } else if (EPI == 2) {
                float2 x0 = *reinterpret_cast<const float2*>(aux + (size_t)r0 * ldc + cN);
                float2 x1 = *reinterpret_cast<const float2*>(aux + (size_t)(r0+8) * ldc + cN);
                *reinterpret_cast<float2*>(Cf + (size_t)r0 * ldc + cN)     = make_float2(a4[0]+x0.x, a4[1]+x0.y);
                *reinterpret_cast<float2*>(Cf + (size_t)(r0+8) * ldc + cN) = make_float2(a4[2]+x1.x, a4[3]+x1.y);
            } else {
                int e = cN >> 7;
                float g0 = gate[r0 * E_ + e], g1 = gate[(r0+8) * E_ + e];
                *reinterpret_cast<__half2*>(Ch + (size_t)r0 * ldc + cN) =
                    __floats2half2_rn(fmaxf(a4[0],0.f)*g0, fmaxf(a4[1],0.f)*g0);
                *reinterpret_cast<__half2*>(Ch + (size_t)(r0+8) * ldc + cN) =
                    __floats2half2_rn(fmaxf(a4[2],0.f)*g1, fmaxf(a4[3],0.f)*g1);
            }
        }
    }
}

// QKV fused: z=0 -> q hi (pre-scaled by 1/8), z=1 -> k hi, z=2 -> v fp32
__global__ __launch_bounds__(256) void khg_qkv(const __half* __restrict__ Ah, const __half* __restrict__ Al,
                                               const __half* __restrict__ B0h,
                                               const __half* __restrict__ B1h,
                                               const __half* __restrict__ B2h) {
    extern __shared__ __half dsm[];
    const int tid = threadIdx.x, wid = tid >> 5, lane = tid & 31;
    const int m0 = blockIdx.y * 128, n0 = blockIdx.x * 128, z = blockIdx.z;
    const int K = D_;
    const int wm0 = (wid & 3) * 32, wn0 = (wid >> 2) * 64;
    const __half* Bh = (z == 0) ? B0h : (z == 1) ? B1h : B2h;
    const __half* Abh = Ah + (size_t)m0 * K;
    const __half* Abl = Al + (size_t)m0 * K;
    const __half* Bbh = Bh + (size_t)n0 * K;
    const uint32_t base = smem_u32(dsm);
    const uint32_t uAh = base, uAl = base + 2*STG128, uBh = base + 4*STG128;
    float acc[2][8][4] = {};
    const int nk = K / 32;
    {
        int kk0 = 0;
        CPLD128(Abh, K, uAh); CPLD128(Abl, K, uAl); CPLD128(Bbh, K, uBh);
        CPA_COMMIT();
    }
    for (int kc = 0; kc < nk; kc++) {
        if (kc + 1 < nk) {
            int kk0 = (kc + 1) * 32;
            uint32_t so = (uint32_t)(((kc + 1) & 1) * STG128);
            CPLD128(Abh, K, uAh + so); CPLD128(Abl, K, uAl + so); CPLD128(Bbh, K, uBh + so);
            CPA_COMMIT();
            CPA_WAIT1();
        } else {
            CPA_WAIT0();
        }
        __syncthreads();
        uint32_t so = (uint32_t)((kc & 1) * STG128);
        mma_tile<2>(uAh + so, uAl + so, uBh + so, lane, wm0, wn0, acc);
        __syncthreads();
    }
#pragma unroll
    for (int am = 0; am < 2; am++) {
        int r0 = m0 + wm0 + am * 16 + (lane >> 2);
#pragma unroll
        for (int bn = 0; bn < 8; bn++) {
            int cN = n0 + wn0 + bn * 8 + (lane & 3) * 2;
            float* a4 = acc[am][bn];
            if (z == 2) {
                *reinterpret_cast<float2*>(g_vb + (size_t)r0 * D_ + cN)     = make_float2(a4[0], a4[1]);
                *reinterpret_cast<float2*>(g_vb + (size_t)(r0+8) * D_ + cN) = make_float2(a4[2], a4[3]);
            } else if (z == 0) {
                *reinterpret_cast<__half2*>(g_qh + (size_t)r0 * D_ + cN) =
                    __floats2half2_rn(a4[0]*0.125f, a4[1]*0.125f);
                *reinterpret_cast<__half2*>(g_qh + (size_t)(r0+8) * D_ + cN) =
                    __floats2half2_rn(a4[2]*0.125f, a4[3]*0.125f);
            } else {
                *reinterpret_cast<__half2*>(g_kh + (size_t)r0 * D_ + cN)     = __floats2half2_rn(a4[0], a4[1]);
                *reinterpret_cast<__half2*>(g_kh + (size_t)(r0+8) * D_ + cN) = __floats2half2_rn(a4[2], a4[3]);
            }
        }
    }
}

// ---------------- attention: bd -> dense banded qp (1-pass, half) ----------------
__global__ __launch_bounds__(256) void k_bd() {
    extern __shared__ __half dsm[];
    const int tid = threadIdx.x, wid = tid >> 5, lane = tid & 31;
    const int bh = blockIdx.z, b = bh >> 4, h = bh & 15;
    const int it = blockIdx.y, i0 = it * 128, rt = blockIdx.x;
    const int rbase = 896 - i0 + rt * 128;
    const int wm0 = (wid & 3) * 32, wn0 = (wid >> 2) * 64;
    const __half* Abh = g_qh + (size_t)(b*L_ + i0) * D_ + h*DH_;
    const __half* Bbh = g_ph + (size_t)rbase * D_ + h*DH_;
    const uint32_t base = smem_u32(dsm);
    const uint32_t uAh = base, uBh = base + 2*STG128;
    float acc[2][8][4] = {};
    {
        int kk0 = 0;
        CPLD128(Abh, D_, uAh); CPLD128(Bbh, D_, uBh);
        CPA_COMMIT();
    }
    for (int kc = 0; kc < 2; kc++) {
        if (kc == 0) {
            int kk0 = 32;
            uint32_t so = STG128;
            CPLD128(Abh, D_, uAh + so); CPLD128(Bbh, D_, uBh + so);
            CPA_COMMIT();
            CPA_WAIT1();
        } else {
            CPA_WAIT0();
        }
        __syncthreads();
        uint32_t so = (uint32_t)((kc & 1) * STG128);
        mma_tile<1>(uAh + so, 0u, uBh + so, lane, wm0, wn0, acc);
        __syncthreads();
    }
    __half* qpb = g_qp + (((size_t)bh * 8 + it) * 128) * BAND_ + rt * 128;
#pragma unroll
    for (int am = 0; am < 2; am++) {
#pragma unroll
        for (int rr = 0; rr < 2; rr++) {
            int il = wm0 + am * 16 + (lane >> 2) + rr * 8;
#pragma unroll
            for (int bn = 0; bn < 8; bn++) {
                int nn = wn0 + bn * 8 + (lane & 3) * 2;
                *reinterpret_cast<__half2*>(qpb + (size_t)il * BAND_ + nn) =
                    __floats2half2_rn(acc[am][bn][rr*2], acc[am][bn][rr*2+1]);
            }
        }
    }
}

// ---------------- flash attention: s = q.k^T + qp ; online softmax ; o += p~.V ----------------
// smem: Q 2*STG128 | K 2*STG128 | P~ 4*STG128 | V 4*STG64 | rmax 128*2 f | rsum 128*2 f
#define FL_SMEM (8*STG128 + 4*STG64 + 2048)
__global__ __launch_bounds__(256) void k_flash() {
    extern __shared__ __half dsm[];
    const int tid = threadIdx.x, wid = tid >> 5, lane = tid & 31;
    const int bh = blockIdx.y, b = bh >> 4, h = bh & 15;
    const int i0 = blockIdx.x * 128;
    const int wm0 = (wid & 3) * 32, wn0s = (wid >> 2) * 64, wn0o = (wid >> 2) * 32;
    const int grp = wid >> 2;
    const uint32_t base = smem_u32(dsm);
    const uint32_t uQ = base;
    const uint32_t uK = base + 2*STG128;
    const uint32_t uP = base + 4*STG128;
    const uint32_t uV = base + 8*STG128;
    __half* pP = dsm + (4*STG128) / 2;
    float* rmax = reinterpret_cast<float*>(dsm + (8*STG128 + 4*STG64) / 2);
    float* rsum = rmax + 256;

    // load q tile once (K=64 -> 2 chunks)
    const __half* Qb = g_qh + (size_t)(b*L_ + i0) * D_ + h*DH_;
    { int kk0 = 0;  CPLD128(Qb, D_, uQ); }
    { int kk0 = 32; CPLD128(Qb, D_, uQ + STG128); }
    CPA_COMMIT();

    const __half* Kb0 = g_kh + (size_t)(b*L_) * D_ + h*DH_;
    const __half* Vb  = g_vth + (size_t)(b*1024 + h*DH_) * 1024;
    const __half* qpb = g_qp + (((size_t)bh * 8 + (i0 >> 7)) * 128) * BAND_;

    float m_run[2][2], l_run[2][2];
    float o[2][4][4] = {};
#pragma unroll
    for (int a = 0; a < 2; a++)
#pragma unroll
        for (int r = 0; r < 2; r++) { m_run[a][r] = -1e30f; l_run[a][r] = 0.f; }

    for (int jt = 0; jt < 8; jt++) {
        int j0 = jt * 128;
        // load k and v tiles
        {
            const __half* Kb = Kb0 + (size_t)j0 * D_;
            { int kk0 = 0;  CPLD128(Kb, D_, uK); }
            { int kk0 = 32; CPLD128(Kb, D_, uK + STG128); }
#pragma unroll
            for (int c = 0; c < 4; c++) { int kk0 = j0 + c * 32; CPLD64(Vb, 1024, uV + c * STG64); }
            CPA_COMMIT();
            CPA_WAIT0();
        }
        __syncthreads();
        // s = q.k^T
        float s[2][8][4] = {};
        mma_tile<1>(uQ, 0u, uK, lane, wm0, wn0s, s);
        mma_tile<1>(uQ + STG128, 0u, uK + STG128, lane, wm0, wn0s, s);
        // + qp band gather
#pragma unroll
        for (int am = 0; am < 2; am++)
#pragma unroll
            for (int rr = 0; rr < 2; rr++) {
                int il = wm0 + am * 16 + (lane >> 2) + rr * 8;
                const __half* qpr = qpb + (size_t)il * BAND_ + (j0 - il + 127);
#pragma unroll
                for (int bn = 0; bn < 8; bn++) {
                    int jc = wn0s + bn * 8 + (lane & 3) * 2;
                    s[am][bn][rr*2]   += __half2float(qpr[jc]);
                    s[am][bn][rr*2+1] += __half2float(qpr[jc + 1]);
                }
            }
        // warp-local row max
        float mt[2][2];
#pragma unroll
        for (int am = 0; am < 2; am++)
#pragma unroll
            for (int rr = 0; rr < 2; rr++) {
                float mv = -1e30f;
#pragma unroll
                for (int bn = 0; bn < 8; bn++)
                    mv = fmaxf(mv, fmaxf(s[am][bn][rr*2], s[am][bn][rr*2+1]));
                mv = fmaxf(mv, __shfl_xor_sync(0xffffffffu, mv, 1));
                mv = fmaxf(mv, __shfl_xor_sync(0xffffffffu, mv, 2));
                mt[am][rr] = mv;
            }
        if ((lane & 3) == 0) {
#pragma unroll
            for (int am = 0; am < 2; am++)
#pragma unroll
                for (int rr = 0; rr < 2; rr++) {
                    int il = wm0 + am * 16 + (lane >> 2) + rr * 8;
                    rmax[il * 2 + grp] = mt[am][rr];
                }
        }
        __syncthreads();
        // combine, exp, rowsum
        float f[2][2], rs_[2][2];
#pragma unroll
        for (int am = 0; am < 2; am++)
#pragma unroll
            for (int rr = 0; rr < 2; rr++) {
                int il = wm0 + am * 16 + (lane >> 2) + rr * 8;
                float mnew = fmaxf(m_run[am][rr], fmaxf(rmax[il*2], rmax[il*2+1]));
                f[am][rr] = expf(m_run[am][rr] - mnew);
                m_run[am][rr] = mnew;
                float sv = 0.f;
#pragma unroll
                for (int bn = 0; bn < 8; bn++) {
                    float e0 = expf(s[am][bn][rr*2]   - mnew);
                    float e1 = expf(s[am][bn][rr*2+1] - mnew);
                    s[am][bn][rr*2] = e0; s[am][bn][rr*2+1] = e1;
                    sv += e0 + e1;
                }
                sv += __shfl_xor_sync(0xffffffffu, sv, 1);
                sv += __shfl_xor_sync(0xffffffffu, sv, 2);
                rs_[am][rr] = sv;
            }
        if ((lane & 3) == 0) {
#pragma unroll
            for (int am = 0; am < 2; am++)
#pragma unroll
                for (int rr = 0; rr < 2; rr++) {
                    int il = wm0 + am * 16 + (lane >> 2) + rr * 8;
                    rsum[il * 2 + grp] = rs_[am][rr];
                }
        }
        // store p~ to smem (half, 40-stride chunks)
#pragma unroll
        for (int am = 0; am < 2; am++)
#pragma unroll
            for (int rr = 0; rr < 2; rr++) {
                int il = wm0 + am * 16 + (lane >> 2) + rr * 8;
#pragma unroll
                for (int bn = 0; bn < 8; bn++) {
                    int jc = wn0s + bn * 8 + (lane & 3) * 2;
                    int ch = jc >> 5;
                    *reinterpret_cast<__half2*>(pP + ch * (STG128/2) + il * 40 + (jc & 31)) =
                        __floats2half2_rn(s[am][bn][rr*2], s[am][bn][rr*2+1]);
                }
            }
        __syncthreads();
        // l update + o rescale
#pragma unroll
        for (int am = 0; am < 2; am++)
#pragma unroll
            for (int rr = 0; rr < 2; rr++) {
                int il = wm0 + am * 16 + (lane >> 2) + rr * 8;
                l_run[am][rr] = l_run[am][rr] * f[am][rr] + rsum[il*2] + rsum[il*2+1];
#pragma unroll
                for (int bn = 0; bn < 4; bn++) {
                    o[am][bn][rr*2]   *= f[am][rr];
                    o[am][bn][rr*2+1] *= f[am][rr];
                }
            }
        // o += p~ . V
#pragma unroll
        for (int c = 0; c < 4; c++)
            mma_tile32(uP + c * STG128, uV + c * STG64, lane, wm0, wn0o, o);
        __syncthreads();
    }
    // write ctx = o / l
#pragma unroll
    for (int am = 0; am < 2; am++) {
        int r0 = i0 + wm0 + am * 16 + (lane >> 2);
        float inv0 = 1.f / l_run[am][0], inv1 = 1.f / l_run[am][1];
#pragma unroll
        for (int bn = 0; bn < 4; bn++) {
            int d = wn0o + bn * 8 + (lane & 3) * 2;
            float* a4 = o[am][bn];
            *reinterpret_cast<__half2*>(g_ctxh + (size_t)(b*L_ + r0) * D_ + h*DH_ + d) =
                __floats2half2_rn(a4[0] * inv0, a4[1] * inv0);
            *reinterpret_cast<__half2*>(g_ctxh + (size_t)(b*L_ + r0 + 8) * D_ + h*DH_ + d) =
                __floats2half2_rn(a4[2] * inv1, a4[3] * inv1);
        }
    }
}

// ---------------- gating (warp-parallel) ----------------
__global__ __launch_bounds__(256) void k_gates(const float* __restrict__ sw) {
    __shared__ float ts[D_];
    __shared__ float gsm[E_];
    const int tok = blockIdx.x;
    const int tid = threadIdx.x;
    const int wid = tid >> 5, lane = tid & 31;
    const __half2* th = reinterpret_cast<const __half2*>(g_tbh + (size_t)tok * D_);
    const __half2* tl = reinterpret_cast<const __half2*>(g_tbl + (size_t)tok * D_);
#pragma unroll
    for (int q = 0; q < 2; q++) {
        __half2 a = th[tid*2+q], c = tl[tid*2+q];
        ts[tid*4 + q*2 + 0] = __low2float(a)  + __low2float(c);
        ts[tid*4 + q*2 + 1] = __high2float(a) + __high2float(c);
    }
    __syncthreads();
#pragma unroll
    for (int sub = 0; sub < 4; sub++) {
        int e = wid * 4 + sub;
        float acc = 0.f;
#pragma unroll 8
        for (int d = lane; d < D_; d += 32)
            acc += ts[d] * sw[d * E_ + e];
        for (int off = 16; off; off >>= 1)
            acc += __shfl_xor_sync(0xffffffffu, acc, off);
        if (lane == 0) gsm[e] = acc;
    }
    __syncthreads();
    if (tid < 32) {
        float gv = 1.f / (1.f + expf(-gsm[tid]));
        bool sel = false;
        for (int r = 0; r < 4; r++) {
            float cand = sel ? -1e30f : gv;
            float bv = cand; int bi = tid;
            for (int off = 16; off; off >>= 1) {
                float ov = __shfl_xor_sync(0xffffffffu, bv, off);
                int oi = __shfl_xor_sync(0xffffffffu, bi, off);
                if (ov > bv || (ov == bv && oi < bi)) { bv = ov; bi = oi; }
            }
            if (tid == bi) sel = true;
        }
        g_gate[tok * E_ + tid] = sel ? gv : 0.f;
    }
}

// ---------------- launch ----------------
extern "C" void kernel_launch(void* const* d_in, const int* in_sizes, int n_in,
                              void* d_out, int out_size) {
    const float* src  = (const float*)d_in[0];
    const float* Wq   = (const float*)d_in[1];
    const float* Wk   = (const float*)d_in[2];
    const float* Wv   = (const float*)d_in[3];
    const float* Wo   = (const float*)d_in[4];
    const float* Wp   = (const float*)d_in[5];
    const float* ln1g = (const float*)d_in[6];
    const float* ln1b = (const float*)d_in[7];
    const float* ln2g = (const float*)d_in[8];
    const float* ln2b = (const float*)d_in[9];
    const float* selw = (const float*)d_in[10];
    const float* keys = (const float*)d_in[11];
    const float* vals = (const float*)d_in[12];
    float* out = (float*)d_out;

    __half *wqh,*wkh,*wvh,*woh,*wph,*keyh,*valh;
    __half *x2h,*x2l,*ph,*peh,*pel,*ctxh,*tbh,*tbl,*hbh;
    float *xr,*gate;
    cudaGetSymbolAddress((void**)&wqh, g_wqh);
    cudaGetSymbolAddress((void**)&wkh, g_wkh);
    cudaGetSymbolAddress((void**)&wvh, g_wvh);
    cudaGetSymbolAddress((void**)&woh, g_woh);
    cudaGetSymbolAddress((void**)&wph, g_wph);
    cudaGetSymbolAddress((void**)&keyh, g_keyh);
    cudaGetSymbolAddress((void**)&valh, g_valh);
    cudaGetSymbolAddress((void**)&x2h, g_x2h);  cudaGetSymbolAddress((void**)&x2l, g_x2l);
    cudaGetSymbolAddress((void**)&peh, g_peh);  cudaGetSymbolAddress((void**)&pel, g_pel);
    cudaGetSymbolAddress((void**)&ph,  g_ph);
    cudaGetSymbolAddress((void**)&ctxh, g_ctxh);
    cudaGetSymbolAddress((void**)&tbh, g_tbh);  cudaGetSymbolAddress((void**)&tbl, g_tbl);
    cudaGetSymbolAddress((void**)&hbh, g_hbh);
    cudaGetSymbolAddress((void**)&xr,  g_xr);
    cudaGetSymbolAddress((void**)&gate, g_gate);

    const int SM2  = 6 * STG128;
    const int SM1  = 4 * STG128;
    cudaFuncSetAttribute((const void*)khg<1,2>, cudaFuncAttributeMaxDynamicSharedMemorySize, SM2);
    cudaFuncSetAttribute((const void*)khg<2,1>, cudaFuncAttributeMaxDynamicSharedMemorySize, SM1);
    cudaFuncSetAttribute((const void*)khg<3,1>, cudaFuncAttributeMaxDynamicSharedMemorySize, SM1);
    cudaFuncSetAttribute((const void*)khg_qkv,  cudaFuncAttributeMaxDynamicSharedMemorySize, SM2);
    cudaFuncSetAttribute((const void*)k_bd,     cudaFuncAttributeMaxDynamicSharedMemorySize, SM1);
    cudaFuncSetAttribute((const void*)k_flash,  cudaFuncAttributeMaxDynamicSharedMemorySize, FL_SMEM);

    // prep
    k_pos<<<P2_, 256>>>();
    dim3 g1k(32, 32, 1);
    k_trh<<<g1k, 256>>>(Wq, wqh, D_, D_);
    k_trh<<<g1k, 256>>>(Wk, wkh, D_, D_);
    k_trh<<<g1k, 256>>>(Wv, wvh, D_, D_);
    k_trh<<<g1k, 256>>>(Wo, woh, D_, D_);
    k_trh<<<g1k, 256>>>(Wp, wph, D_, D_);
    k_trh<<<dim3(4, 32, E_), 256>>>(keys, keyh, D_, ES_);
    k_trh<<<dim3(32, 128, 1), 256>>>(vals, valh, NC_, D_);

    k_ln<<<T_, 256>>>(src, ln1g, ln1b, x2h, x2l);

    // projections
    khg_qkv<<<dim3(8, 16, 3), 256, SM2>>>(x2h, x2l, wqh, wkh, wvh);
    khg<1,2><<<dim3(8, 16), 256, SM2>>>(peh, pel, wph, nullptr, ph, nullptr, nullptr, D_);
    k_vts<<<dim3(32, 32, 2), 256>>>();

    // attention: banded bd then fused flash (ac + softmax + av)
    k_bd<<<dim3(9, 8, 32), 256, SM1>>>();
    k_flash<<<dim3(8, 32), 256, FL_SMEM>>>();
    khg<2,1><<<dim3(8, 16), 256, SM1>>>(ctxh, nullptr, woh, xr, nullptr, src, nullptr, D_);

    // MoE (1-pass)
    k_ln<<<T_, 256>>>(xr, ln2g, ln2b, tbh, tbl);
    k_gates<<<T_, 256>>>(selw);
    khg<3,1><<<dim3(32, 16), 256, SM1>>>(tbh, nullptr, keyh, nullptr, hbh, nullptr, gate, D_);
    khg<2,1><<<dim3(8, 16), 256, SM1>>>(hbh, nullptr, valh, out, nullptr, xr, nullptr, NC_);
}

// round 16
// speedup vs baseline: 1.5452x; 1.0618x over previous
#include <cuda_runtime.h>
#include <cuda_fp16.h>
#include <math.h>
#include <stdint.h>

#define B_    2
#define L_    1024
#define D_    1024
#define H_    16
#define DH_   64
#define E_    32
#define ES_   128
#define T_    (B_*L_)
#define P2_   (2*L_-1)
#define NC_   (E_*ES_)
#define BAND_ 1152

// ---------------- helpers ----------------
__device__ __forceinline__ uint32_t smem_u32(const void* p) {
    uint32_t a;
    asm("{ .reg .u64 t; cvta.to.shared.u64 t, %1; cvt.u32.u64 %0, t; }" : "=r"(a) : "l"(p));
    return a;
}
__device__ __forceinline__ void ldsm4(uint32_t& r0, uint32_t& r1, uint32_t& r2, uint32_t& r3, uint32_t addr) {
    asm volatile("ldmatrix.sync.aligned.m8n8.x4.shared.b16 {%0,%1,%2,%3}, [%4];"
        : "=r"(r0), "=r"(r1), "=r"(r2), "=r"(r3) : "r"(addr));
}
__device__ __forceinline__ void mma16816(float* c, const uint32_t* a, uint32_t b0, uint32_t b1) {
    asm volatile("mma.sync.aligned.m16n8k16.row.col.f32.f16.f16.f32 "
        "{%0,%1,%2,%3}, {%4,%5,%6,%7}, {%8,%9}, {%0,%1,%2,%3};"
        : "+f"(c[0]), "+f"(c[1]), "+f"(c[2]), "+f"(c[3])
        : "r"(a[0]), "r"(a[1]), "r"(a[2]), "r"(a[3]), "r"(b0), "r"(b1));
}
__device__ __forceinline__ void cpa16(uint32_t saddr, const void* gaddr) {
    asm volatile("cp.async.ca.shared.global [%0], [%1], 16;" :: "r"(saddr), "l"(gaddr));
}
#define CPA_COMMIT() asm volatile("cp.async.commit_group;" ::: "memory")
#define CPA_WAIT1()  asm volatile("cp.async.wait_group 1;" ::: "memory")
#define CPA_WAIT0()  asm volatile("cp.async.wait_group 0;" ::: "memory")

__device__ __forceinline__ void sp2(float x, float y, __half* ph, __half* pl, size_t idx) {
    __half hx = __float2half_rn(x), hy = __float2half_rn(y);
    *reinterpret_cast<__half2*>(ph + idx) = __halves2half2(hx, hy);
    if (pl)
        *reinterpret_cast<__half2*>(pl + idx) = __halves2half2(
            __float2half_rn(x - __half2float(hx)), __float2half_rn(y - __half2float(hy)));
}

template<int PASS>
__device__ __forceinline__ void mma_tile(uint32_t sAh, uint32_t sAl, uint32_t sBh,
                                         int lane, int wm0, int wn0, float acc[2][8][4]) {
#pragma unroll
    for (int ks = 0; ks < 2; ks++) {
        uint32_t bh[16];
        int g = lane >> 3;
#pragma unroll
        for (int p = 0; p < 4; p++) {
            uint32_t bo = (uint32_t)(((wn0 + p*16 + (g>>1)*8 + (lane&7))*40 + ks*16 + (g&1)*8) * 2);
            ldsm4(bh[p*4], bh[p*4+1], bh[p*4+2], bh[p*4+3], sBh + bo);
        }
#pragma unroll
        for (int am = 0; am < 2; am++) {
            uint32_t ah[4], al[4];
            uint32_t ao = (uint32_t)(((wm0 + am*16 + (lane&15))*40 + ks*16 + (lane>>4)*8) * 2);
            ldsm4(ah[0], ah[1], ah[2], ah[3], sAh + ao);
            if (PASS == 2) ldsm4(al[0], al[1], al[2], al[3], sAl + ao);
#pragma unroll
            for (int bn = 0; bn < 8; bn++) {
                mma16816(acc[am][bn], ah, bh[bn*2], bh[bn*2+1]);
                if (PASS == 2) mma16816(acc[am][bn], al, bh[bn*2], bh[bn*2+1]);
            }
        }
    }
}
__device__ __forceinline__ void mma_tile32(uint32_t sAh, uint32_t sBh,
                                           int lane, int wm0, int wn0, float acc[2][4][4]) {
#pragma unroll
    for (int ks = 0; ks < 2; ks++) {
        uint32_t bh[8];
        int g = lane >> 3;
#pragma unroll
        for (int p = 0; p < 2; p++) {
            uint32_t bo = (uint32_t)(((wn0 + p*16 + (g>>1)*8 + (lane&7))*40 + ks*16 + (g&1)*8) * 2);
            ldsm4(bh[p*4], bh[p*4+1], bh[p*4+2], bh[p*4+3], sBh + bo);
        }
#pragma unroll
        for (int am = 0; am < 2; am++) {
            uint32_t ah[4];
            uint32_t ao = (uint32_t)(((wm0 + am*16 + (lane&15))*40 + ks*16 + (lane>>4)*8) * 2);
            ldsm4(ah[0], ah[1], ah[2], ah[3], sAh + ao);
#pragma unroll
            for (int bn = 0; bn < 4; bn++)
                mma16816(acc[am][bn], ah, bh[bn*2], bh[bn*2+1]);
        }
    }
}

#define CPLD128(SRC, KST, DB) do { \
    int _row = tid >> 2, _q = tid & 3; \
    cpa16((DB) + (uint32_t)((_row*40 + _q*8) * 2), &(SRC)[(size_t)_row*(KST) + kk0 + _q*8]); \
    cpa16((DB) + (uint32_t)(((_row+64)*40 + _q*8) * 2), &(SRC)[(size_t)(_row+64)*(KST) + kk0 + _q*8]); \
} while (0)
#define CPLD64(SRC, KST, DB) do { \
    int _row = tid >> 2, _q = tid & 3; \
    cpa16((DB) + (uint32_t)((_row*40 + _q*8) * 2), &(SRC)[(size_t)_row*(KST) + kk0 + _q*8]); \
} while (0)

#define STG128 (128*40*2)
#define STG64  (64*40*2)

// ---------------- scratch ----------------
__device__ __align__(16) __half g_peh [(size_t)2048 * D_];
__device__ __align__(16) __half g_wqh [(size_t)D_ * D_];
__device__ __align__(16) __half g_wkh [(size_t)D_ * D_];
__device__ __align__(16) __half g_wvh [(size_t)D_ * D_];
__device__ __align__(16) __half g_woh [(size_t)D_ * D_];
__device__ __align__(16) __half g_wph [(size_t)D_ * D_];
__device__ __align__(16) __half g_keyh[(size_t)NC_ * D_];
__device__ __align__(16) __half g_valh[(size_t)D_ * NC_];
__device__ __align__(16) __half g_x2h [(size_t)T_ * D_];
__device__ __align__(16) __half g_qh  [(size_t)T_ * D_];
__device__ __align__(16) __half g_kh  [(size_t)T_ * D_];
__device__ __align__(16) __half g_vth [(size_t)T_ * D_];
__device__ __align__(16) __half g_ph  [(size_t)2048 * D_];
__device__ __align__(16) __half g_ctxh[(size_t)T_ * D_];
__device__ __align__(16) __half g_tbh [(size_t)T_ * D_],  g_tbl [(size_t)T_ * D_];
__device__ __align__(16) __half g_hbh [(size_t)T_ * NC_];
__device__ __align__(16) __half g_qp  [(size_t)B_*H_*8*128*BAND_];
__device__ __align__(16) float  g_vb  [(size_t)T_ * D_];
__device__ __align__(16) float  g_xr  [(size_t)T_ * D_];
__device__ __align__(16) float  g_gate[(size_t)T_ * E_];

// ---------------- small kernels ----------------
__global__ __launch_bounds__(256) void k_pos() {
    int r = blockIdx.x;
    float pos = (float)(L_ - 1 - r);
    const float c = 9.210340371976184f / 1024.0f;
    for (int m = threadIdx.x; m < D_; m += 256) {
        int j = (m < 512) ? m : m - 512;
        float ang = pos * expf(-c * (float)(2 * j));
        float v = (m < 512) ? sinf(ang) : cosf(ang);
        g_peh[(size_t)r * D_ + m] = __float2half_rn(v);
    }
}

__global__ __launch_bounds__(256) void k_trh(const float* __restrict__ in,
                                             __half* __restrict__ oh, int R, int C) {
    __shared__ float t[32][33];
    size_t zoff = (size_t)blockIdx.z * R * C;
    int c0 = blockIdx.x * 32, r0 = blockIdx.y * 32;
    int x = threadIdx.x & 31, y = threadIdx.x >> 5;
    for (int i = y; i < 32; i += 8)
        t[i][x] = in[zoff + (size_t)(r0 + i) * C + c0 + x];
    __syncthreads();
    for (int i = y; i < 32; i += 8)
        oh[zoff + (size_t)(c0 + i) * R + r0 + x] = __float2half_rn(t[x][i]);
}

__global__ __launch_bounds__(256) void k_vts() {
    __shared__ float t[32][33];
    int b = blockIdx.z;
    int i0 = blockIdx.x * 32, hd0 = blockIdx.y * 32;
    int x = threadIdx.x & 31, y = threadIdx.x >> 5;
    for (int r = y; r < 32; r += 8)
        t[r][x] = g_vb[(size_t)(b*L_ + i0 + r) * D_ + hd0 + x];
    __syncthreads();
    for (int r = y; r < 32; r += 8)
        g_vth[(size_t)(b*1024 + hd0 + r) * 1024 + i0 + x] = __float2half_rn(t[x][r]);
}

__global__ __launch_bounds__(256) void k_ln(const float* __restrict__ x,
                                            const float* __restrict__ g,
                                            const float* __restrict__ b,
                                            __half* __restrict__ oh, __half* __restrict__ ol) {
    __shared__ float rs[256], rq[256];
    size_t row = blockIdx.x;
    int tid = threadIdx.x;
    float4 v = reinterpret_cast<const float4*>(x + row * D_)[tid];
    rs[tid] = v.x + v.y + v.z + v.w;
    rq[tid] = v.x*v.x + v.y*v.y + v.z*v.z + v.w*v.w;
    __syncthreads();
    for (int s = 128; s; s >>= 1) {
        if (tid < s) { rs[tid] += rs[tid+s]; rq[tid] += rq[tid+s]; }
        __syncthreads();
    }
    float mean = rs[0] * (1.0f / D_);
    float inv  = rsqrtf(rq[0] * (1.0f / D_) - mean * mean + 1e-5f);
    float4 gv = reinterpret_cast<const float4*>(g)[tid];
    float4 bv = reinterpret_cast<const float4*>(b)[tid];
    size_t o = row * D_ + tid * 4;
    sp2((v.x-mean)*inv*gv.x+bv.x, (v.y-mean)*inv*gv.y+bv.y, oh, ol, o);
    sp2((v.z-mean)*inv*gv.z+bv.z, (v.w-mean)*inv*gv.w+bv.w, oh, ol, o + 2);
}

// ---------------- HMMA GEMM ----------------
template<int EPI, int PASS>
__global__ __launch_bounds__(256) void khg(const __half* __restrict__ Ah, const __half* __restrict__ Al,
                                           const __half* __restrict__ Bh,
                                           float* __restrict__ Cf,
                                           __half* __restrict__ Ch,
                                           const float* __restrict__ aux,
                                           const float* __restrict__ gate, int K) {
    extern __shared__ __half dsm[];
    const int tid = threadIdx.x, wid = tid >> 5, lane = tid & 31;
    const int m0 = blockIdx.y * 128, n0 = blockIdx.x * 128;
    const int ldc = gridDim.x * 128;
    const int wm0 = (wid & 3) * 32, wn0 = (wid >> 2) * 64;
    const __half* Abh = Ah + (size_t)m0 * K;
    const __half* Abl = (PASS == 2) ? (Al + (size_t)m0 * K) : nullptr;
    const __half* Bbh = Bh + (size_t)n0 * K;
    const uint32_t base = smem_u32(dsm);
    const uint32_t uAh = base;
    const uint32_t uAl = base + 2*STG128;
    const uint32_t uBh = base + PASS * 2 * STG128;
    float acc[2][8][4] = {};
    const int nk = K / 32;
    {
        int kk0 = 0;
        CPLD128(Abh, K, uAh);
        if (PASS == 2) CPLD128(Abl, K, uAl);
        CPLD128(Bbh, K, uBh);
        CPA_COMMIT();
    }
    for (int kc = 0; kc < nk; kc++) {
        if (kc + 1 < nk) {
            int kk0 = (kc + 1) * 32;
            uint32_t so = (uint32_t)(((kc + 1) & 1) * STG128);
            CPLD128(Abh, K, uAh + so);
            if (PASS == 2) CPLD128(Abl, K, uAl + so);
            CPLD128(Bbh, K, uBh + so);
            CPA_COMMIT();
            CPA_WAIT1();
        } else {
            CPA_WAIT0();
        }
        __syncthreads();
        uint32_t so = (uint32_t)((kc & 1) * STG128);
        mma_tile<PASS>(uAh + so, uAl + so, uBh + so, lane, wm0, wn0, acc);
        __syncthreads();
    }
#pragma unroll
    for (int am = 0; am < 2; am++) {
        int r0 = m0 + wm0 + am * 16 + (lane >> 2);
#pragma unroll
        for (int bn = 0; bn < 8; bn++) {
            int cN = n0 + wn0 + bn * 8 + (lane & 3) * 2;
            float* a4 = acc[am][bn];
            if (EPI == 1) {
                *reinterpret_cast<__half2*>(Ch + (size_t)r0 * ldc + cN)     = __floats2half2_rn(a4[0], a4[1]);
                *reinterpret_cast<__half2*>(Ch + (size_t)(r0+8) * ldc + cN) = __floats2half2_rn(a4[2], a4[3]);
            } else if (EPI == 2) {
                float2 x0 = *reinterpret_cast<const float2*>(aux + (size_t)r0 * ldc + cN);
                float2 x1 = *reinterpret_cast<const float2*>(aux + (size_t)(r0+8) * ldc + cN);
                *reinterpret_cast<float2*>(Cf + (size_t)r0 * ldc + cN)     = make_float2(a4[0]+x0.x, a4[1]+x0.y);
                *reinterpret_cast<float2*>(Cf + (size_t)(r0+8) * ldc + cN) = make_float2(a4[2]+x1.x, a4[3]+x1.y);
            } else {
                int e = cN >> 7;
                float g0 = gate[r0 * E_ + e], g1 = gate[(r0+8) * E_ + e];
                *reinterpret_cast<__half2*>(Ch + (size_t)r0 * ldc + cN) =
                    __floats2half2_rn(fmaxf(a4[0],0.f)*g0, fmaxf(a4[1],0.f)*g0);
                *reinterpret_cast<__half2*>(Ch + (size_t)(r0+8) * ldc + cN) =
                    __floats2half2_rn(fmaxf(a4[2],0.f)*g1, fmaxf(a4[3],0.f)*g1);
            }
        }
    }
}

// QKV fused (1-pass): z=0 -> q hi (pre-scaled by 1/8), z=1 -> k hi, z=2 -> v fp32
__global__ __launch_bounds__(256) void khg_qkv(const __half* __restrict__ Ah,
                                               const __half* __restrict__ B0h,
                                               const __half* __restrict__ B1h,
                                               const __half* __restrict__ B2h) {
    extern __shared__ __half dsm[];
    const int tid = threadIdx.x, wid = tid >> 5, lane = tid & 31;
    const int m0 = blockIdx.y * 128, n0 = blockIdx.x * 128, z = blockIdx.z;
    const int K = D_;
    const int wm0 = (wid & 3) * 32, wn0 = (wid >> 2) * 64;
    const __half* Bh = (z == 0) ? B0h : (z == 1) ? B1h : B2h;
    const __half* Abh = Ah + (size_t)m0 * K;
    const __half* Bbh = Bh + (size_t)n0 * K;
    const uint32_t base = smem_u32(dsm);
    const uint32_t uAh = base, uBh = base + 2*STG128;
    float acc[2][8][4] = {};
    const int nk = K / 32;
    {
        int kk0 = 0;
        CPLD128(Abh, K, uAh); CPLD128(Bbh, K, uBh);
        CPA_COMMIT();
    }
    for (int kc = 0; kc < nk; kc++) {
        if (kc + 1 < nk) {
            int kk0 = (kc + 1) * 32;
            uint32_t so = (uint32_t)(((kc + 1) & 1) * STG128);
            CPLD128(Abh, K, uAh + so); CPLD128(Bbh, K, uBh + so);
            CPA_COMMIT();
            CPA_WAIT1();
        } else {
            CPA_WAIT0();
        }
        __syncthreads();
        uint32_t so = (uint32_t)((kc & 1) * STG128);
        mma_tile<1>(uAh + so, 0u, uBh + so, lane, wm0, wn0, acc);
        __syncthreads();
    }
#pragma unroll
    for (int am = 0; am < 2; am++) {
        int r0 = m0 + wm0 + am * 16 + (lane >> 2);
#pragma unroll
        for (int bn = 0; bn < 8; bn++) {
            int cN = n0 + wn0 + bn * 8 + (lane & 3) * 2;
            float* a4 = acc[am][bn];
            if (z == 2) {
                *reinterpret_cast<float2*>(g_vb + (size_t)r0 * D_ + cN)     = make_float2(a4[0], a4[1]);
                *reinterpret_cast<float2*>(g_vb + (size_t)(r0+8) * D_ + cN) = make_float2(a4[2], a4[3]);
            } else if (z == 0) {
                *reinterpret_cast<__half2*>(g_qh + (size_t)r0 * D_ + cN) =
                    __floats2half2_rn(a4[0]*0.125f, a4[1]*0.125f);
                *reinterpret_cast<__half2*>(g_qh + (size_t)(r0+8) * D_ + cN) =
                    __floats2half2_rn(a4[2]*0.125f, a4[3]*0.125f);
            } else {
                *reinterpret_cast<__half2*>(g_kh + (size_t)r0 * D_ + cN)     = __floats2half2_rn(a4[0], a4[1]);
                *reinterpret_cast<__half2*>(g_kh + (size_t)(r0+8) * D_ + cN) = __floats2half2_rn(a4[2], a4[3]);
            }
        }
    }
}

// ---------------- attention: bd -> dense banded qp (1-pass, half) ----------------
__global__ __launch_bounds__(256) void k_bd() {
    extern __shared__ __half dsm[];
    const int tid = threadIdx.x, wid = tid >> 5, lane = tid & 31;
    const int bh = blockIdx.z, b = bh >> 4, h = bh & 15;
    const int it = blockIdx.y, i0 = it * 128, rt = blockIdx.x;
    const int rbase = 896 - i0 + rt * 128;
    const int wm0 = (wid & 3) * 32, wn0 = (wid >> 2) * 64;
    const __half* Abh = g_qh + (size_t)(b*L_ + i0) * D_ + h*DH_;
    const __half* Bbh = g_ph + (size_t)rbase * D_ + h*DH_;
    const uint32_t base = smem_u32(dsm);
    const uint32_t uAh = base, uBh = base + 2*STG128;
    float acc[2][8][4] = {};
    {
        int kk0 = 0;
        CPLD128(Abh, D_, uAh); CPLD128(Bbh, D_, uBh);
        CPA_COMMIT();
    }
    for (int kc = 0; kc < 2; kc++) {
        if (kc == 0) {
            int kk0 = 32;
            uint32_t so = STG128;
            CPLD128(Abh, D_, uAh + so); CPLD128(Bbh, D_, uBh + so);
            CPA_COMMIT();
            CPA_WAIT1();
        } else {
            CPA_WAIT0();
        }
        __syncthreads();
        uint32_t so = (uint32_t)((kc & 1) * STG128);
        mma_tile<1>(uAh + so, 0u, uBh + so, lane, wm0, wn0, acc);
        __syncthreads();
    }
    __half* qpb = g_qp + (((size_t)bh * 8 + it) * 128) * BAND_ + rt * 128;
#pragma unroll
    for (int am = 0; am < 2; am++) {
#pragma unroll
        for (int rr = 0; rr < 2; rr++) {
            int il = wm0 + am * 16 + (lane >> 2) + rr * 8;
#pragma unroll
            for (int bn = 0; bn < 8; bn++) {
                int nn = wn0 + bn * 8 + (lane & 3) * 2;
                *reinterpret_cast<__half2*>(qpb + (size_t)il * BAND_ + nn) =
                    __floats2half2_rn(acc[am][bn][rr*2], acc[am][bn][rr*2+1]);
            }
        }
    }
}

// ---------------- flash attention ----------------
#define FL_SMEM (8*STG128 + 4*STG64 + 2048)
__global__ __launch_bounds__(256) void k_flash() {
    extern __shared__ __half dsm[];
    const int tid = threadIdx.x, wid = tid >> 5, lane = tid & 31;
    const int bh = blockIdx.y, b = bh >> 4, h = bh & 15;
    const int i0 = blockIdx.x * 128;
    const int wm0 = (wid & 3) * 32, wn0s = (wid >> 2) * 64, wn0o = (wid >> 2) * 32;
    const int grp = wid >> 2;
    const uint32_t base = smem_u32(dsm);
    const uint32_t uQ = base;
    const uint32_t uK = base + 2*STG128;
    const uint32_t uP = base + 4*STG128;
    const uint32_t uV = base + 8*STG128;
    __half* pP = dsm + (4*STG128) / 2;
    float* rmax = reinterpret_cast<float*>(dsm + (8*STG128 + 4*STG64) / 2);
    float* rsum = rmax + 256;

    const __half* Qb = g_qh + (size_t)(b*L_ + i0) * D_ + h*DH_;
    { int kk0 = 0;  CPLD128(Qb, D_, uQ); }
    { int kk0 = 32; CPLD128(Qb, D_, uQ + STG128); }
    CPA_COMMIT();

    const __half* Kb0 = g_kh + (size_t)(b*L_) * D_ + h*DH_;
    const __half* Vb  = g_vth + (size_t)(b*1024 + h*DH_) * 1024;
    const __half* qpb = g_qp + (((size_t)bh * 8 + (i0 >> 7)) * 128) * BAND_;

    float m_run[2][2], l_run[2][2];
    float o[2][4][4] = {};
#pragma unroll
    for (int a = 0; a < 2; a++)
#pragma unroll
        for (int r = 0; r < 2; r++) { m_run[a][r] = -1e30f; l_run[a][r] = 0.f; }

    for (int jt = 0; jt < 8; jt++) {
        int j0 = jt * 128;
        {
            const __half* Kb = Kb0 + (size_t)j0 * D_;
            { int kk0 = 0;  CPLD128(Kb, D_, uK); }
            { int kk0 = 32; CPLD128(Kb, D_, uK + STG128); }
#pragma unroll
            for (int c = 0; c < 4; c++) { int kk0 = j0 + c * 32; CPLD64(Vb, 1024, uV + c * STG64); }
            CPA_COMMIT();
            CPA_WAIT0();
        }
        __syncthreads();
        float s[2][8][4] = {};
        mma_tile<1>(uQ, 0u, uK, lane, wm0, wn0s, s);
        mma_tile<1>(uQ + STG128, 0u, uK + STG128, lane, wm0, wn0s, s);
#pragma unroll
        for (int am = 0; am < 2; am++)
#pragma unroll
            for (int rr = 0; rr < 2; rr++) {
                int il = wm0 + am * 16 + (lane >> 2) + rr * 8;
                const __half* qpr = qpb + (size_t)il * BAND_ + (j0 - il + 127);
#pragma unroll
                for (int bn = 0; bn < 8; bn++) {
                    int jc = wn0s + bn * 8 + (lane & 3) * 2;
                    s[am][bn][rr*2]   += __half2float(qpr[jc]);
                    s[am][bn][rr*2+1] += __half2float(qpr[jc + 1]);
                }
            }
        float mt[2][2];
#pragma unroll
        for (int am = 0; am < 2; am++)
#pragma unroll
            for (int rr = 0; rr < 2; rr++) {
                float mv = -1e30f;
#pragma unroll
                for (int bn = 0; bn < 8; bn++)
                    mv = fmaxf(mv, fmaxf(s[am][bn][rr*2], s[am][bn][rr*2+1]));
                mv = fmaxf(mv, __shfl_xor_sync(0xffffffffu, mv, 1));
                mv = fmaxf(mv, __shfl_xor_sync(0xffffffffu, mv, 2));
                mt[am][rr] = mv;
            }
        if ((lane & 3) == 0) {
#pragma unroll
            for (int am = 0; am < 2; am++)
#pragma unroll
                for (int rr = 0; rr < 2; rr++) {
                    int il = wm0 + am * 16 + (lane >> 2) + rr * 8;
                    rmax[il * 2 + grp] = mt[am][rr];
                }
        }
        __syncthreads();
        float f[2][2], rs_[2][2];
#pragma unroll
        for (int am = 0; am < 2; am++)
#pragma unroll
            for (int rr = 0; rr < 2; rr++) {
                int il = wm0 + am * 16 + (lane >> 2) + rr * 8;
                float mnew = fmaxf(m_run[am][rr], fmaxf(rmax[il*2], rmax[il*2+1]));
                f[am][rr] = expf(m_run[am][rr] - mnew);
                m_run[am][rr] = mnew;
                float sv = 0.f;
#pragma unroll
                for (int bn = 0; bn < 8; bn++) {
                    float e0 = expf(s[am][bn][rr*2]   - mnew);
                    float e1 = expf(s[am][bn][rr*2+1] - mnew);
                    s[am][bn][rr*2] = e0; s[am][bn][rr*2+1] = e1;
                    sv += e0 + e1;
                }
                sv += __shfl_xor_sync(0xffffffffu, sv, 1);
                sv += __shfl_xor_sync(0xffffffffu, sv, 2);
                rs_[am][rr] = sv;
            }
        if ((lane & 3) == 0) {
#pragma unroll
            for (int am = 0; am < 2; am++)
#pragma unroll
                for (int rr = 0; rr < 2; rr++) {
                    int il = wm0 + am * 16 + (lane >> 2) + rr * 8;
                    rsum[il * 2 + grp] = rs_[am][rr];
                }
        }
#pragma unroll
        for (int am = 0; am < 2; am++)
#pragma unroll
            for (int rr = 0; rr < 2; rr++) {
                int il = wm0 + am * 16 + (lane >> 2) + rr * 8;
#pragma unroll
                for (int bn = 0; bn < 8; bn++) {
                    int jc = wn0s + bn * 8 + (lane & 3) * 2;
                    int ch = jc >> 5;
                    *reinterpret_cast<__half2*>(pP + ch * (STG128/2) + il * 40 + (jc & 31)) =
                        __floats2half2_rn(s[am][bn][rr*2], s[am][bn][rr*2+1]);
                }
            }
        __syncthreads();
#pragma unroll
        for (int am = 0; am < 2; am++)
#pragma unroll
            for (int rr = 0; rr < 2; rr++) {
                int il = wm0 + am * 16 + (lane >> 2) + rr * 8;
                l_run[am][rr] = l_run[am][rr] * f[am][rr] + rsum[il*2] + rsum[il*2+1];
#pragma unroll
                for (int bn = 0; bn < 4; bn++) {
                    o[am][bn][rr*2]   *= f[am][rr];
                    o[am][bn][rr*2+1] *= f[am][rr];
                }
            }
#pragma unroll
        for (int c = 0; c < 4; c++)
            mma_tile32(uP + c * STG128, uV + c * STG64, lane, wm0, wn0o, o);
        __syncthreads();
    }
#pragma unroll
    for (int am = 0; am < 2; am++) {
        int r0 = i0 + wm0 + am * 16 + (lane >> 2);
        float inv0 = 1.f / l_run[am][0], inv1 = 1.f / l_run[am][1];
#pragma unroll
        for (int bn = 0; bn < 4; bn++) {
            int d = wn0o + bn * 8 + (lane & 3) * 2;
            float* a4 = o[am][bn];
            *reinterpret_cast<__half2*>(g_ctxh + (size_t)(b*L_ + r0) * D_ + h*DH_ + d) =
                __floats2half2_rn(a4[0] * inv0, a4[1] * inv0);
            *reinterpret_cast<__half2*>(g_ctxh + (size_t)(b*L_ + r0 + 8) * D_ + h*DH_ + d) =
                __floats2half2_rn(a4[2] * inv1, a4[3] * inv1);
        }
    }
}

// ---------------- gating (warp-parallel) ----------------
__global__ __launch_bounds__(256) void k_gates(const float* __restrict__ sw) {
    __shared__ float ts[D_];
    __shared__ float gsm[E_];
    const int tok = blockIdx.x;
    const int tid = threadIdx.x;
    const int wid = tid >> 5, lane = tid & 31;
    const __half2* th = reinterpret_cast<const __half2*>(g_tbh + (size_t)tok * D_);
    const __half2* tl = reinterpret_cast<const __half2*>(g_tbl + (size_t)tok * D_);
#pragma unroll
    for (int q = 0; q < 2; q++) {
        __half2 a = th[tid*2+q], c = tl[tid*2+q];
        ts[tid*4 + q*2 + 0] = __low2float(a)  + __low2float(c);
        ts[tid*4 + q*2 + 1] = __high2float(a) + __high2float(c);
    }
    __syncthreads();
#pragma unroll
    for (int sub = 0; sub < 4; sub++) {
        int e = wid * 4 + sub;
        float acc = 0.f;
#pragma unroll 8
        for (int d = lane; d < D_; d += 32)
            acc += ts[d] * sw[d * E_ + e];
        for (int off = 16; off; off >>= 1)
            acc += __shfl_xor_sync(0xffffffffu, acc, off);
        if (lane == 0) gsm[e] = acc;
    }
    __syncthreads();
    if (tid < 32) {
        float gv = 1.f / (1.f + expf(-gsm[tid]));
        bool sel = false;
        for (int r = 0; r < 4; r++) {
            float cand = sel ? -1e30f : gv;
            float bv = cand; int bi = tid;
            for (int off = 16; off; off >>= 1) {
                float ov = __shfl_xor_sync(0xffffffffu, bv, off);
                int oi = __shfl_xor_sync(0xffffffffu, bi, off);
                if (ov > bv || (ov == bv && oi < bi)) { bv = ov; bi = oi; }
            }
            if (tid == bi) sel = true;
        }
        g_gate[tok * E_ + tid] = sel ? gv : 0.f;
    }
}

// ---------------- launch ----------------
extern "C" void kernel_launch(void* const* d_in, const int* in_sizes, int n_in,
                              void* d_out, int out_size) {
    const float* src  = (const float*)d_in[0];
    const float* Wq   = (const float*)d_in[1];
    const float* Wk   = (const float*)d_in[2];
    const float* Wv   = (const float*)d_in[3];
    const float* Wo   = (const float*)d_in[4];
    const float* Wp   = (const float*)d_in[5];
    const float* ln1g = (const float*)d_in[6];
    const float* ln1b = (const float*)d_in[7];
    const float* ln2g = (const float*)d_in[8];
    const float* ln2b = (const float*)d_in[9];
    const float* selw = (const float*)d_in[10];
    const float* keys = (const float*)d_in[11];
    const float* vals = (const float*)d_in[12];
    float* out = (float*)d_out;

    __half *wqh,*wkh,*wvh,*woh,*wph,*keyh,*valh;
    __half *x2h,*ph,*peh,*ctxh,*tbh,*tbl,*hbh;
    float *xr,*gate;
    cudaGetSymbolAddress((void**)&wqh, g_wqh);
    cudaGetSymbolAddress((void**)&wkh, g_wkh);
    cudaGetSymbolAddress((void**)&wvh, g_wvh);
    cudaGetSymbolAddress((void**)&woh, g_woh);
    cudaGetSymbolAddress((void**)&wph, g_wph);
    cudaGetSymbolAddress((void**)&keyh, g_keyh);
    cudaGetSymbolAddress((void**)&valh, g_valh);
    cudaGetSymbolAddress((void**)&x2h, g_x2h);
    cudaGetSymbolAddress((void**)&peh, g_peh);
    cudaGetSymbolAddress((void**)&ph,  g_ph);
    cudaGetSymbolAddress((void**)&ctxh, g_ctxh);
    cudaGetSymbolAddress((void**)&tbh, g_tbh);  cudaGetSymbolAddress((void**)&tbl, g_tbl);
    cudaGetSymbolAddress((void**)&hbh, g_hbh);
    cudaGetSymbolAddress((void**)&xr,  g_xr);
    cudaGetSymbolAddress((void**)&gate, g_gate);

    const int SM1  = 4 * STG128;
    cudaFuncSetAttribute((const void*)khg<1,1>, cudaFuncAttributeMaxDynamicSharedMemorySize, SM1);
    cudaFuncSetAttribute((const void*)khg<2,1>, cudaFuncAttributeMaxDynamicSharedMemorySize, SM1);
    cudaFuncSetAttribute((const void*)khg<3,1>, cudaFuncAttributeMaxDynamicSharedMemorySize, SM1);
    cudaFuncSetAttribute((const void*)khg_qkv,  cudaFuncAttributeMaxDynamicSharedMemorySize, SM1);
    cudaFuncSetAttribute((const void*)k_bd,     cudaFuncAttributeMaxDynamicSharedMemorySize, SM1);
    cudaFuncSetAttribute((const void*)k_flash,  cudaFuncAttributeMaxDynamicSharedMemorySize, FL_SMEM);

    // prep
    k_pos<<<P2_, 256>>>();
    dim3 g1k(32, 32, 1);
    k_trh<<<g1k, 256>>>(Wq, wqh, D_, D_);
    k_trh<<<g1k, 256>>>(Wk, wkh, D_, D_);
    k_trh<<<g1k, 256>>>(Wv, wvh, D_, D_);
    k_trh<<<g1k, 256>>>(Wo, woh, D_, D_);
    k_trh<<<g1k, 256>>>(Wp, wph, D_, D_);
    k_trh<<<dim3(4, 32, E_), 256>>>(keys, keyh, D_, ES_);
    k_trh<<<dim3(32, 128, 1), 256>>>(vals, valh, NC_, D_);

    k_ln<<<T_, 256>>>(src, ln1g, ln1b, x2h, nullptr);

    // projections (1-pass)
    khg_qkv<<<dim3(8, 16, 3), 256, SM1>>>(x2h, wqh, wkh, wvh);
    khg<1,1><<<dim3(8, 16), 256, SM1>>>(peh, nullptr, wph, nullptr, ph, nullptr, nullptr, D_);
    k_vts<<<dim3(32, 32, 2), 256>>>();

    // attention: banded bd then fused flash
    k_bd<<<dim3(9, 8, 32), 256, SM1>>>();
    k_flash<<<dim3(8, 32), 256, FL_SMEM>>>();
    khg<2,1><<<dim3(8, 16), 256, SM1>>>(ctxh, nullptr, woh, xr, nullptr, src, nullptr, D_);

    // MoE (1-pass)
    k_ln<<<T_, 256>>>(xr, ln2g, ln2b, tbh, tbl);
    k_gates<<<T_, 256>>>(selw);
    khg<3,1><<<dim3(32, 16), 256, SM1>>>(tbh, nullptr, keyh, nullptr, hbh, nullptr, gate, D_);
    khg<2,1><<<dim3(8, 16), 256, SM1>>>(hbh, nullptr, valh, out, nullptr, xr, nullptr, NC_);
}

// round 17
// speedup vs baseline: 1.5542x; 1.0059x over previous
#include <cuda_runtime.h>
#include <cuda_fp16.h>
#include <math.h>
#include <stdint.h>

#define B_    2
#define L_    1024
#define D_    1024
#define H_    16
#define DH_   64
#define E_    32
#define ES_   128
#define T_    (B_*L_)
#define P2_   (2*L_-1)
#define NC_   (E_*ES_)
#define BAND_ 1152

// ---------------- helpers ----------------
__device__ __forceinline__ uint32_t smem_u32(const void* p) {
    uint32_t a;
    asm("{ .reg .u64 t; cvta.to.shared.u64 t, %1; cvt.u32.u64 %0, t; }" : "=r"(a) : "l"(p));
    return a;
}
__device__ __forceinline__ void ldsm4(uint32_t& r0, uint32_t& r1, uint32_t& r2, uint32_t& r3, uint32_t addr) {
    asm volatile("ldmatrix.sync.aligned.m8n8.x4.shared.b16 {%0,%1,%2,%3}, [%4];"
        : "=r"(r0), "=r"(r1), "=r"(r2), "=r"(r3) : "r"(addr));
}
__device__ __forceinline__ void mma16816(float* c, const uint32_t* a, uint32_t b0, uint32_t b1) {
    asm volatile("mma.sync.aligned.m16n8k16.row.col.f32.f16.f16.f32 "
        "{%0,%1,%2,%3}, {%4,%5,%6,%7}, {%8,%9}, {%0,%1,%2,%3};"
        : "+f"(c[0]), "+f"(c[1]), "+f"(c[2]), "+f"(c[3])
        : "r"(a[0]), "r"(a[1]), "r"(a[2]), "r"(a[3]), "r"(b0), "r"(b1));
}
__device__ __forceinline__ void cpa16(uint32_t saddr, const void* gaddr) {
    asm volatile("cp.async.ca.shared.global [%0], [%1], 16;" :: "r"(saddr), "l"(gaddr));
}
#define CPA_COMMIT() asm volatile("cp.async.commit_group;" ::: "memory")
#define CPA_WAIT1()  asm volatile("cp.async.wait_group 1;" ::: "memory")
#define CPA_WAIT0()  asm volatile("cp.async.wait_group 0;" ::: "memory")

__device__ __forceinline__ void sp2(float x, float y, __half* ph, __half* pl, size_t idx) {
    __half hx = __float2half_rn(x), hy = __float2half_rn(y);
    *reinterpret_cast<__half2*>(ph + idx) = __halves2half2(hx, hy);
    if (pl)
        *reinterpret_cast<__half2*>(pl + idx) = __halves2half2(
            __float2half_rn(x - __half2float(hx)), __float2half_rn(y - __half2float(hy)));
}

template<int PASS>
__device__ __forceinline__ void mma_tile(uint32_t sAh, uint32_t sAl, uint32_t sBh,
                                         int lane, int wm0, int wn0, float acc[2][8][4]) {
#pragma unroll
    for (int ks = 0; ks < 2; ks++) {
        uint32_t bh[16];
        int g = lane >> 3;
#pragma unroll
        for (int p = 0; p < 4; p++) {
            uint32_t bo = (uint32_t)(((wn0 + p*16 + (g>>1)*8 + (lane&7))*40 + ks*16 + (g&1)*8) * 2);
            ldsm4(bh[p*4], bh[p*4+1], bh[p*4+2], bh[p*4+3], sBh + bo);
        }
#pragma unroll
        for (int am = 0; am < 2; am++) {
            uint32_t ah[4], al[4];
            uint32_t ao = (uint32_t)(((wm0 + am*16 + (lane&15))*40 + ks*16 + (lane>>4)*8) * 2);
            ldsm4(ah[0], ah[1], ah[2], ah[3], sAh + ao);
            if (PASS == 2) ldsm4(al[0], al[1], al[2], al[3], sAl + ao);
#pragma unroll
            for (int bn = 0; bn < 8; bn++) {
                mma16816(acc[am][bn], ah, bh[bn*2], bh[bn*2+1]);
                if (PASS == 2) mma16816(acc[am][bn], al, bh[bn*2], bh[bn*2+1]);
            }
        }
    }
}
__device__ __forceinline__ void mma_tile32(uint32_t sAh, uint32_t sBh,
                                           int lane, int wm0, int wn0, float acc[2][4][4]) {
#pragma unroll
    for (int ks = 0; ks < 2; ks++) {
        uint32_t bh[8];
        int g = lane >> 3;
#pragma unroll
        for (int p = 0; p < 2; p++) {
            uint32_t bo = (uint32_t)(((wn0 + p*16 + (g>>1)*8 + (lane&7))*40 + ks*16 + (g&1)*8) * 2);
            ldsm4(bh[p*4], bh[p*4+1], bh[p*4+2], bh[p*4+3], sBh + bo);
        }
#pragma unroll
        for (int am = 0; am < 2; am++) {
            uint32_t ah[4];
            uint32_t ao = (uint32_t)(((wm0 + am*16 + (lane&15))*40 + ks*16 + (lane>>4)*8) * 2);
            ldsm4(ah[0], ah[1], ah[2], ah[3], sAh + ao);
#pragma unroll
            for (int bn = 0; bn < 4; bn++)
                mma16816(acc[am][bn], ah, bh[bn*2], bh[bn*2+1]);
        }
    }
}

#define CPLD128(SRC, KST, DB) do { \
    int _row = tid >> 2, _q = tid & 3; \
    cpa16((DB) + (uint32_t)((_row*40 + _q*8) * 2), &(SRC)[(size_t)_row*(KST) + kk0 + _q*8]); \
    cpa16((DB) + (uint32_t)(((_row+64)*40 + _q*8) * 2), &(SRC)[(size_t)(_row+64)*(KST) + kk0 + _q*8]); \
} while (0)
#define CPLD64(SRC, KST, DB) do { \
    int _row = tid >> 2, _q = tid & 3; \
    cpa16((DB) + (uint32_t)((_row*40 + _q*8) * 2), &(SRC)[(size_t)_row*(KST) + kk0 + _q*8]); \
} while (0)

#define STG128 (128*40*2)
#define STG64  (64*40*2)

// ---------------- scratch ----------------
__device__ __align__(16) __half g_peh [(size_t)2048 * D_];
__device__ __align__(16) __half g_wqh [(size_t)D_ * D_];
__device__ __align__(16) __half g_wkh [(size_t)D_ * D_];
__device__ __align__(16) __half g_wvh [(size_t)D_ * D_];
__device__ __align__(16) __half g_woh [(size_t)D_ * D_];
__device__ __align__(16) __half g_wph [(size_t)D_ * D_];
__device__ __align__(16) __half g_keyh[(size_t)NC_ * D_];
__device__ __align__(16) __half g_valh[(size_t)D_ * NC_];
__device__ __align__(16) __half g_x2h [(size_t)T_ * D_];
__device__ __align__(16) __half g_qh  [(size_t)T_ * D_];
__device__ __align__(16) __half g_kh  [(size_t)T_ * D_];
__device__ __align__(16) __half g_vth [(size_t)T_ * D_];
__device__ __align__(16) __half g_ph  [(size_t)2048 * D_];
__device__ __align__(16) __half g_ctxh[(size_t)T_ * D_];
__device__ __align__(16) __half g_tbh [(size_t)T_ * D_],  g_tbl [(size_t)T_ * D_];
__device__ __align__(16) __half g_hbh [(size_t)T_ * NC_];
__device__ __align__(16) __half g_qp  [(size_t)B_*H_*8*128*BAND_];
__device__ __align__(16) float  g_vb  [(size_t)T_ * D_];
__device__ __align__(16) float  g_xr  [(size_t)T_ * D_];
__device__ __align__(16) float  g_gate[(size_t)T_ * E_];

// ---------------- small kernels ----------------
__global__ __launch_bounds__(256) void k_pos() {
    int r = blockIdx.x;
    float pos = (float)(L_ - 1 - r);
    const float c = 9.210340371976184f / 1024.0f;
    for (int m = threadIdx.x; m < D_; m += 256) {
        int j = (m < 512) ? m : m - 512;
        float ang = pos * __expf(-c * (float)(2 * j));
        float v = (m < 512) ? __sinf(ang) : __cosf(ang);
        g_peh[(size_t)r * D_ + m] = __float2half_rn(v);
    }
}

__global__ __launch_bounds__(256) void k_trh(const float* __restrict__ in,
                                             __half* __restrict__ oh, int R, int C) {
    __shared__ float t[32][33];
    size_t zoff = (size_t)blockIdx.z * R * C;
    int c0 = blockIdx.x * 32, r0 = blockIdx.y * 32;
    int x = threadIdx.x & 31, y = threadIdx.x >> 5;
    for (int i = y; i < 32; i += 8)
        t[i][x] = in[zoff + (size_t)(r0 + i) * C + c0 + x];
    __syncthreads();
    for (int i = y; i < 32; i += 8)
        oh[zoff + (size_t)(c0 + i) * R + r0 + x] = __float2half_rn(t[x][i]);
}

__global__ __launch_bounds__(256) void k_vts() {
    __shared__ float t[32][33];
    int b = blockIdx.z;
    int i0 = blockIdx.x * 32, hd0 = blockIdx.y * 32;
    int x = threadIdx.x & 31, y = threadIdx.x >> 5;
    for (int r = y; r < 32; r += 8)
        t[r][x] = g_vb[(size_t)(b*L_ + i0 + r) * D_ + hd0 + x];
    __syncthreads();
    for (int r = y; r < 32; r += 8)
        g_vth[(size_t)(b*1024 + hd0 + r) * 1024 + i0 + x] = __float2half_rn(t[x][r]);
}

__global__ __launch_bounds__(256) void k_ln(const float* __restrict__ x,
                                            const float* __restrict__ g,
                                            const float* __restrict__ b,
                                            __half* __restrict__ oh, __half* __restrict__ ol) {
    __shared__ float rs[256], rq[256];
    size_t row = blockIdx.x;
    int tid = threadIdx.x;
    float4 v = reinterpret_cast<const float4*>(x + row * D_)[tid];
    rs[tid] = v.x + v.y + v.z + v.w;
    rq[tid] = v.x*v.x + v.y*v.y + v.z*v.z + v.w*v.w;
    __syncthreads();
    for (int s = 128; s; s >>= 1) {
        if (tid < s) { rs[tid] += rs[tid+s]; rq[tid] += rq[tid+s]; }
        __syncthreads();
    }
    float mean = rs[0] * (1.0f / D_);
    float inv  = rsqrtf(rq[0] * (1.0f / D_) - mean * mean + 1e-5f);
    float4 gv = reinterpret_cast<const float4*>(g)[tid];
    float4 bv = reinterpret_cast<const float4*>(b)[tid];
    size_t o = row * D_ + tid * 4;
    sp2((v.x-mean)*inv*gv.x+bv.x, (v.y-mean)*inv*gv.y+bv.y, oh, ol, o);
    sp2((v.z-mean)*inv*gv.z+bv.z, (v.w-mean)*inv*gv.w+bv.w, oh, ol, o + 2);
}

// ---------------- HMMA GEMM ----------------
template<int EPI, int PASS>
__global__ __launch_bounds__(256) void khg(const __half* __restrict__ Ah, const __half* __restrict__ Al,
                                           const __half* __restrict__ Bh,
                                           float* __restrict__ Cf,
                                           __half* __restrict__ Ch,
                                           const float* __restrict__ aux,
                                           const float* __restrict__ gate, int K) {
    extern __shared__ __half dsm[];
    const int tid = threadIdx.x, wid = tid >> 5, lane = tid & 31;
    const int m0 = blockIdx.y * 128, n0 = blockIdx.x * 128;
    const int ldc = gridDim.x * 128;
    const int wm0 = (wid & 3) * 32, wn0 = (wid >> 2) * 64;
    const __half* Abh = Ah + (size_t)m0 * K;
    const __half* Abl = (PASS == 2) ? (Al + (size_t)m0 * K) : nullptr;
    const __half* Bbh = Bh + (size_t)n0 * K;
    const uint32_t base = smem_u32(dsm);
    const uint32_t uAh = base;
    const uint32_t uAl = base + 2*STG128;
    const uint32_t uBh = base + PASS * 2 * STG128;
    float acc[2][8][4] = {};
    const int nk = K / 32;
    {
        int kk0 = 0;
        CPLD128(Abh, K, uAh);
        if (PASS == 2) CPLD128(Abl, K, uAl);
        CPLD128(Bbh, K, uBh);
        CPA_COMMIT();
    }
    for (int kc = 0; kc < nk; kc++) {
        if (kc + 1 < nk) {
            int kk0 = (kc + 1) * 32;
            uint32_t so = (uint32_t)(((kc + 1) & 1) * STG128);
            CPLD128(Abh, K, uAh + so);
            if (PASS == 2) CPLD128(Abl, K, uAl + so);
            CPLD128(Bbh, K, uBh + so);
            CPA_COMMIT();
            CPA_WAIT1();
        } else {
            CPA_WAIT0();
        }
        __syncthreads();
        uint32_t so = (uint32_t)((kc & 1) * STG128);
        mma_tile<PASS>(uAh + so, uAl + so, uBh + so, lane, wm0, wn0, acc);
        __syncthreads();
    }
#pragma unroll
    for (int am = 0; am < 2; am++) {
        int r0 = m0 + wm0 + am * 16 + (lane >> 2);
#pragma unroll
        for (int bn = 0; bn < 8; bn++) {
            int cN = n0 + wn0 + bn * 8 + (lane & 3) * 2;
            float* a4 = acc[am][bn];
            if (EPI == 1) {
                *reinterpret_cast<__half2*>(Ch + (size_t)r0 * ldc + cN)     = __floats2half2_rn(a4[0], a4[1]);
                *reinterpret_cast<__half2*>(Ch + (size_t)(r0+8) * ldc + cN) = __floats2half2_rn(a4[2], a4[3]);
            } else if (EPI == 2) {
                float2 x0 = *reinterpret_cast<const float2*>(aux + (size_t)r0 * ldc + cN);
                float2 x1 = *reinterpret_cast<const float2*>(aux + (size_t)(r0+8) * ldc + cN);
                *reinterpret_cast<float2*>(Cf + (size_t)r0 * ldc + cN)     = make_float2(a4[0]+x0.x, a4[1]+x0.y);
                *reinterpret_cast<float2*>(Cf + (size_t)(r0+8) * ldc + cN) = make_float2(a4[2]+x1.x, a4[3]+x1.y);
            } else {
                int e = cN >> 7;
                float g0 = gate[r0 * E_ + e], g1 = gate[(r0+8) * E_ + e];
                *reinterpret_cast<__half2*>(Ch + (size_t)r0 * ldc + cN) =
                    __floats2half2_rn(fmaxf(a4[0],0.f)*g0, fmaxf(a4[1],0.f)*g0);
                *reinterpret_cast<__half2*>(Ch + (size_t)(r0+8) * ldc + cN) =
                    __floats2half2_rn(fmaxf(a4[2],0.f)*g1, fmaxf(a4[3],0.f)*g1);
            }
        }
    }
}

// QKV fused (1-pass): z=0 -> q hi (pre-scaled by 1/8), z=1 -> k hi, z=2 -> v fp32
__global__ __launch_bounds__(256) void khg_qkv(const __half* __restrict__ Ah,
                                               const __half* __restrict__ B0h,
                                               const __half* __restrict__ B1h,
                                               const __half* __restrict__ B2h) {
    extern __shared__ __half dsm[];
    const int tid = threadIdx.x, wid = tid >> 5, lane = tid & 31;
    const int m0 = blockIdx.y * 128, n0 = blockIdx.x * 128, z = blockIdx.z;
    const int K = D_;
    const int wm0 = (wid & 3) * 32, wn0 = (wid >> 2) * 64;
    const __half* Bh = (z == 0) ? B0h : (z == 1) ? B1h : B2h;
    const __half* Abh = Ah + (size_t)m0 * K;
    const __half* Bbh = Bh + (size_t)n0 * K;
    const uint32_t base = smem_u32(dsm);
    const uint32_t uAh = base, uBh = base + 2*STG128;
    float acc[2][8][4] = {};
    const int nk = K / 32;
    {
        int kk0 = 0;
        CPLD128(Abh, K, uAh); CPLD128(Bbh, K, uBh);
        CPA_COMMIT();
    }
    for (int kc = 0; kc < nk; kc++) {
        if (kc + 1 < nk) {
            int kk0 = (kc + 1) * 32;
            uint32_t so = (uint32_t)(((kc + 1) & 1) * STG128);
            CPLD128(Abh, K, uAh + so); CPLD128(Bbh, K, uBh + so);
            CPA_COMMIT();
            CPA_WAIT1();
        } else {
            CPA_WAIT0();
        }
        __syncthreads();
        uint32_t so = (uint32_t)((kc & 1) * STG128);
        mma_tile<1>(uAh + so, 0u, uBh + so, lane, wm0, wn0, acc);
        __syncthreads();
    }
#pragma unroll
    for (int am = 0; am < 2; am++) {
        int r0 = m0 + wm0 + am * 16 + (lane >> 2);
#pragma unroll
        for (int bn = 0; bn < 8; bn++) {
            int cN = n0 + wn0 + bn * 8 + (lane & 3) * 2;
            float* a4 = acc[am][bn];
            if (z == 2) {
                *reinterpret_cast<float2*>(g_vb + (size_t)r0 * D_ + cN)     = make_float2(a4[0], a4[1]);
                *reinterpret_cast<float2*>(g_vb + (size_t)(r0+8) * D_ + cN) = make_float2(a4[2], a4[3]);
            } else if (z == 0) {
                *reinterpret_cast<__half2*>(g_qh + (size_t)r0 * D_ + cN) =
                    __floats2half2_rn(a4[0]*0.125f, a4[1]*0.125f);
                *reinterpret_cast<__half2*>(g_qh + (size_t)(r0+8) * D_ + cN) =
                    __floats2half2_rn(a4[2]*0.125f, a4[3]*0.125f);
            } else {
                *reinterpret_cast<__half2*>(g_kh + (size_t)r0 * D_ + cN)     = __floats2half2_rn(a4[0], a4[1]);
                *reinterpret_cast<__half2*>(g_kh + (size_t)(r0+8) * D_ + cN) = __floats2half2_rn(a4[2], a4[3]);
            }
        }
    }
}

// ---------------- attention: bd -> dense banded qp (1-pass, half) ----------------
__global__ __launch_bounds__(256) void k_bd() {
    extern __shared__ __half dsm[];
    const int tid = threadIdx.x, wid = tid >> 5, lane = tid & 31;
    const int bh = blockIdx.z, b = bh >> 4, h = bh & 15;
    const int it = blockIdx.y, i0 = it * 128, rt = blockIdx.x;
    const int rbase = 896 - i0 + rt * 128;
    const int wm0 = (wid & 3) * 32, wn0 = (wid >> 2) * 64;
    const __half* Abh = g_qh + (size_t)(b*L_ + i0) * D_ + h*DH_;
    const __half* Bbh = g_ph + (size_t)rbase * D_ + h*DH_;
    const uint32_t base = smem_u32(dsm);
    const uint32_t uAh = base, uBh = base + 2*STG128;
    float acc[2][8][4] = {};
    {
        int kk0 = 0;
        CPLD128(Abh, D_, uAh); CPLD128(Bbh, D_, uBh);
        CPA_COMMIT();
    }
    for (int kc = 0; kc < 2; kc++) {
        if (kc == 0) {
            int kk0 = 32;
            uint32_t so = STG128;
            CPLD128(Abh, D_, uAh + so); CPLD128(Bbh, D_, uBh + so);
            CPA_COMMIT();
            CPA_WAIT1();
        } else {
            CPA_WAIT0();
        }
        __syncthreads();
        uint32_t so = (uint32_t)((kc & 1) * STG128);
        mma_tile<1>(uAh + so, 0u, uBh + so, lane, wm0, wn0, acc);
        __syncthreads();
    }
    __half* qpb = g_qp + (((size_t)bh * 8 + it) * 128) * BAND_ + rt * 128;
#pragma unroll
    for (int am = 0; am < 2; am++) {
#pragma unroll
        for (int rr = 0; rr < 2; rr++) {
            int il = wm0 + am * 16 + (lane >> 2) + rr * 8;
#pragma unroll
            for (int bn = 0; bn < 8; bn++) {
                int nn = wn0 + bn * 8 + (lane & 3) * 2;
                *reinterpret_cast<__half2*>(qpb + (size_t)il * BAND_ + nn) =
                    __floats2half2_rn(acc[am][bn][rr*2], acc[am][bn][rr*2+1]);
            }
        }
    }
}

// ---------------- flash attention ----------------
#define FL_SMEM (8*STG128 + 4*STG64 + 2048)
__global__ __launch_bounds__(256) void k_flash() {
    extern __shared__ __half dsm[];
    const int tid = threadIdx.x, wid = tid >> 5, lane = tid & 31;
    const int bh = blockIdx.y, b = bh >> 4, h = bh & 15;
    const int i0 = blockIdx.x * 128;
    const int wm0 = (wid & 3) * 32, wn0s = (wid >> 2) * 64, wn0o = (wid >> 2) * 32;
    const int grp = wid >> 2;
    const uint32_t base = smem_u32(dsm);
    const uint32_t uQ = base;
    const uint32_t uK = base + 2*STG128;
    const uint32_t uP = base + 4*STG128;
    const uint32_t uV = base + 8*STG128;
    __half* pP = dsm + (4*STG128) / 2;
    float* rmax = reinterpret_cast<float*>(dsm + (8*STG128 + 4*STG64) / 2);
    float* rsum = rmax + 256;

    const __half* Qb = g_qh + (size_t)(b*L_ + i0) * D_ + h*DH_;
    { int kk0 = 0;  CPLD128(Qb, D_, uQ); }
    { int kk0 = 32; CPLD128(Qb, D_, uQ + STG128); }
    CPA_COMMIT();

    const __half* Kb0 = g_kh + (size_t)(b*L_) * D_ + h*DH_;
    const __half* Vb  = g_vth + (size_t)(b*1024 + h*DH_) * 1024;
    const __half* qpb = g_qp + (((size_t)bh * 8 + (i0 >> 7)) * 128) * BAND_;

    float m_run[2][2], l_run[2][2];
    float o[2][4][4] = {};
#pragma unroll
    for (int a = 0; a < 2; a++)
#pragma unroll
        for (int r = 0; r < 2; r++) { m_run[a][r] = -1e30f; l_run[a][r] = 0.f; }

    for (int jt = 0; jt < 8; jt++) {
        int j0 = jt * 128;
        {
            const __half* Kb = Kb0 + (size_t)j0 * D_;
            { int kk0 = 0;  CPLD128(Kb, D_, uK); }
            { int kk0 = 32; CPLD128(Kb, D_, uK + STG128); }
#pragma unroll
            for (int c = 0; c < 4; c++) { int kk0 = j0 + c * 32; CPLD64(Vb, 1024, uV + c * STG64); }
            CPA_COMMIT();
            CPA_WAIT0();
        }
        __syncthreads();
        float s[2][8][4] = {};
        mma_tile<1>(uQ, 0u, uK, lane, wm0, wn0s, s);
        mma_tile<1>(uQ + STG128, 0u, uK + STG128, lane, wm0, wn0s, s);
#pragma unroll
        for (int am = 0; am < 2; am++)
#pragma unroll
            for (int rr = 0; rr < 2; rr++) {
                int il = wm0 + am * 16 + (lane >> 2) + rr * 8;
                const __half* qpr = qpb + (size_t)il * BAND_ + (j0 - il + 127);
#pragma unroll
                for (int bn = 0; bn < 8; bn++) {
                    int jc = wn0s + bn * 8 + (lane & 3) * 2;
                    s[am][bn][rr*2]   += __half2float(qpr[jc]);
                    s[am][bn][rr*2+1] += __half2float(qpr[jc + 1]);
                }
            }
        float mt[2][2];
#pragma unroll
        for (int am = 0; am < 2; am++)
#pragma unroll
            for (int rr = 0; rr < 2; rr++) {
                float mv = -1e30f;
#pragma unroll
                for (int bn = 0; bn < 8; bn++)
                    mv = fmaxf(mv, fmaxf(s[am][bn][rr*2], s[am][bn][rr*2+1]));
                mv = fmaxf(mv, __shfl_xor_sync(0xffffffffu, mv, 1));
                mv = fmaxf(mv, __shfl_xor_sync(0xffffffffu, mv, 2));
                mt[am][rr] = mv;
            }
        if ((lane & 3) == 0) {
#pragma unroll
            for (int am = 0; am < 2; am++)
#pragma unroll
                for (int rr = 0; rr < 2; rr++) {
                    int il = wm0 + am * 16 + (lane >> 2) + rr * 8;
                    rmax[il * 2 + grp] = mt[am][rr];
                }
        }
        __syncthreads();
        float f[2][2], rs_[2][2];
#pragma unroll
        for (int am = 0; am < 2; am++)
#pragma unroll
            for (int rr = 0; rr < 2; rr++) {
                int il = wm0 + am * 16 + (lane >> 2) + rr * 8;
                float mnew = fmaxf(m_run[am][rr], fmaxf(rmax[il*2], rmax[il*2+1]));
                f[am][rr] = __expf(m_run[am][rr] - mnew);
                m_run[am][rr] = mnew;
                float sv = 0.f;
#pragma unroll
                for (int bn = 0; bn < 8; bn++) {
                    float e0 = __expf(s[am][bn][rr*2]   - mnew);
                    float e1 = __expf(s[am][bn][rr*2+1] - mnew);
                    s[am][bn][rr*2] = e0; s[am][bn][rr*2+1] = e1;
                    sv += e0 + e1;
                }
                sv += __shfl_xor_sync(0xffffffffu, sv, 1);
                sv += __shfl_xor_sync(0xffffffffu, sv, 2);
                rs_[am][rr] = sv;
            }
        if ((lane & 3) == 0) {
#pragma unroll
            for (int am = 0; am < 2; am++)
#pragma unroll
                for (int rr = 0; rr < 2; rr++) {
                    int il = wm0 + am * 16 + (lane >> 2) + rr * 8;
                    rsum[il * 2 + grp] = rs_[am][rr];
                }
        }
#pragma unroll
        for (int am = 0; am < 2; am++)
#pragma unroll
            for (int rr = 0; rr < 2; rr++) {
                int il = wm0 + am * 16 + (lane >> 2) + rr * 8;
#pragma unroll
                for (int bn = 0; bn < 8; bn++) {
                    int jc = wn0s + bn * 8 + (lane & 3) * 2;
                    int ch = jc >> 5;
                    *reinterpret_cast<__half2*>(pP + ch * (STG128/2) + il * 40 + (jc & 31)) =
                        __floats2half2_rn(s[am][bn][rr*2], s[am][bn][rr*2+1]);
                }
            }
        __syncthreads();
#pragma unroll
        for (int am = 0; am < 2; am++)
#pragma unroll
            for (int rr = 0; rr < 2; rr++) {
                int il = wm0 + am * 16 + (lane >> 2) + rr * 8;
                l_run[am][rr] = l_run[am][rr] * f[am][rr] + rsum[il*2] + rsum[il*2+1];
#pragma unroll
                for (int bn = 0; bn < 4; bn++) {
                    o[am][bn][rr*2]   *= f[am][rr];
                    o[am][bn][rr*2+1] *= f[am][rr];
                }
            }
#pragma unroll
        for (int c = 0; c < 4; c++)
            mma_tile32(uP + c * STG128, uV + c * STG64, lane, wm0, wn0o, o);
        __syncthreads();
    }
#pragma unroll
    for (int am = 0; am < 2; am++) {
        int r0 = i0 + wm0 + am * 16 + (lane >> 2);
        float inv0 = 1.f / l_run[am][0], inv1 = 1.f / l_run[am][1];
#pragma unroll
        for (int bn = 0; bn < 4; bn++) {
            int d = wn0o + bn * 8 + (lane & 3) * 2;
            float* a4 = o[am][bn];
            *reinterpret_cast<__half2*>(g_ctxh + (size_t)(b*L_ + r0) * D_ + h*DH_ + d) =
                __floats2half2_rn(a4[0] * inv0, a4[1] * inv0);
            *reinterpret_cast<__half2*>(g_ctxh + (size_t)(b*L_ + r0 + 8) * D_ + h*DH_ + d) =
                __floats2half2_rn(a4[2] * inv1, a4[3] * inv1);
        }
    }
}

// ---------------- gating (warp-parallel) ----------------
__global__ __launch_bounds__(256) void k_gates(const float* __restrict__ sw) {
    __shared__ float ts[D_];
    __shared__ float gsm[E_];
    const int tok = blockIdx.x;
    const int tid = threadIdx.x;
    const int wid = tid >> 5, lane = tid & 31;
    const __half2* th = reinterpret_cast<const __half2*>(g_tbh + (size_t)tok * D_);
    const __half2* tl = reinterpret_cast<const __half2*>(g_tbl + (size_t)tok * D_);
#pragma unroll
    for (int q = 0; q < 2; q++) {
        __half2 a = th[tid*2+q], c = tl[tid*2+q];
        ts[tid*4 + q*2 + 0] = __low2float(a)  + __low2float(c);
        ts[tid*4 + q*2 + 1] = __high2float(a) + __high2float(c);
    }
    __syncthreads();
#pragma unroll
    for (int sub = 0; sub < 4; sub++) {
        int e = wid * 4 + sub;
        float acc = 0.f;
#pragma unroll 8
        for (int d = lane; d < D_; d += 32)
            acc += ts[d] * sw[d * E_ + e];
        for (int off = 16; off; off >>= 1)
            acc += __shfl_xor_sync(0xffffffffu, acc, off);
        if (lane == 0) gsm[e] = acc;
    }
    __syncthreads();
    if (tid < 32) {
        float gv = 1.f / (1.f + __expf(-gsm[tid]));
        bool sel = false;
        for (int r = 0; r < 4; r++) {
            float cand = sel ? -1e30f : gv;
            float bv = cand; int bi = tid;
            for (int off = 16; off; off >>= 1) {
                float ov = __shfl_xor_sync(0xffffffffu, bv, off);
                int oi = __shfl_xor_sync(0xffffffffu, bi, off);
                if (ov > bv || (ov == bv && oi < bi)) { bv = ov; bi = oi; }
            }
            if (tid == bi) sel = true;
        }
        g_gate[tok * E_ + tid] = sel ? gv : 0.f;
    }
}

// ---------------- launch ----------------
extern "C" void kernel_launch(void* const* d_in, const int* in_sizes, int n_in,
                              void* d_out, int out_size) {
    const float* src  = (const float*)d_in[0];
    const float* Wq   = (const float*)d_in[1];
    const float* Wk   = (const float*)d_in[2];
    const float* Wv   = (const float*)d_in[3];
    const float* Wo   = (const float*)d_in[4];
    const float* Wp   = (const float*)d_in[5];
    const float* ln1g = (const float*)d_in[6];
    const float* ln1b = (const float*)d_in[7];
    const float* ln2g = (const float*)d_in[8];
    const float* ln2b = (const float*)d_in[9];
    const float* selw = (const float*)d_in[10];
    const float* keys = (const float*)d_in[11];
    const float* vals = (const float*)d_in[12];
    float* out = (float*)d_out;

    __half *wqh,*wkh,*wvh,*woh,*wph,*keyh,*valh;
    __half *x2h,*ph,*peh,*ctxh,*tbh,*tbl,*hbh;
    float *xr,*gate;
    cudaGetSymbolAddress((void**)&wqh, g_wqh);
    cudaGetSymbolAddress((void**)&wkh, g_wkh);
    cudaGetSymbolAddress((void**)&wvh, g_wvh);
    cudaGetSymbolAddress((void**)&woh, g_woh);
    cudaGetSymbolAddress((void**)&wph, g_wph);
    cudaGetSymbolAddress((void**)&keyh, g_keyh);
    cudaGetSymbolAddress((void**)&valh, g_valh);
    cudaGetSymbolAddress((void**)&x2h, g_x2h);
    cudaGetSymbolAddress((void**)&peh, g_peh);
    cudaGetSymbolAddress((void**)&ph,  g_ph);
    cudaGetSymbolAddress((void**)&ctxh, g_ctxh);
    cudaGetSymbolAddress((void**)&tbh, g_tbh);  cudaGetSymbolAddress((void**)&tbl, g_tbl);
    cudaGetSymbolAddress((void**)&hbh, g_hbh);
    cudaGetSymbolAddress((void**)&xr,  g_xr);
    cudaGetSymbolAddress((void**)&gate, g_gate);

    const int SM1  = 4 * STG128;
    cudaFuncSetAttribute((const void*)khg<1,1>, cudaFuncAttributeMaxDynamicSharedMemorySize, SM1);
    cudaFuncSetAttribute((const void*)khg<2,1>, cudaFuncAttributeMaxDynamicSharedMemorySize, SM1);
    cudaFuncSetAttribute((const void*)khg<3,1>, cudaFuncAttributeMaxDynamicSharedMemorySize, SM1);
    cudaFuncSetAttribute((const void*)khg_qkv,  cudaFuncAttributeMaxDynamicSharedMemorySize, SM1);
    cudaFuncSetAttribute((const void*)k_bd,     cudaFuncAttributeMaxDynamicSharedMemorySize, SM1);
    cudaFuncSetAttribute((const void*)k_flash,  cudaFuncAttributeMaxDynamicSharedMemorySize, FL_SMEM);

    // prep
    k_pos<<<P2_, 256>>>();
    dim3 g1k(32, 32, 1);
    k_trh<<<g1k, 256>>>(Wq, wqh, D_, D_);
    k_trh<<<g1k, 256>>>(Wk, wkh, D_, D_);
    k_trh<<<g1k, 256>>>(Wv, wvh, D_, D_);
    k_trh<<<g1k, 256>>>(Wo, woh, D_, D_);
    k_trh<<<g1k, 256>>>(Wp, wph, D_, D_);
    k_trh<<<dim3(4, 32, E_), 256>>>(keys, keyh, D_, ES_);
    k_trh<<<dim3(32, 128, 1), 256>>>(vals, valh, NC_, D_);

    k_ln<<<T_, 256>>>(src, ln1g, ln1b, x2h, nullptr);

    // projections (1-pass)
    khg_qkv<<<dim3(8, 16, 3), 256, SM1>>>(x2h, wqh, wkh, wvh);
    khg<1,1><<<dim3(8, 16), 256, SM1>>>(peh, nullptr, wph, nullptr, ph, nullptr, nullptr, D_);
    k_vts<<<dim3(32, 32, 2), 256>>>();

    // attention: banded bd then fused flash
    k_bd<<<dim3(9, 8, 32), 256, SM1>>>();
    k_flash<<<dim3(8, 32), 256, FL_SMEM>>>();
    khg<2,1><<<dim3(8, 16), 256, SM1>>>(ctxh, nullptr, woh, xr, nullptr, src, nullptr, D_);

    // MoE (1-pass)
    k_ln<<<T_, 256>>>(xr, ln2g, ln2b, tbh, tbl);
    k_gates<<<T_, 256>>>(selw);
    khg<3,1><<<dim3(32, 16), 256, SM1>>>(tbh, nullptr, keyh, nullptr, hbh, nullptr, gate, D_);
    khg<2,1><<<dim3(8, 16), 256, SM1>>>(hbh, nullptr, valh, out, nullptr, xr, nullptr, NC_);
}